// round 4
// baseline (speedup 1.0000x reference)
#include <cuda_runtime.h>
#include <math.h>

// Problem constants
#define Bq 2
#define Pq 4096
#define Eq 512
#define Hq 8
#define Dq 64
#define E3 1536
#define PE (Pq*Eq)          // 2,097,152 elements per batch
#define NB_RED 256

// ----------------------------------------------------------------------------
// Scratch (device globals; no allocation allowed in kernel_launch)
// ----------------------------------------------------------------------------
__device__ float  g_h   [Bq*Pq*Eq];                 // LN output (reused for LN2)
__device__ float  g_qkv [Bq*Pq*E3];                 // QKV projection
__device__ float  g_S   [(size_t)Bq*Hq*Pq*Pq];      // S^T scores (1 GB)
__device__ float  g_out1[Bq*Pq*Eq];                 // x + attention
__device__ float  g_t   [Bq*Pq*E3];                 // MLP hidden
__device__ double g_part[Bq*NB_RED*2];              // LN partial sums
__device__ float  g_stats[Bq*2];                    // LN mean / invstd

// ----------------------------------------------------------------------------
// LayerNorm over [P,E] jointly, per batch — 3 stage deterministic reduction
// ----------------------------------------------------------------------------
__global__ void ln_reduce_kernel(const float* __restrict__ x)
{
    int b = blockIdx.y;
    const float4* xb = (const float4*)(x + (size_t)b * PE);
    const int n4 = PE / 4;
    double s = 0.0, s2 = 0.0;
    for (int i = blockIdx.x * blockDim.x + threadIdx.x; i < n4;
         i += gridDim.x * blockDim.x) {
        float4 v = xb[i];
        s  += (double)v.x + (double)v.y + (double)v.z + (double)v.w;
        s2 += (double)v.x*v.x + (double)v.y*v.y + (double)v.z*v.z + (double)v.w*v.w;
    }
    __shared__ double ss[256], ss2[256];
    int t = threadIdx.x;
    ss[t] = s; ss2[t] = s2;
    __syncthreads();
    for (int o = 128; o > 0; o >>= 1) {
        if (t < o) { ss[t] += ss[t+o]; ss2[t] += ss2[t+o]; }
        __syncthreads();
    }
    if (t == 0) {
        g_part[(b*NB_RED + blockIdx.x)*2 + 0] = ss[0];
        g_part[(b*NB_RED + blockIdx.x)*2 + 1] = ss2[0];
    }
}

__global__ void ln_final_kernel()
{
    int b = blockIdx.x;
    int t = threadIdx.x;   // 256 threads == NB_RED
    __shared__ double ss[256], ss2[256];
    ss[t]  = g_part[(b*NB_RED + t)*2 + 0];
    ss2[t] = g_part[(b*NB_RED + t)*2 + 1];
    __syncthreads();
    for (int o = 128; o > 0; o >>= 1) {
        if (t < o) { ss[t] += ss[t+o]; ss2[t] += ss2[t+o]; }
        __syncthreads();
    }
    if (t == 0) {
        double mean = ss[0] / (double)PE;
        double var  = ss2[0] / (double)PE - mean * mean;
        g_stats[b*2 + 0] = (float)mean;
        g_stats[b*2 + 1] = (float)(1.0 / sqrt(var + 1e-5));
    }
}

__global__ void ln_apply_kernel(const float* __restrict__ x,
                                const float* __restrict__ gam,
                                const float* __restrict__ bet,
                                float* __restrict__ out)
{
    const int n4 = PE / 4;
    int i = blockIdx.x * blockDim.x + threadIdx.x;
    if (i >= Bq * n4) return;
    int b  = i / n4;
    int pe = i - b * n4;
    float mean = g_stats[b*2 + 0];
    float inv  = g_stats[b*2 + 1];
    float4 xv = ((const float4*)x)[i];
    float4 gv = ((const float4*)gam)[pe];
    float4 bv = ((const float4*)bet)[pe];
    float4 o;
    o.x = (xv.x - mean) * inv * gv.x + bv.x;
    o.y = (xv.y - mean) * inv * gv.y + bv.y;
    o.z = (xv.z - mean) * inv * gv.z + bv.z;
    o.w = (xv.w - mean) * inv * gv.w + bv.w;
    ((float4*)out)[i] = o;
}

// ----------------------------------------------------------------------------
// Exact GELU (matches jax.nn.gelu(approximate=False))
// ----------------------------------------------------------------------------
__device__ __forceinline__ float gelu_f(float v)
{
    return 0.5f * v * (1.0f + erff(v * 0.70710678118654752440f));
}

// ----------------------------------------------------------------------------
// C[m,n] = alpha * sum_k A[m,k]*B[n,k]  (NT GEMM, both operands K-major)
// 128x128x8 tile, 256 threads, 8x8 microtile. Batched via blockIdx.z with
// decomposed (outer, inner) offsets: off = (z/Hn)*Out + (z%Hn)*In.
// Epilogue: optional bias[n], exact GELU, residual add.
// ----------------------------------------------------------------------------
__global__ __launch_bounds__(256, 2)
void gemm_nt_kernel(const float* __restrict__ A, const float* __restrict__ Bm,
                    float* __restrict__ C,
                    int K, int lda, int ldb, int ldc,
                    long aOut, long aIn, long bOut, long bIn,
                    long cOut, long cIn, int Hn,
                    float alpha,
                    const float* __restrict__ bias,
                    const float* __restrict__ resid, int ldr,
                    int do_gelu)
{
    int z  = blockIdx.z;
    int zo = z / Hn, zi = z % Hn;
    A  += zo*aOut + zi*aIn;
    Bm += zo*bOut + zi*bIn;
    C  += zo*cOut + zi*cIn;
    if (resid) resid += zo*cOut + zi*cIn;

    __shared__ float As[8][128];
    __shared__ float Bs[8][128];

    int tid  = threadIdx.x;
    long row0 = (long)blockIdx.y * 128;
    long col0 = (long)blockIdx.x * 128;

    int la_r = tid >> 1;            // 0..127
    int la_c = (tid & 1) * 4;       // 0 or 4

    float acc[8][8];
    #pragma unroll
    for (int i = 0; i < 8; i++)
        #pragma unroll
        for (int j = 0; j < 8; j++) acc[i][j] = 0.0f;

    int r = (tid >> 4) * 8;         // row offset within tile
    int c = (tid & 15) * 8;         // col offset within tile

    const float* Ap = A  + (row0 + la_r) * (long)lda + la_c;
    const float* Bp = Bm + (col0 + la_r) * (long)ldb + la_c;

    for (int k0 = 0; k0 < K; k0 += 8) {
        float4 av = *(const float4*)(Ap + k0);
        float4 bv = *(const float4*)(Bp + k0);
        As[la_c+0][la_r] = av.x; As[la_c+1][la_r] = av.y;
        As[la_c+2][la_r] = av.z; As[la_c+3][la_r] = av.w;
        Bs[la_c+0][la_r] = bv.x; Bs[la_c+1][la_r] = bv.y;
        Bs[la_c+2][la_r] = bv.z; Bs[la_c+3][la_r] = bv.w;
        __syncthreads();
        #pragma unroll
        for (int kk = 0; kk < 8; kk++) {
            float a[8], bb2[8];
            #pragma unroll
            for (int i = 0; i < 8; i++) a[i]   = As[kk][r + i];
            #pragma unroll
            for (int j = 0; j < 8; j++) bb2[j] = Bs[kk][c + j];
            #pragma unroll
            for (int i = 0; i < 8; i++)
                #pragma unroll
                for (int j = 0; j < 8; j++)
                    acc[i][j] = fmaf(a[i], bb2[j], acc[i][j]);
        }
        __syncthreads();
    }

    // Epilogue (vectorized float4 stores)
    #pragma unroll
    for (int i = 0; i < 8; i++) {
        long rr = row0 + r + i;
        float* Crow = C + rr * (long)ldc + col0 + c;
        #pragma unroll
        for (int j4 = 0; j4 < 2; j4++) {
            float vv[4];
            #pragma unroll
            for (int u = 0; u < 4; u++) {
                int j = j4*4 + u;
                float v = acc[i][j] * alpha;
                if (bias)    v += bias[col0 + c + j];
                if (do_gelu) v  = gelu_f(v);
                vv[u] = v;
            }
            if (resid) {
                float4 rv = *(const float4*)(resid + rr * (long)ldr + col0 + c + j4*4);
                vv[0] += rv.x; vv[1] += rv.y; vv[2] += rv.z; vv[3] += rv.w;
            }
            float4 o; o.x = vv[0]; o.y = vv[1]; o.z = vv[2]; o.w = vv[3];
            *(float4*)(Crow + j4*4) = o;
        }
    }
}

// ----------------------------------------------------------------------------
// C[i,j] = resid[i,j] + sum_k A[k,i]*B[k,j]   (TN GEMM for O = A_t^T @ V)
// 128x64x16 tile, 256 threads, 8x4 microtile.
// ----------------------------------------------------------------------------
__global__ __launch_bounds__(256, 2)
void gemm_tn_kernel(const float* __restrict__ A, const float* __restrict__ Bm,
                    float* __restrict__ C,
                    int K, int lda, int ldb, int ldc,
                    long aOut, long aIn, long bOut, long bIn,
                    long cOut, long cIn, int Hn,
                    const float* __restrict__ resid)
{
    int z  = blockIdx.z;
    int zo = z / Hn, zi = z % Hn;
    A  += zo*aOut + zi*aIn;
    Bm += zo*bOut + zi*bIn;
    C  += zo*cOut + zi*cIn;
    const float* R = resid + zo*cOut + zi*cIn;

    __shared__ float As[16][128];
    __shared__ float Bs[16][64];

    int tid = threadIdx.x;
    long i0 = (long)blockIdx.y * 128;
    long j0 = (long)blockIdx.x * 64;

    float acc[8][4];
    #pragma unroll
    for (int i = 0; i < 8; i++)
        #pragma unroll
        for (int j = 0; j < 4; j++) acc[i][j] = 0.0f;

    int r = (tid >> 4) * 8;   // 0..120
    int c = (tid & 15) * 4;   // 0..60

    for (int k0 = 0; k0 < K; k0 += 16) {
        #pragma unroll
        for (int s = 0; s < 2; s++) {
            int idx = tid + s * 256;
            int kr = idx >> 5;
            int cc = (idx & 31) * 4;
            *(float4*)&As[kr][cc] =
                *(const float4*)(A + (long)(k0 + kr) * lda + i0 + cc);
        }
        {
            int kr = tid >> 4;
            int cc = (tid & 15) * 4;
            *(float4*)&Bs[kr][cc] =
                *(const float4*)(Bm + (long)(k0 + kr) * ldb + j0 + cc);
        }
        __syncthreads();
        #pragma unroll
        for (int kk = 0; kk < 16; kk++) {
            float a[8], b[4];
            #pragma unroll
            for (int i = 0; i < 8; i++) a[i] = As[kk][r + i];
            #pragma unroll
            for (int j = 0; j < 4; j++) b[j] = Bs[kk][c + j];
            #pragma unroll
            for (int i = 0; i < 8; i++)
                #pragma unroll
                for (int j = 0; j < 4; j++)
                    acc[i][j] = fmaf(a[i], b[j], acc[i][j]);
        }
        __syncthreads();
    }

    #pragma unroll
    for (int i = 0; i < 8; i++) {
        long rr = i0 + r + i;
        long cc = j0 + c;
        float4 rv = *(const float4*)(R + rr * (long)ldc + cc);
        float4 o;
        o.x = acc[i][0] + rv.x;
        o.y = acc[i][1] + rv.y;
        o.z = acc[i][2] + rv.z;
        o.w = acc[i][3] + rv.w;
        *(float4*)(C + rr * (long)ldc + cc) = o;
    }
}

// ----------------------------------------------------------------------------
// Row softmax of S^T (4096 contiguous floats per row). One block per row.
// Equivalent to reference's softmax over the query axis of S.
// ----------------------------------------------------------------------------
__global__ void softmax_kernel(float* __restrict__ S)
{
    float* p = S + (size_t)blockIdx.x * Pq;
    int t = threadIdx.x;  // 256 threads, 16 floats each
    float4 v[4];
    float lmax = -1e30f;
    #pragma unroll
    for (int s = 0; s < 4; s++) {
        v[s] = ((float4*)p)[t + s*256];
        lmax = fmaxf(lmax, fmaxf(fmaxf(v[s].x, v[s].y), fmaxf(v[s].z, v[s].w)));
    }
    __shared__ float sm[33];
    #pragma unroll
    for (int o = 16; o > 0; o >>= 1)
        lmax = fmaxf(lmax, __shfl_xor_sync(0xffffffffu, lmax, o));
    if ((t & 31) == 0) sm[t >> 5] = lmax;
    __syncthreads();
    if (t == 0) {
        float m = sm[0];
        #pragma unroll
        for (int w = 1; w < 8; w++) m = fmaxf(m, sm[w]);
        sm[32] = m;
    }
    __syncthreads();
    float rmax = sm[32];

    float lsum = 0.0f;
    #pragma unroll
    for (int s = 0; s < 4; s++) {
        v[s].x = __expf(v[s].x - rmax); lsum += v[s].x;
        v[s].y = __expf(v[s].y - rmax); lsum += v[s].y;
        v[s].z = __expf(v[s].z - rmax); lsum += v[s].z;
        v[s].w = __expf(v[s].w - rmax); lsum += v[s].w;
    }
    #pragma unroll
    for (int o = 16; o > 0; o >>= 1)
        lsum += __shfl_xor_sync(0xffffffffu, lsum, o);
    if ((t & 31) == 0) sm[t >> 5] = lsum;
    __syncthreads();
    if (t == 0) {
        float s0 = 0.0f;
        #pragma unroll
        for (int w = 0; w < 8; w++) s0 += sm[w];
        sm[32] = s0;
    }
    __syncthreads();
    float inv = 1.0f / sm[32];
    #pragma unroll
    for (int s = 0; s < 4; s++) {
        v[s].x *= inv; v[s].y *= inv; v[s].z *= inv; v[s].w *= inv;
        ((float4*)p)[t + s*256] = v[s];
    }
}

// ----------------------------------------------------------------------------
// Host launcher — graph-capturable (kernel launches only)
// ----------------------------------------------------------------------------
extern "C" void kernel_launch(void* const* d_in, const int* in_sizes, int n_in,
                              void* d_out, int out_size)
{
    const float* x  = (const float*)d_in[0];
    const float* g1 = (const float*)d_in[1];
    const float* b1 = (const float*)d_in[2];
    const float* W1 = (const float*)d_in[3];
    const float* g2 = (const float*)d_in[4];
    const float* b2 = (const float*)d_in[5];
    const float* Wa = (const float*)d_in[6];
    const float* ba = (const float*)d_in[7];
    const float* Wb = (const float*)d_in[8];
    const float* bb = (const float*)d_in[9];
    float* out = (float*)d_out;

    float *h, *qkv, *S, *out1, *tbuf;
    cudaGetSymbolAddress((void**)&h,    g_h);
    cudaGetSymbolAddress((void**)&qkv,  g_qkv);
    cudaGetSymbolAddress((void**)&S,    g_S);
    cudaGetSymbolAddress((void**)&out1, g_out1);
    cudaGetSymbolAddress((void**)&tbuf, g_t);

    // ---- LN1: h = LN(x) ----
    ln_reduce_kernel<<<dim3(NB_RED, Bq), 256>>>(x);
    ln_final_kernel<<<Bq, 256>>>();
    ln_apply_kernel<<<(Bq*PE/4 + 255)/256, 256>>>(x, g1, b1, h);

    // ---- QKV = h @ W1^T : [8192,1536] ----
    gemm_nt_kernel<<<dim3(E3/128, (Bq*Pq)/128, 1), 256>>>(
        h, W1, qkv,
        Eq, Eq, Eq, E3,
        0, 0, 0, 0, 0, 0, 1,
        1.0f, nullptr, nullptr, 0, 0);

    // ---- S^T[k,q] = scale * K[k,:]·Q[q,:] per (b,h) ----
    gemm_nt_kernel<<<dim3(Pq/128, Pq/128, Bq*Hq), 256>>>(
        qkv + Eq /*K*/, qkv /*Q*/, S,
        Dq, E3, E3, Pq,
        (long)Pq*E3, 64, (long)Pq*E3, 64,
        (long)Hq*Pq*Pq, (long)Pq*Pq, Hq,
        0.125f, nullptr, nullptr, 0, 0);

    // ---- row softmax of S^T == softmax over query axis of S ----
    softmax_kernel<<<Bq*Hq*Pq, 256>>>(S);

    // ---- out1 = x + A^T_t @ V  (TN GEMM, M=4096, N=64, K=4096 per (b,h)) ----
    gemm_tn_kernel<<<dim3(1, Pq/128, Bq*Hq), 256>>>(
        S, qkv + 2*Eq /*V*/, out1,
        Pq, Pq, E3, Eq,
        (long)Hq*Pq*Pq, (long)Pq*Pq,
        (long)Pq*E3, 64,
        (long)PE, 64, Hq,
        x);

    // ---- LN2: h = LN(out1) ----
    ln_reduce_kernel<<<dim3(NB_RED, Bq), 256>>>(out1);
    ln_final_kernel<<<Bq, 256>>>();
    ln_apply_kernel<<<(Bq*PE/4 + 255)/256, 256>>>(out1, g2, b2, h);

    // ---- t = gelu(h @ Wa^T + ba) : [8192,1536] ----
    gemm_nt_kernel<<<dim3(E3/128, (Bq*Pq)/128, 1), 256>>>(
        h, Wa, tbuf,
        Eq, Eq, Eq, E3,
        0, 0, 0, 0, 0, 0, 1,
        1.0f, ba, nullptr, 0, 1);

    // ---- out = gelu(t @ Wb^T + bb) + out1 : [8192,512] ----
    gemm_nt_kernel<<<dim3(Eq/128, (Bq*Pq)/128, 1), 256>>>(
        tbuf, Wb, out,
        E3, E3, E3, Eq,
        0, 0, 0, 0, 0, 0, 1,
        1.0f, bb, out1, Eq, 1);
}

// round 5
// speedup vs baseline: 1.0007x; 1.0007x over previous
#include <cuda_runtime.h>
#include <math.h>

// Problem constants
#define Bq 2
#define Pq 4096
#define Eq 512
#define Hq 8
#define Dq 64
#define E3 1536
#define PE (Pq*Eq)          // 2,097,152 elements per batch
#define NB_RED 256

// ----------------------------------------------------------------------------
// Scratch (device globals; no allocation allowed in kernel_launch)
// ----------------------------------------------------------------------------
__device__ float  g_h   [Bq*Pq*Eq];                 // LN output (reused for LN2)
__device__ float  g_qkv [Bq*Pq*E3];                 // QKV projection
__device__ float  g_S   [(size_t)Bq*Hq*Pq*Pq];      // S^T scores (1 GB)
__device__ float  g_out1[Bq*Pq*Eq];                 // x + attention
__device__ float  g_t   [Bq*Pq*E3];                 // MLP hidden
__device__ double g_part[Bq*NB_RED*2];              // LN partial sums
__device__ float  g_stats[Bq*2];                    // LN mean / invstd

// ----------------------------------------------------------------------------
// LayerNorm over [P,E] jointly, per batch — 3 stage deterministic reduction
// ----------------------------------------------------------------------------
__global__ void ln_reduce_kernel(const float* __restrict__ x)
{
    int b = blockIdx.y;
    const float4* xb = (const float4*)(x + (size_t)b * PE);
    const int n4 = PE / 4;
    double s = 0.0, s2 = 0.0;
    for (int i = blockIdx.x * blockDim.x + threadIdx.x; i < n4;
         i += gridDim.x * blockDim.x) {
        float4 v = xb[i];
        s  += (double)v.x + (double)v.y + (double)v.z + (double)v.w;
        s2 += (double)v.x*v.x + (double)v.y*v.y + (double)v.z*v.z + (double)v.w*v.w;
    }
    __shared__ double ss[256], ss2[256];
    int t = threadIdx.x;
    ss[t] = s; ss2[t] = s2;
    __syncthreads();
    for (int o = 128; o > 0; o >>= 1) {
        if (t < o) { ss[t] += ss[t+o]; ss2[t] += ss2[t+o]; }
        __syncthreads();
    }
    if (t == 0) {
        g_part[(b*NB_RED + blockIdx.x)*2 + 0] = ss[0];
        g_part[(b*NB_RED + blockIdx.x)*2 + 1] = ss2[0];
    }
}

__global__ void ln_final_kernel()
{
    int b = blockIdx.x;
    int t = threadIdx.x;   // 256 threads == NB_RED
    __shared__ double ss[256], ss2[256];
    ss[t]  = g_part[(b*NB_RED + t)*2 + 0];
    ss2[t] = g_part[(b*NB_RED + t)*2 + 1];
    __syncthreads();
    for (int o = 128; o > 0; o >>= 1) {
        if (t < o) { ss[t] += ss[t+o]; ss2[t] += ss2[t+o]; }
        __syncthreads();
    }
    if (t == 0) {
        double mean = ss[0] / (double)PE;
        double var  = ss2[0] / (double)PE - mean * mean;
        g_stats[b*2 + 0] = (float)mean;
        g_stats[b*2 + 1] = (float)(1.0 / sqrt(var + 1e-5));
    }
}

__global__ void ln_apply_kernel(const float* __restrict__ x,
                                const float* __restrict__ gam,
                                const float* __restrict__ bet,
                                float* __restrict__ out)
{
    const int n4 = PE / 4;
    int i = blockIdx.x * blockDim.x + threadIdx.x;
    if (i >= Bq * n4) return;
    int b  = i / n4;
    int pe = i - b * n4;
    float mean = g_stats[b*2 + 0];
    float inv  = g_stats[b*2 + 1];
    float4 xv = ((const float4*)x)[i];
    float4 gv = ((const float4*)gam)[pe];
    float4 bv = ((const float4*)bet)[pe];
    float4 o;
    o.x = (xv.x - mean) * inv * gv.x + bv.x;
    o.y = (xv.y - mean) * inv * gv.y + bv.y;
    o.z = (xv.z - mean) * inv * gv.z + bv.z;
    o.w = (xv.w - mean) * inv * gv.w + bv.w;
    ((float4*)out)[i] = o;
}

// ----------------------------------------------------------------------------
// Exact GELU (matches jax.nn.gelu(approximate=False))
// ----------------------------------------------------------------------------
__device__ __forceinline__ float gelu_f(float v)
{
    return 0.5f * v * (1.0f + erff(v * 0.70710678118654752440f));
}

// ----------------------------------------------------------------------------
// C[m,n] = alpha * sum_k A[m,k]*B[n,k]  (NT GEMM, both operands K-major)
// 128x128x8 tile, 256 threads, 8x8 microtile. Batched via blockIdx.z with
// decomposed (outer, inner) offsets: off = (z/Hn)*Out + (z%Hn)*In.
// Epilogue: optional bias[n], exact GELU, residual add.
// ----------------------------------------------------------------------------
__global__ __launch_bounds__(256, 2)
void gemm_nt_kernel(const float* __restrict__ A, const float* __restrict__ Bm,
                    float* __restrict__ C,
                    int K, int lda, int ldb, int ldc,
                    long aOut, long aIn, long bOut, long bIn,
                    long cOut, long cIn, int Hn,
                    float alpha,
                    const float* __restrict__ bias,
                    const float* __restrict__ resid, int ldr,
                    int do_gelu)
{
    int z  = blockIdx.z;
    int zo = z / Hn, zi = z % Hn;
    A  += zo*aOut + zi*aIn;
    Bm += zo*bOut + zi*bIn;
    C  += zo*cOut + zi*cIn;
    if (resid) resid += zo*cOut + zi*cIn;

    __shared__ float As[8][128];
    __shared__ float Bs[8][128];

    int tid  = threadIdx.x;
    long row0 = (long)blockIdx.y * 128;
    long col0 = (long)blockIdx.x * 128;

    int la_r = tid >> 1;            // 0..127
    int la_c = (tid & 1) * 4;       // 0 or 4

    float acc[8][8];
    #pragma unroll
    for (int i = 0; i < 8; i++)
        #pragma unroll
        for (int j = 0; j < 8; j++) acc[i][j] = 0.0f;

    int r = (tid >> 4) * 8;         // row offset within tile
    int c = (tid & 15) * 8;         // col offset within tile

    const float* Ap = A  + (row0 + la_r) * (long)lda + la_c;
    const float* Bp = Bm + (col0 + la_r) * (long)ldb + la_c;

    for (int k0 = 0; k0 < K; k0 += 8) {
        float4 av = *(const float4*)(Ap + k0);
        float4 bv = *(const float4*)(Bp + k0);
        As[la_c+0][la_r] = av.x; As[la_c+1][la_r] = av.y;
        As[la_c+2][la_r] = av.z; As[la_c+3][la_r] = av.w;
        Bs[la_c+0][la_r] = bv.x; Bs[la_c+1][la_r] = bv.y;
        Bs[la_c+2][la_r] = bv.z; Bs[la_c+3][la_r] = bv.w;
        __syncthreads();
        #pragma unroll
        for (int kk = 0; kk < 8; kk++) {
            float a[8], bb2[8];
            #pragma unroll
            for (int i = 0; i < 8; i++) a[i]   = As[kk][r + i];
            #pragma unroll
            for (int j = 0; j < 8; j++) bb2[j] = Bs[kk][c + j];
            #pragma unroll
            for (int i = 0; i < 8; i++)
                #pragma unroll
                for (int j = 0; j < 8; j++)
                    acc[i][j] = fmaf(a[i], bb2[j], acc[i][j]);
        }
        __syncthreads();
    }

    // Epilogue (vectorized float4 stores)
    #pragma unroll
    for (int i = 0; i < 8; i++) {
        long rr = row0 + r + i;
        float* Crow = C + rr * (long)ldc + col0 + c;
        #pragma unroll
        for (int j4 = 0; j4 < 2; j4++) {
            float vv[4];
            #pragma unroll
            for (int u = 0; u < 4; u++) {
                int j = j4*4 + u;
                float v = acc[i][j] * alpha;
                if (bias)    v += bias[col0 + c + j];
                if (do_gelu) v  = gelu_f(v);
                vv[u] = v;
            }
            if (resid) {
                float4 rv = *(const float4*)(resid + rr * (long)ldr + col0 + c + j4*4);
                vv[0] += rv.x; vv[1] += rv.y; vv[2] += rv.z; vv[3] += rv.w;
            }
            float4 o; o.x = vv[0]; o.y = vv[1]; o.z = vv[2]; o.w = vv[3];
            *(float4*)(Crow + j4*4) = o;
        }
    }
}

// ----------------------------------------------------------------------------
// C[i,j] = resid[i,j] + sum_k A[k,i]*B[k,j]   (TN GEMM for O = A_t^T @ V)
// 128x64x16 tile, 256 threads, 8x4 microtile.
// ----------------------------------------------------------------------------
__global__ __launch_bounds__(256, 2)
void gemm_tn_kernel(const float* __restrict__ A, const float* __restrict__ Bm,
                    float* __restrict__ C,
                    int K, int lda, int ldb, int ldc,
                    long aOut, long aIn, long bOut, long bIn,
                    long cOut, long cIn, int Hn,
                    const float* __restrict__ resid)
{
    int z  = blockIdx.z;
    int zo = z / Hn, zi = z % Hn;
    A  += zo*aOut + zi*aIn;
    Bm += zo*bOut + zi*bIn;
    C  += zo*cOut + zi*cIn;
    const float* R = resid + zo*cOut + zi*cIn;

    __shared__ float As[16][128];
    __shared__ float Bs[16][64];

    int tid = threadIdx.x;
    long i0 = (long)blockIdx.y * 128;
    long j0 = (long)blockIdx.x * 64;

    float acc[8][4];
    #pragma unroll
    for (int i = 0; i < 8; i++)
        #pragma unroll
        for (int j = 0; j < 4; j++) acc[i][j] = 0.0f;

    int r = (tid >> 4) * 8;   // 0..120
    int c = (tid & 15) * 4;   // 0..60

    for (int k0 = 0; k0 < K; k0 += 16) {
        #pragma unroll
        for (int s = 0; s < 2; s++) {
            int idx = tid + s * 256;
            int kr = idx >> 5;
            int cc = (idx & 31) * 4;
            *(float4*)&As[kr][cc] =
                *(const float4*)(A + (long)(k0 + kr) * lda + i0 + cc);
        }
        {
            int kr = tid >> 4;
            int cc = (tid & 15) * 4;
            *(float4*)&Bs[kr][cc] =
                *(const float4*)(Bm + (long)(k0 + kr) * ldb + j0 + cc);
        }
        __syncthreads();
        #pragma unroll
        for (int kk = 0; kk < 16; kk++) {
            float a[8], b[4];
            #pragma unroll
            for (int i = 0; i < 8; i++) a[i] = As[kk][r + i];
            #pragma unroll
            for (int j = 0; j < 4; j++) b[j] = Bs[kk][c + j];
            #pragma unroll
            for (int i = 0; i < 8; i++)
                #pragma unroll
                for (int j = 0; j < 4; j++)
                    acc[i][j] = fmaf(a[i], b[j], acc[i][j]);
        }
        __syncthreads();
    }

    #pragma unroll
    for (int i = 0; i < 8; i++) {
        long rr = i0 + r + i;
        long cc = j0 + c;
        float4 rv = *(const float4*)(R + rr * (long)ldc + cc);
        float4 o;
        o.x = acc[i][0] + rv.x;
        o.y = acc[i][1] + rv.y;
        o.z = acc[i][2] + rv.z;
        o.w = acc[i][3] + rv.w;
        *(float4*)(C + rr * (long)ldc + cc) = o;
    }
}

// ----------------------------------------------------------------------------
// Row softmax of S^T (4096 contiguous floats per row). One block per row.
// Equivalent to reference's softmax over the query axis of S.
// ----------------------------------------------------------------------------
__global__ void softmax_kernel(float* __restrict__ S)
{
    float* p = S + (size_t)blockIdx.x * Pq;
    int t = threadIdx.x;  // 256 threads, 16 floats each
    float4 v[4];
    float lmax = -1e30f;
    #pragma unroll
    for (int s = 0; s < 4; s++) {
        v[s] = ((float4*)p)[t + s*256];
        lmax = fmaxf(lmax, fmaxf(fmaxf(v[s].x, v[s].y), fmaxf(v[s].z, v[s].w)));
    }
    __shared__ float sm[33];
    #pragma unroll
    for (int o = 16; o > 0; o >>= 1)
        lmax = fmaxf(lmax, __shfl_xor_sync(0xffffffffu, lmax, o));
    if ((t & 31) == 0) sm[t >> 5] = lmax;
    __syncthreads();
    if (t == 0) {
        float m = sm[0];
        #pragma unroll
        for (int w = 1; w < 8; w++) m = fmaxf(m, sm[w]);
        sm[32] = m;
    }
    __syncthreads();
    float rmax = sm[32];

    float lsum = 0.0f;
    #pragma unroll
    for (int s = 0; s < 4; s++) {
        v[s].x = __expf(v[s].x - rmax); lsum += v[s].x;
        v[s].y = __expf(v[s].y - rmax); lsum += v[s].y;
        v[s].z = __expf(v[s].z - rmax); lsum += v[s].z;
        v[s].w = __expf(v[s].w - rmax); lsum += v[s].w;
    }
    #pragma unroll
    for (int o = 16; o > 0; o >>= 1)
        lsum += __shfl_xor_sync(0xffffffffu, lsum, o);
    if ((t & 31) == 0) sm[t >> 5] = lsum;
    __syncthreads();
    if (t == 0) {
        float s0 = 0.0f;
        #pragma unroll
        for (int w = 0; w < 8; w++) s0 += sm[w];
        sm[32] = s0;
    }
    __syncthreads();
    float inv = 1.0f / sm[32];
    #pragma unroll
    for (int s = 0; s < 4; s++) {
        v[s].x *= inv; v[s].y *= inv; v[s].z *= inv; v[s].w *= inv;
        ((float4*)p)[t + s*256] = v[s];
    }
}

// ----------------------------------------------------------------------------
// Host launcher — graph-capturable (kernel launches only)
// ----------------------------------------------------------------------------
extern "C" void kernel_launch(void* const* d_in, const int* in_sizes, int n_in,
                              void* d_out, int out_size)
{
    const float* x  = (const float*)d_in[0];
    const float* g1 = (const float*)d_in[1];
    const float* b1 = (const float*)d_in[2];
    const float* W1 = (const float*)d_in[3];
    const float* g2 = (const float*)d_in[4];
    const float* b2 = (const float*)d_in[5];
    const float* Wa = (const float*)d_in[6];
    const float* ba = (const float*)d_in[7];
    const float* Wb = (const float*)d_in[8];
    const float* bb = (const float*)d_in[9];
    float* out = (float*)d_out;

    float *h, *qkv, *S, *out1, *tbuf;
    cudaGetSymbolAddress((void**)&h,    g_h);
    cudaGetSymbolAddress((void**)&qkv,  g_qkv);
    cudaGetSymbolAddress((void**)&S,    g_S);
    cudaGetSymbolAddress((void**)&out1, g_out1);
    cudaGetSymbolAddress((void**)&tbuf, g_t);

    // ---- LN1: h = LN(x) ----
    ln_reduce_kernel<<<dim3(NB_RED, Bq), 256>>>(x);
    ln_final_kernel<<<Bq, 256>>>();
    ln_apply_kernel<<<(Bq*PE/4 + 255)/256, 256>>>(x, g1, b1, h);

    // ---- QKV = h @ W1^T : [8192,1536] ----
    gemm_nt_kernel<<<dim3(E3/128, (Bq*Pq)/128, 1), 256>>>(
        h, W1, qkv,
        Eq, Eq, Eq, E3,
        0, 0, 0, 0, 0, 0, 1,
        1.0f, nullptr, nullptr, 0, 0);

    // ---- S^T[k,q] = scale * K[k,:]·Q[q,:] per (b,h) ----
    gemm_nt_kernel<<<dim3(Pq/128, Pq/128, Bq*Hq), 256>>>(
        qkv + Eq /*K*/, qkv /*Q*/, S,
        Dq, E3, E3, Pq,
        (long)Pq*E3, 64, (long)Pq*E3, 64,
        (long)Hq*Pq*Pq, (long)Pq*Pq, Hq,
        0.125f, nullptr, nullptr, 0, 0);

    // ---- row softmax of S^T == softmax over query axis of S ----
    softmax_kernel<<<Bq*Hq*Pq, 256>>>(S);

    // ---- out1 = x + A^T_t @ V  (TN GEMM, M=4096, N=64, K=4096 per (b,h)) ----
    gemm_tn_kernel<<<dim3(1, Pq/128, Bq*Hq), 256>>>(
        S, qkv + 2*Eq /*V*/, out1,
        Pq, Pq, E3, Eq,
        (long)Hq*Pq*Pq, (long)Pq*Pq,
        (long)Pq*E3, 64,
        (long)PE, 64, Hq,
        x);

    // ---- LN2: h = LN(out1) ----
    ln_reduce_kernel<<<dim3(NB_RED, Bq), 256>>>(out1);
    ln_final_kernel<<<Bq, 256>>>();
    ln_apply_kernel<<<(Bq*PE/4 + 255)/256, 256>>>(out1, g2, b2, h);

    // ---- t = gelu(h @ Wa^T + ba) : [8192,1536] ----
    gemm_nt_kernel<<<dim3(E3/128, (Bq*Pq)/128, 1), 256>>>(
        h, Wa, tbuf,
        Eq, Eq, Eq, E3,
        0, 0, 0, 0, 0, 0, 1,
        1.0f, ba, nullptr, 0, 1);

    // ---- out = gelu(t @ Wb^T + bb) + out1 : [8192,512] ----
    gemm_nt_kernel<<<dim3(Eq/128, (Bq*Pq)/128, 1), 256>>>(
        tbuf, Wb, out,
        E3, E3, E3, Eq,
        0, 0, 0, 0, 0, 0, 1,
        1.0f, bb, out1, Eq, 1);
}

// round 7
// speedup vs baseline: 1.6386x; 1.6375x over previous
#include <cuda_runtime.h>
#include <math.h>
#include <stdint.h>

#define Bq 2
#define Pq 4096
#define Eq 512
#define Hq 8
#define E3 1536
#define PE (Pq*Eq)
#define NB_RED 256

// ------------------------------------------------------------- scratch
__device__ float  g_h   [(size_t)Bq*Pq*Eq];
__device__ float  g_qkv [(size_t)Bq*Pq*E3];
__device__ float  g_S   [(size_t)Bq*Hq*Pq*Pq];   // S^T logits (1 GB)
__device__ float  g_out1[(size_t)Bq*Pq*Eq];
__device__ float  g_t   [(size_t)Bq*Pq*E3];
__device__ float  g_rmax[(size_t)Bq*Hq*Pq];
__device__ float  g_rinv[(size_t)Bq*Hq*Pq];
__device__ double g_part[Bq*NB_RED*2];
__device__ float  g_stats[Bq*2];

// ------------------------------------------------------------- helpers
__device__ __forceinline__ uint32_t f2tf32(float x){
    uint32_t r; asm("cvt.rna.tf32.f32 %0, %1;" : "=r"(r) : "f"(x)); return r;
}
__device__ __forceinline__ uint4 rna4(float4 v){
    return make_uint4(f2tf32(v.x), f2tf32(v.y), f2tf32(v.z), f2tf32(v.w));
}
__device__ __forceinline__ void split4(float4 v, uint4& h, uint4& l){
    h = rna4(v);
    l = make_uint4(f2tf32(v.x - __uint_as_float(h.x)),
                   f2tf32(v.y - __uint_as_float(h.y)),
                   f2tf32(v.z - __uint_as_float(h.z)),
                   f2tf32(v.w - __uint_as_float(h.w)));
}
__device__ __forceinline__ void mma8(float d[4], const uint32_t a[4], const uint32_t b[2]){
    asm volatile(
        "mma.sync.aligned.m16n8k8.row.col.f32.tf32.tf32.f32 "
        "{%0,%1,%2,%3}, {%4,%5,%6,%7}, {%8,%9}, {%0,%1,%2,%3};"
        : "+f"(d[0]), "+f"(d[1]), "+f"(d[2]), "+f"(d[3])
        : "r"(a[0]), "r"(a[1]), "r"(a[2]), "r"(a[3]), "r"(b[0]), "r"(b[1]));
}
__device__ __forceinline__ float gelu_f(float v){
    return 0.5f * v * (1.0f + erff(v * 0.70710678118654752440f));
}

// ============================================================== LayerNorm
__global__ void ln_reduce_kernel(const float* __restrict__ x)
{
    int b = blockIdx.y;
    const float4* xb = (const float4*)(x + (size_t)b * PE);
    const int n4 = PE / 4;
    double s = 0.0, s2 = 0.0;
    for (int i = blockIdx.x * blockDim.x + threadIdx.x; i < n4;
         i += gridDim.x * blockDim.x) {
        float4 v = xb[i];
        s  += (double)v.x + (double)v.y + (double)v.z + (double)v.w;
        s2 += (double)v.x*v.x + (double)v.y*v.y + (double)v.z*v.z + (double)v.w*v.w;
    }
    __shared__ double ss[256], ss2[256];
    int t = threadIdx.x;
    ss[t] = s; ss2[t] = s2;
    __syncthreads();
    for (int o = 128; o > 0; o >>= 1) {
        if (t < o) { ss[t] += ss[t+o]; ss2[t] += ss2[t+o]; }
        __syncthreads();
    }
    if (t == 0) {
        g_part[(b*NB_RED + blockIdx.x)*2 + 0] = ss[0];
        g_part[(b*NB_RED + blockIdx.x)*2 + 1] = ss2[0];
    }
}

__global__ void ln_final_kernel()
{
    int b = blockIdx.x, t = threadIdx.x;
    __shared__ double ss[256], ss2[256];
    ss[t]  = g_part[(b*NB_RED + t)*2 + 0];
    ss2[t] = g_part[(b*NB_RED + t)*2 + 1];
    __syncthreads();
    for (int o = 128; o > 0; o >>= 1) {
        if (t < o) { ss[t] += ss[t+o]; ss2[t] += ss2[t+o]; }
        __syncthreads();
    }
    if (t == 0) {
        double mean = ss[0] / (double)PE;
        double var  = ss2[0] / (double)PE - mean * mean;
        g_stats[b*2 + 0] = (float)mean;
        g_stats[b*2 + 1] = (float)(1.0 / sqrt(var + 1e-5));
    }
}

__global__ void ln_apply_kernel(const float* __restrict__ x,
                                const float* __restrict__ gam,
                                const float* __restrict__ bet,
                                float* __restrict__ out)
{
    const int n4 = PE / 4;
    int i = blockIdx.x * blockDim.x + threadIdx.x;
    if (i >= Bq * n4) return;
    int b = i / n4, pe = i - b * n4;
    float mean = g_stats[b*2 + 0], inv = g_stats[b*2 + 1];
    float4 xv = ((const float4*)x)[i];
    float4 gv = ((const float4*)gam)[pe];
    float4 bv = ((const float4*)bet)[pe];
    float4 o;
    o.x = (xv.x - mean) * inv * gv.x + bv.x;
    o.y = (xv.y - mean) * inv * gv.y + bv.y;
    o.z = (xv.z - mean) * inv * gv.z + bv.z;
    o.w = (xv.w - mean) * inv * gv.w + bv.w;
    ((float4*)out)[i] = o;
}

// ============================================================== NT GEMM (mma.sync tf32)
// C[m,n] = alpha * sum_k A[m,k] B[n,k]  (+bias, +gelu, +resid)
// 128x128 block, 256 threads (8 warps of 64x32), KT=16.
// SPLIT => 3xTF32 hi/lo (weights); else plain tf32 (attention scores).
// smem stride 20 floats (== 4 mod 32) makes fragment reads bank-conflict-free.
template<bool SPLIT>
__global__ __launch_bounds__(256)
void gemm_nt_mma(const float* __restrict__ A, const float* __restrict__ B,
                 float* __restrict__ C, int K, int lda, int ldb, int ldc,
                 long aOut, long aIn, long bOut, long bIn, long cOut, long cIn,
                 int Hn, float alpha, const float* __restrict__ bias,
                 const float* __restrict__ resid, int do_gelu)
{
    int z = blockIdx.z; int zo = z / Hn, zi = z % Hn;
    A += zo*aOut + zi*aIn; B += zo*bOut + zi*bIn; C += zo*cOut + zi*cIn;
    const float* R = resid ? resid + zo*cOut + zi*cIn : (const float*)0;

    extern __shared__ uint32_t sm[];
    uint32_t* Ah = sm;                 // [128][20]
    uint32_t* Bh = sm + 2560;
    uint32_t* Al = sm + 5120;          // SPLIT only
    uint32_t* Bl = sm + 7680;

    int tid = threadIdx.x, lane = tid & 31, wid = tid >> 5;
    int gid = lane >> 2, tig = lane & 3;
    int wm = (wid >> 2) * 64, wn = (wid & 3) * 32;
    long row0 = (long)blockIdx.y * 128, col0 = (long)blockIdx.x * 128;
    const float* Ab = A + row0 * lda;
    const float* Bb = B + col0 * ldb;

    float acc[4][4][4];
    #pragma unroll
    for (int i = 0; i < 4; i++)
        #pragma unroll
        for (int j = 0; j < 4; j++)
            #pragma unroll
            for (int u = 0; u < 4; u++) acc[i][j][u] = 0.0f;

    for (int kt = 0; kt < K; kt += 16) {
        __syncthreads();
        #pragma unroll
        for (int i = 0; i < 2; i++) {
            int idx = tid + i * 256;         // 0..511
            int row = idx >> 2;              // 4 float4 per row
            int c4  = (idx & 3) * 4;
            float4 va = *(const float4*)(Ab + (long)row * lda + kt + c4);
            float4 vb = *(const float4*)(Bb + (long)row * ldb + kt + c4);
            if (SPLIT) {
                uint4 h, l;
                split4(va, h, l);
                *(uint4*)&Ah[row*20 + c4] = h; *(uint4*)&Al[row*20 + c4] = l;
                split4(vb, h, l);
                *(uint4*)&Bh[row*20 + c4] = h; *(uint4*)&Bl[row*20 + c4] = l;
            } else {
                *(uint4*)&Ah[row*20 + c4] = rna4(va);
                *(uint4*)&Bh[row*20 + c4] = rna4(vb);
            }
        }
        __syncthreads();
        #pragma unroll
        for (int kk = 0; kk < 16; kk += 8) {
            uint32_t bh[4][2], bl[4][2];
            #pragma unroll
            for (int tn = 0; tn < 4; tn++) {
                int n = wn + tn*8 + gid, k = kk + tig;
                bh[tn][0] = Bh[n*20 + k]; bh[tn][1] = Bh[n*20 + k + 4];
                if (SPLIT) { bl[tn][0] = Bl[n*20 + k]; bl[tn][1] = Bl[n*20 + k + 4]; }
            }
            #pragma unroll
            for (int tm = 0; tm < 4; tm++) {
                int m = wm + tm*16 + gid, k = kk + tig;
                uint32_t ah[4], al[4];
                ah[0] = Ah[m*20 + k];     ah[1] = Ah[(m+8)*20 + k];
                ah[2] = Ah[m*20 + k + 4]; ah[3] = Ah[(m+8)*20 + k + 4];
                if (SPLIT) {
                    al[0] = Al[m*20 + k];     al[1] = Al[(m+8)*20 + k];
                    al[2] = Al[m*20 + k + 4]; al[3] = Al[(m+8)*20 + k + 4];
                }
                #pragma unroll
                for (int tn = 0; tn < 4; tn++) {
                    mma8(acc[tm][tn], ah, bh[tn]);
                    if (SPLIT) {
                        mma8(acc[tm][tn], al, bh[tn]);
                        mma8(acc[tm][tn], ah, bl[tn]);
                    }
                }
            }
        }
    }

    // epilogue: pairs (c0,c1) at (row, col..col+1), (c2,c3) at (row+8, ..)
    #pragma unroll
    for (int tm = 0; tm < 4; tm++) {
        #pragma unroll
        for (int tn = 0; tn < 4; tn++) {
            long row = row0 + wm + tm*16 + gid;
            long col = col0 + wn + tn*8 + tig*2;
            #pragma unroll
            for (int half = 0; half < 2; half++) {
                long r = row + half*8;
                float v0 = acc[tm][tn][half*2+0] * alpha;
                float v1 = acc[tm][tn][half*2+1] * alpha;
                if (bias) { v0 += bias[col]; v1 += bias[col+1]; }
                if (do_gelu) { v0 = gelu_f(v0); v1 = gelu_f(v1); }
                if (R) {
                    float2 rv = *(const float2*)(R + r*ldc + col);
                    v0 += rv.x; v1 += rv.y;
                }
                float2 o; o.x = v0; o.y = v1;
                *(float2*)(C + r*ldc + col) = o;
            }
        }
    }
}

// ============================================================== row stats
// Per row of S^T (4096 floats): max and 1/sum(exp(v-max)).
__global__ void rowstat_kernel(const float* __restrict__ S,
                               float* __restrict__ rmax, float* __restrict__ rinv)
{
    const float* p = S + (size_t)blockIdx.x * Pq;
    int t = threadIdx.x;
    float4 v[4];
    float lmax = -1e30f;
    #pragma unroll
    for (int s = 0; s < 4; s++) {
        v[s] = ((const float4*)p)[t + s*256];
        lmax = fmaxf(lmax, fmaxf(fmaxf(v[s].x, v[s].y), fmaxf(v[s].z, v[s].w)));
    }
    __shared__ float sm[33];
    #pragma unroll
    for (int o = 16; o > 0; o >>= 1)
        lmax = fmaxf(lmax, __shfl_xor_sync(0xffffffffu, lmax, o));
    if ((t & 31) == 0) sm[t >> 5] = lmax;
    __syncthreads();
    if (t == 0) {
        float m = sm[0];
        #pragma unroll
        for (int w = 1; w < 8; w++) m = fmaxf(m, sm[w]);
        sm[32] = m;
    }
    __syncthreads();
    float M = sm[32];
    float lsum = 0.0f;
    #pragma unroll
    for (int s = 0; s < 4; s++) {
        lsum += __expf(v[s].x - M) + __expf(v[s].y - M)
              + __expf(v[s].z - M) + __expf(v[s].w - M);
    }
    #pragma unroll
    for (int o = 16; o > 0; o >>= 1)
        lsum += __shfl_xor_sync(0xffffffffu, lsum, o);
    if ((t & 31) == 0) sm[t >> 5] = lsum;
    __syncthreads();
    if (t == 0) {
        float s0 = 0.0f;
        #pragma unroll
        for (int w = 0; w < 8; w++) s0 += sm[w];
        rmax[blockIdx.x] = M;
        rinv[blockIdx.x] = 1.0f / s0;
    }
}

// ============================================================== attention O
// out1[q, zi*64+d] = x[q,..] + sum_k softmax-weight(k,q) * V[k,d]
// Stages S^T [k][q] coalesced with exp fused; mma fragments read the staging
// buffer directly (stride 136 == 8 mod 32 -> conflict-free transpose reads).
__global__ __launch_bounds__(256)
void attn_o_mma(const float* __restrict__ St, const float* __restrict__ qkv,
                float* __restrict__ out1, const float* __restrict__ x,
                const float* __restrict__ rmax, const float* __restrict__ rinv)
{
    int z = blockIdx.z, zo = z >> 3, zi = z & 7;
    const float* Sb  = St   + (size_t)z * Pq * Pq;
    const float* Vb  = qkv  + (size_t)zo * Pq * E3 + 2*Eq + (size_t)zi*64;
    float*       Cb  = out1 + (size_t)zo * PE + (size_t)zi*64;
    const float* Rb  = x    + (size_t)zo * PE + (size_t)zi*64;
    const float* rmx = rmax + (size_t)z * Pq;
    const float* riv = rinv + (size_t)z * Pq;

    __shared__ uint32_t stP[32*136];   // [k][q] tf32, stride 136
    __shared__ uint32_t stV[32*72];    // [k][d] tf32, stride 72

    int tid = threadIdx.x, lane = tid & 31, wid = tid >> 5;
    int gid = lane >> 2, tig = lane & 3;
    int wm = (wid >> 2) * 64, wn = (wid & 3) * 16;   // warp tile 64x16
    long q0 = (long)blockIdx.y * 128;

    float acc[4][2][4];
    #pragma unroll
    for (int i = 0; i < 4; i++)
        #pragma unroll
        for (int j = 0; j < 2; j++)
            #pragma unroll
            for (int u = 0; u < 4; u++) acc[i][j][u] = 0.0f;

    for (int k0 = 0; k0 < Pq; k0 += 32) {
        __syncthreads();
        #pragma unroll
        for (int i = 0; i < 4; i++) {
            int idx = tid + i * 256;          // 1024 float4 = 32k x 128q
            int kr = idx >> 5, q4 = (idx & 31) * 4;
            int gr = k0 + kr;
            float4 v = *(const float4*)(Sb + (size_t)gr * Pq + q0 + q4);
            float m = rmx[gr], iv = riv[gr];
            v.x = __expf(v.x - m) * iv; v.y = __expf(v.y - m) * iv;
            v.z = __expf(v.z - m) * iv; v.w = __expf(v.w - m) * iv;
            *(uint4*)&stP[kr*136 + q4] = rna4(v);
        }
        #pragma unroll
        for (int i = 0; i < 2; i++) {
            int idx = tid + i * 256;          // 512 float4 = 32k x 64d
            int kr = idx >> 4, d4 = (idx & 15) * 4;
            float4 v = *(const float4*)(Vb + (size_t)(k0 + kr) * E3 + d4);
            *(uint4*)&stV[kr*72 + d4] = rna4(v);
        }
        __syncthreads();
        #pragma unroll
        for (int kk = 0; kk < 32; kk += 8) {
            uint32_t b[2][2];
            #pragma unroll
            for (int tn = 0; tn < 2; tn++) {
                int n = wn + tn*8 + gid;
                b[tn][0] = stV[(kk + tig)*72 + n];
                b[tn][1] = stV[(kk + tig + 4)*72 + n];
            }
            #pragma unroll
            for (int tm = 0; tm < 4; tm++) {
                int q = wm + tm*16 + gid;
                uint32_t a[4];
                a[0] = stP[(kk + tig)*136 + q];
                a[1] = stP[(kk + tig)*136 + q + 8];
                a[2] = stP[(kk + tig + 4)*136 + q];
                a[3] = stP[(kk + tig + 4)*136 + q + 8];
                #pragma unroll
                for (int tn = 0; tn < 2; tn++)
                    mma8(acc[tm][tn], a, b[tn]);
            }
        }
    }

    #pragma unroll
    for (int tm = 0; tm < 4; tm++) {
        #pragma unroll
        for (int tn = 0; tn < 2; tn++) {
            long q = q0 + wm + tm*16 + gid;
            int  d = wn + tn*8 + tig*2;
            #pragma unroll
            for (int half = 0; half < 2; half++) {
                long r = q + half*8;
                float2 rv = *(const float2*)(Rb + r*Eq + d);
                float2 o;
                o.x = acc[tm][tn][half*2+0] + rv.x;
                o.y = acc[tm][tn][half*2+1] + rv.y;
                *(float2*)(Cb + r*Eq + d) = o;
            }
        }
    }
}

// ============================================================== launcher
extern "C" void kernel_launch(void* const* d_in, const int* in_sizes, int n_in,
                              void* d_out, int out_size)
{
    const float* x  = (const float*)d_in[0];
    const float* g1 = (const float*)d_in[1];
    const float* b1 = (const float*)d_in[2];
    const float* W1 = (const float*)d_in[3];
    const float* g2 = (const float*)d_in[4];
    const float* b2 = (const float*)d_in[5];
    const float* Wa = (const float*)d_in[6];
    const float* ba = (const float*)d_in[7];
    const float* Wb = (const float*)d_in[8];
    const float* bb = (const float*)d_in[9];
    float* out = (float*)d_out;

    float *h, *qkv, *S, *out1, *tbuf, *rmx, *riv;
    cudaGetSymbolAddress((void**)&h,    g_h);
    cudaGetSymbolAddress((void**)&qkv,  g_qkv);
    cudaGetSymbolAddress((void**)&S,    g_S);
    cudaGetSymbolAddress((void**)&out1, g_out1);
    cudaGetSymbolAddress((void**)&tbuf, g_t);
    cudaGetSymbolAddress((void**)&rmx,  g_rmax);
    cudaGetSymbolAddress((void**)&riv,  g_rinv);

    const int SM_SPLIT = 10240 * 4;   // 4 tiles of 128x20 uint
    const int SM_PLAIN = 5120 * 4;    // 2 tiles

    // LN1
    ln_reduce_kernel<<<dim3(NB_RED, Bq), 256>>>(x);
    ln_final_kernel<<<Bq, 256>>>();
    ln_apply_kernel<<<(Bq*PE/4 + 255)/256, 256>>>(x, g1, b1, h);

    // QKV = h @ W1^T   [8192,1536], K=512
    gemm_nt_mma<true><<<dim3(E3/128, (Bq*Pq)/128, 1), 256, SM_SPLIT>>>(
        h, W1, qkv, Eq, Eq, Eq, E3,
        0, 0, 0, 0, 0, 0, 1, 1.0f, (const float*)0, (const float*)0, 0);

    // S^T[k,q] = 0.125 * K[k]·Q[q]  per (b,h), K=64
    gemm_nt_mma<false><<<dim3(Pq/128, Pq/128, Bq*Hq), 256, SM_PLAIN>>>(
        qkv + Eq, qkv, S, 64, E3, E3, Pq,
        (long)Pq*E3, 64, (long)Pq*E3, 64,
        (long)Hq*Pq*Pq, (long)Pq*Pq, Hq,
        0.125f, (const float*)0, (const float*)0, 0);

    // per-row softmax stats of S^T
    rowstat_kernel<<<Bq*Hq*Pq, 256>>>(S, rmx, riv);

    // out1 = x + softmax-weighted V (exp fused into staging load)
    attn_o_mma<<<dim3(1, Pq/128, Bq*Hq), 256>>>(S, qkv, out1, x, rmx, riv);

    // LN2
    ln_reduce_kernel<<<dim3(NB_RED, Bq), 256>>>(out1);
    ln_final_kernel<<<Bq, 256>>>();
    ln_apply_kernel<<<(Bq*PE/4 + 255)/256, 256>>>(out1, g2, b2, h);

    // t = gelu(h @ Wa^T + ba)   [8192,1536], K=512
    gemm_nt_mma<true><<<dim3(E3/128, (Bq*Pq)/128, 1), 256, SM_SPLIT>>>(
        h, Wa, tbuf, Eq, Eq, Eq, E3,
        0, 0, 0, 0, 0, 0, 1, 1.0f, ba, (const float*)0, 1);

    // out = gelu(t @ Wb^T + bb) + out1   [8192,512], K=1536
    gemm_nt_mma<true><<<dim3(Eq/128, (Bq*Pq)/128, 1), 256, SM_SPLIT>>>(
        tbuf, Wb, out, E3, E3, E3, Eq,
        0, 0, 0, 0, 0, 0, 1, 1.0f, bb, out1, 1);
}

// round 8
// speedup vs baseline: 1.9953x; 1.2177x over previous
#include <cuda_runtime.h>
#include <cuda_fp16.h>
#include <math.h>
#include <stdint.h>

#define Bq 2
#define Pq 4096
#define Eq 512
#define Hq 8
#define E3 1536
#define PE (Pq*Eq)
#define NB_RED 256

// ------------------------------------------------------------- scratch
__device__ float  g_h   [(size_t)Bq*Pq*Eq];
__device__ float  g_qkv [(size_t)Bq*Pq*E3];
__device__ __half g_E   [(size_t)Bq*Hq*Pq*Pq];   // exp(S^T) fp16 (0.5 GB)
__device__ float  g_out1[(size_t)Bq*Pq*Eq];
__device__ float  g_t   [(size_t)Bq*Pq*E3];
__device__ float  g_rinv[(size_t)Bq*Hq*Pq];
__device__ float  g_psum[(size_t)Bq*Hq*Pq*32];   // per-(k, q-block) partial sums
__device__ double g_part[Bq*NB_RED*2];
__device__ float  g_stats[Bq*2];

// ------------------------------------------------------------- helpers
__device__ __forceinline__ uint32_t f2tf32(float x){
    uint32_t r; asm("cvt.rna.tf32.f32 %0, %1;" : "=r"(r) : "f"(x)); return r;
}
__device__ __forceinline__ uint4 rna4(float4 v){
    return make_uint4(f2tf32(v.x), f2tf32(v.y), f2tf32(v.z), f2tf32(v.w));
}
__device__ __forceinline__ void split4(float4 v, uint4& h, uint4& l){
    h = rna4(v);
    l = make_uint4(f2tf32(v.x - __uint_as_float(h.x)),
                   f2tf32(v.y - __uint_as_float(h.y)),
                   f2tf32(v.z - __uint_as_float(h.z)),
                   f2tf32(v.w - __uint_as_float(h.w)));
}
__device__ __forceinline__ void mma8(float d[4], const uint32_t a[4], const uint32_t b[2]){
    asm volatile(
        "mma.sync.aligned.m16n8k8.row.col.f32.tf32.tf32.f32 "
        "{%0,%1,%2,%3}, {%4,%5,%6,%7}, {%8,%9}, {%0,%1,%2,%3};"
        : "+f"(d[0]), "+f"(d[1]), "+f"(d[2]), "+f"(d[3])
        : "r"(a[0]), "r"(a[1]), "r"(a[2]), "r"(a[3]), "r"(b[0]), "r"(b[1]));
}
__device__ __forceinline__ float gelu_f(float v){
    return 0.5f * v * (1.0f + erff(v * 0.70710678118654752440f));
}

// ============================================================== LayerNorm
__global__ void ln_reduce_kernel(const float* __restrict__ x)
{
    int b = blockIdx.y;
    const float4* xb = (const float4*)(x + (size_t)b * PE);
    const int n4 = PE / 4;
    double s = 0.0, s2 = 0.0;
    for (int i = blockIdx.x * blockDim.x + threadIdx.x; i < n4;
         i += gridDim.x * blockDim.x) {
        float4 v = xb[i];
        s  += (double)v.x + (double)v.y + (double)v.z + (double)v.w;
        s2 += (double)v.x*v.x + (double)v.y*v.y + (double)v.z*v.z + (double)v.w*v.w;
    }
    __shared__ double ss[256], ss2[256];
    int t = threadIdx.x;
    ss[t] = s; ss2[t] = s2;
    __syncthreads();
    for (int o = 128; o > 0; o >>= 1) {
        if (t < o) { ss[t] += ss[t+o]; ss2[t] += ss2[t+o]; }
        __syncthreads();
    }
    if (t == 0) {
        g_part[(b*NB_RED + blockIdx.x)*2 + 0] = ss[0];
        g_part[(b*NB_RED + blockIdx.x)*2 + 1] = ss2[0];
    }
}

__global__ void ln_final_kernel()
{
    int b = blockIdx.x, t = threadIdx.x;
    __shared__ double ss[256], ss2[256];
    ss[t]  = g_part[(b*NB_RED + t)*2 + 0];
    ss2[t] = g_part[(b*NB_RED + t)*2 + 1];
    __syncthreads();
    for (int o = 128; o > 0; o >>= 1) {
        if (t < o) { ss[t] += ss[t+o]; ss2[t] += ss2[t+o]; }
        __syncthreads();
    }
    if (t == 0) {
        double mean = ss[0] / (double)PE;
        double var  = ss2[0] / (double)PE - mean * mean;
        g_stats[b*2 + 0] = (float)mean;
        g_stats[b*2 + 1] = (float)(1.0 / sqrt(var + 1e-5));
    }
}

__global__ void ln_apply_kernel(const float* __restrict__ x,
                                const float* __restrict__ gam,
                                const float* __restrict__ bet,
                                float* __restrict__ out)
{
    const int n4 = PE / 4;
    int i = blockIdx.x * blockDim.x + threadIdx.x;
    if (i >= Bq * n4) return;
    int b = i / n4, pe = i - b * n4;
    float mean = g_stats[b*2 + 0], inv = g_stats[b*2 + 1];
    float4 xv = ((const float4*)x)[i];
    float4 gv = ((const float4*)gam)[pe];
    float4 bv = ((const float4*)bet)[pe];
    float4 o;
    o.x = (xv.x - mean) * inv * gv.x + bv.x;
    o.y = (xv.y - mean) * inv * gv.y + bv.y;
    o.z = (xv.z - mean) * inv * gv.z + bv.z;
    o.w = (xv.w - mean) * inv * gv.w + bv.w;
    ((float4*)out)[i] = o;
}

// ============================================================== NT GEMM (mma.sync tf32)
// C[m,n] = alpha * sum_k A[m,k] B[n,k]  (+bias, +gelu, +resid)
// 128x128 block, 256 threads (8 warps of 64x32), KT=16. SPLIT => 3xTF32 hi/lo.
template<bool SPLIT>
__global__ __launch_bounds__(256)
void gemm_nt_mma(const float* __restrict__ A, const float* __restrict__ B,
                 float* __restrict__ C, int K, int lda, int ldb, int ldc,
                 float alpha, const float* __restrict__ bias,
                 const float* __restrict__ resid, int do_gelu)
{
    extern __shared__ uint32_t sm[];
    uint32_t* Ah = sm;                 // [128][20]
    uint32_t* Bh = sm + 2560;
    uint32_t* Al = sm + 5120;          // SPLIT only
    uint32_t* Bl = sm + 7680;

    int tid = threadIdx.x, lane = tid & 31, wid = tid >> 5;
    int gid = lane >> 2, tig = lane & 3;
    int wm = (wid >> 2) * 64, wn = (wid & 3) * 32;
    long row0 = (long)blockIdx.y * 128, col0 = (long)blockIdx.x * 128;
    const float* Ab = A + row0 * lda;
    const float* Bb = B + col0 * ldb;

    float acc[4][4][4];
    #pragma unroll
    for (int i = 0; i < 4; i++)
        #pragma unroll
        for (int j = 0; j < 4; j++)
            #pragma unroll
            for (int u = 0; u < 4; u++) acc[i][j][u] = 0.0f;

    for (int kt = 0; kt < K; kt += 16) {
        __syncthreads();
        #pragma unroll
        for (int i = 0; i < 2; i++) {
            int idx = tid + i * 256;
            int row = idx >> 2;
            int c4  = (idx & 3) * 4;
            float4 va = *(const float4*)(Ab + (long)row * lda + kt + c4);
            float4 vb = *(const float4*)(Bb + (long)row * ldb + kt + c4);
            if (SPLIT) {
                uint4 h, l;
                split4(va, h, l);
                *(uint4*)&Ah[row*20 + c4] = h; *(uint4*)&Al[row*20 + c4] = l;
                split4(vb, h, l);
                *(uint4*)&Bh[row*20 + c4] = h; *(uint4*)&Bl[row*20 + c4] = l;
            } else {
                *(uint4*)&Ah[row*20 + c4] = rna4(va);
                *(uint4*)&Bh[row*20 + c4] = rna4(vb);
            }
        }
        __syncthreads();
        #pragma unroll
        for (int kk = 0; kk < 16; kk += 8) {
            uint32_t bh[4][2], bl[4][2];
            #pragma unroll
            for (int tn = 0; tn < 4; tn++) {
                int n = wn + tn*8 + gid, k = kk + tig;
                bh[tn][0] = Bh[n*20 + k]; bh[tn][1] = Bh[n*20 + k + 4];
                if (SPLIT) { bl[tn][0] = Bl[n*20 + k]; bl[tn][1] = Bl[n*20 + k + 4]; }
            }
            #pragma unroll
            for (int tm = 0; tm < 4; tm++) {
                int m = wm + tm*16 + gid, k = kk + tig;
                uint32_t ah[4], al[4];
                ah[0] = Ah[m*20 + k];     ah[1] = Ah[(m+8)*20 + k];
                ah[2] = Ah[m*20 + k + 4]; ah[3] = Ah[(m+8)*20 + k + 4];
                if (SPLIT) {
                    al[0] = Al[m*20 + k];     al[1] = Al[(m+8)*20 + k];
                    al[2] = Al[m*20 + k + 4]; al[3] = Al[(m+8)*20 + k + 4];
                }
                #pragma unroll
                for (int tn = 0; tn < 4; tn++) {
                    mma8(acc[tm][tn], ah, bh[tn]);
                    if (SPLIT) {
                        mma8(acc[tm][tn], al, bh[tn]);
                        mma8(acc[tm][tn], ah, bl[tn]);
                    }
                }
            }
        }
    }

    #pragma unroll
    for (int tm = 0; tm < 4; tm++) {
        #pragma unroll
        for (int tn = 0; tn < 4; tn++) {
            long row = row0 + wm + tm*16 + gid;
            long col = col0 + wn + tn*8 + tig*2;
            #pragma unroll
            for (int half = 0; half < 2; half++) {
                long r = row + half*8;
                float v0 = acc[tm][tn][half*2+0] * alpha;
                float v1 = acc[tm][tn][half*2+1] * alpha;
                if (bias) { v0 += bias[col]; v1 += bias[col+1]; }
                if (do_gelu) { v0 = gelu_f(v0); v1 = gelu_f(v1); }
                if (resid) {
                    float2 rv = *(const float2*)(resid + r*ldc + col);
                    v0 += rv.x; v1 += rv.y;
                }
                float2 o; o.x = v0; o.y = v1;
                *(float2*)(C + r*ldc + col) = o;
            }
        }
    }
}

// ============================================================== S GEMM + exp
// E[k,q] = exp(0.125 * K[k]·Q[q]) stored fp16; per-(k, q-block) partial sums.
// No max subtraction (logits bounded ~|8|; exp via ex2.approx.f16x2, 2/MUFU-op).
__global__ __launch_bounds__(256)
void s_gemm_exp(const float* __restrict__ qkv, __half* __restrict__ Eo,
                float* __restrict__ psum)
{
    int z = blockIdx.z, zo = z >> 3, zi = z & 7;
    const float* A = qkv + (size_t)zo*Pq*E3 + Eq  + (size_t)zi*64;  // K rows
    const float* B = qkv + (size_t)zo*Pq*E3        + (size_t)zi*64; // Q rows
    __half* C = Eo + (size_t)z * Pq * Pq;

    __shared__ uint32_t Ah[128*20], Bh[128*20];
    __shared__ float ps[128][4];

    int tid = threadIdx.x, lane = tid & 31, wid = tid >> 5;
    int gid = lane >> 2, tig = lane & 3;
    int wm = (wid >> 2) * 64, wn = (wid & 3) * 32;
    long row0 = (long)blockIdx.y * 128, col0 = (long)blockIdx.x * 128;
    const float* Ab = A + row0 * E3;
    const float* Bb = B + col0 * E3;

    float acc[4][4][4];
    #pragma unroll
    for (int i = 0; i < 4; i++)
        #pragma unroll
        for (int j = 0; j < 4; j++)
            #pragma unroll
            for (int u = 0; u < 4; u++) acc[i][j][u] = 0.0f;

    #pragma unroll
    for (int kt = 0; kt < 64; kt += 16) {
        __syncthreads();
        #pragma unroll
        for (int i = 0; i < 2; i++) {
            int idx = tid + i * 256;
            int row = idx >> 2, c4 = (idx & 3) * 4;
            *(uint4*)&Ah[row*20 + c4] = rna4(*(const float4*)(Ab + (long)row*E3 + kt + c4));
            *(uint4*)&Bh[row*20 + c4] = rna4(*(const float4*)(Bb + (long)row*E3 + kt + c4));
        }
        __syncthreads();
        #pragma unroll
        for (int kk = 0; kk < 16; kk += 8) {
            uint32_t bh[4][2];
            #pragma unroll
            for (int tn = 0; tn < 4; tn++) {
                int n = wn + tn*8 + gid, k = kk + tig;
                bh[tn][0] = Bh[n*20 + k]; bh[tn][1] = Bh[n*20 + k + 4];
            }
            #pragma unroll
            for (int tm = 0; tm < 4; tm++) {
                int m = wm + tm*16 + gid, k = kk + tig;
                uint32_t ah[4];
                ah[0] = Ah[m*20 + k];     ah[1] = Ah[(m+8)*20 + k];
                ah[2] = Ah[m*20 + k + 4]; ah[3] = Ah[(m+8)*20 + k + 4];
                #pragma unroll
                for (int tn = 0; tn < 4; tn++) mma8(acc[tm][tn], ah, bh[tn]);
            }
        }
    }

    // epilogue: E = 2^(s * 0.125*log2e), fp16 store + per-row partial sums
    const float SC = 0.125f * 1.44269504088896f;
    #pragma unroll
    for (int tm = 0; tm < 4; tm++) {
        #pragma unroll
        for (int half = 0; half < 2; half++) {
            int  rl = wm + tm*16 + gid + half*8;
            long r  = row0 + rl;
            float rsum = 0.0f;
            #pragma unroll
            for (int tn = 0; tn < 4; tn++) {
                float y0 = acc[tm][tn][half*2+0] * SC;
                float y1 = acc[tm][tn][half*2+1] * SC;
                __half2 e2 = h2exp2(__floats2half2_rn(y0, y1));
                long col = col0 + wn + tn*8 + tig*2;
                *(__half2*)(C + r*Pq + col) = e2;
                float2 f = __half22float2(e2);
                rsum += f.x + f.y;
            }
            rsum += __shfl_xor_sync(0xffffffffu, rsum, 1);
            rsum += __shfl_xor_sync(0xffffffffu, rsum, 2);
            if (tig == 0) ps[rl][wid & 3] = rsum;
        }
    }
    __syncthreads();
    if (tid < 128) {
        float tot = ps[tid][0] + ps[tid][1] + ps[tid][2] + ps[tid][3];
        psum[(((size_t)z*Pq + row0 + tid) << 5) + blockIdx.x] = tot;
    }
}

// ============================================================== combine
// rinv[z,k] = 1 / sum over 32 q-block partials
__global__ void combine_kernel(const float* __restrict__ psum,
                               float* __restrict__ rinv)
{
    size_t r = (size_t)blockIdx.x * 256 + threadIdx.x;   // z*Pq + k
    const float4* p = (const float4*)(psum + (r << 5));
    float s = 0.0f;
    #pragma unroll
    for (int i = 0; i < 8; i++) {
        float4 v = p[i];
        s += v.x + v.y + v.z + v.w;
    }
    rinv[r] = 1.0f / s;
}

// ============================================================== attention O
// out1[q, zi*64+d] = x[q,..] + sum_k E[k,q] * (rinv[k]*V[k,d]) — pure tf32 GEMM.
__global__ __launch_bounds__(256)
void attn_o_mma(const __half* __restrict__ Et, const float* __restrict__ qkv,
                float* __restrict__ out1, const float* __restrict__ x,
                const float* __restrict__ rinv)
{
    int z = blockIdx.z, zo = z >> 3, zi = z & 7;
    const __half* Eb = Et   + (size_t)z * Pq * Pq;
    const float*  Vb = qkv  + (size_t)zo * Pq * E3 + 2*Eq + (size_t)zi*64;
    float*        Cb = out1 + (size_t)zo * PE + (size_t)zi*64;
    const float*  Rb = x    + (size_t)zo * PE + (size_t)zi*64;
    const float* riv = rinv + (size_t)z * Pq;

    __shared__ uint32_t stP[32*136];   // [k][q], stride 136 (conflict-free frag reads)
    __shared__ uint32_t stV[32*72];    // [k][d], stride 72

    int tid = threadIdx.x, lane = tid & 31, wid = tid >> 5;
    int gid = lane >> 2, tig = lane & 3;
    int wm = (wid >> 2) * 64, wn = (wid & 3) * 16;
    long q0 = (long)blockIdx.y * 128;

    float acc[4][2][4];
    #pragma unroll
    for (int i = 0; i < 4; i++)
        #pragma unroll
        for (int j = 0; j < 2; j++)
            #pragma unroll
            for (int u = 0; u < 4; u++) acc[i][j][u] = 0.0f;

    for (int k0 = 0; k0 < Pq; k0 += 32) {
        __syncthreads();
        // stage E tile: 32k x 128q halves (half->float is exact & tf32-exact)
        #pragma unroll
        for (int i = 0; i < 2; i++) {
            int idx = tid + i * 256;          // 512 x 8 halves
            int kr = idx >> 4, q8 = (idx & 15) * 8;
            uint4 raw = *(const uint4*)(Eb + (size_t)(k0 + kr) * Pq + q0 + q8);
            const __half2* hp = (const __half2*)&raw;
            uint4 lo, hi;
            float2 f0 = __half22float2(hp[0]), f1 = __half22float2(hp[1]);
            float2 f2 = __half22float2(hp[2]), f3 = __half22float2(hp[3]);
            lo.x = __float_as_uint(f0.x); lo.y = __float_as_uint(f0.y);
            lo.z = __float_as_uint(f1.x); lo.w = __float_as_uint(f1.y);
            hi.x = __float_as_uint(f2.x); hi.y = __float_as_uint(f2.y);
            hi.z = __float_as_uint(f3.x); hi.w = __float_as_uint(f3.y);
            *(uint4*)&stP[kr*136 + q8]     = lo;
            *(uint4*)&stP[kr*136 + q8 + 4] = hi;
        }
        // stage V tile scaled by rinv[k]
        #pragma unroll
        for (int i = 0; i < 2; i++) {
            int idx = tid + i * 256;
            int kr = idx >> 4, d4 = (idx & 15) * 4;
            float iv = riv[k0 + kr];
            float4 v = *(const float4*)(Vb + (size_t)(k0 + kr) * E3 + d4);
            v.x *= iv; v.y *= iv; v.z *= iv; v.w *= iv;
            *(uint4*)&stV[kr*72 + d4] = rna4(v);
        }
        __syncthreads();
        #pragma unroll
        for (int kk = 0; kk < 32; kk += 8) {
            uint32_t b[2][2];
            #pragma unroll
            for (int tn = 0; tn < 2; tn++) {
                int n = wn + tn*8 + gid;
                b[tn][0] = stV[(kk + tig)*72 + n];
                b[tn][1] = stV[(kk + tig + 4)*72 + n];
            }
            #pragma unroll
            for (int tm = 0; tm < 4; tm++) {
                int q = wm + tm*16 + gid;
                uint32_t a[4];
                a[0] = stP[(kk + tig)*136 + q];
                a[1] = stP[(kk + tig)*136 + q + 8];
                a[2] = stP[(kk + tig + 4)*136 + q];
                a[3] = stP[(kk + tig + 4)*136 + q + 8];
                #pragma unroll
                for (int tn = 0; tn < 2; tn++)
                    mma8(acc[tm][tn], a, b[tn]);
            }
        }
    }

    #pragma unroll
    for (int tm = 0; tm < 4; tm++) {
        #pragma unroll
        for (int tn = 0; tn < 2; tn++) {
            long q = q0 + wm + tm*16 + gid;
            int  d = wn + tn*8 + tig*2;
            #pragma unroll
            for (int half = 0; half < 2; half++) {
                long r = q + half*8;
                float2 rv = *(const float2*)(Rb + r*Eq + d);
                float2 o;
                o.x = acc[tm][tn][half*2+0] + rv.x;
                o.y = acc[tm][tn][half*2+1] + rv.y;
                *(float2*)(Cb + r*Eq + d) = o;
            }
        }
    }
}

// ============================================================== launcher
extern "C" void kernel_launch(void* const* d_in, const int* in_sizes, int n_in,
                              void* d_out, int out_size)
{
    const float* x  = (const float*)d_in[0];
    const float* g1 = (const float*)d_in[1];
    const float* b1 = (const float*)d_in[2];
    const float* W1 = (const float*)d_in[3];
    const float* g2 = (const float*)d_in[4];
    const float* b2 = (const float*)d_in[5];
    const float* Wa = (const float*)d_in[6];
    const float* ba = (const float*)d_in[7];
    const float* Wb = (const float*)d_in[8];
    const float* bb = (const float*)d_in[9];
    float* out = (float*)d_out;

    float *h, *qkv, *out1, *tbuf, *riv, *psm;
    __half* E;
    cudaGetSymbolAddress((void**)&h,    g_h);
    cudaGetSymbolAddress((void**)&qkv,  g_qkv);
    cudaGetSymbolAddress((void**)&E,    g_E);
    cudaGetSymbolAddress((void**)&out1, g_out1);
    cudaGetSymbolAddress((void**)&tbuf, g_t);
    cudaGetSymbolAddress((void**)&riv,  g_rinv);
    cudaGetSymbolAddress((void**)&psm,  g_psum);

    const int SM_SPLIT = 10240 * 4;

    // LN1
    ln_reduce_kernel<<<dim3(NB_RED, Bq), 256>>>(x);
    ln_final_kernel<<<Bq, 256>>>();
    ln_apply_kernel<<<(Bq*PE/4 + 255)/256, 256>>>(x, g1, b1, h);

    // QKV = h @ W1^T   [8192,1536], K=512
    gemm_nt_mma<true><<<dim3(E3/128, (Bq*Pq)/128, 1), 256, SM_SPLIT>>>(
        h, W1, qkv, Eq, Eq, Eq, E3, 1.0f, (const float*)0, (const float*)0, 0);

    // E[k,q] = exp(0.125 K·Q) fp16 + partial row sums (exp fused, no rowstat pass)
    s_gemm_exp<<<dim3(Pq/128, Pq/128, Bq*Hq), 256>>>(qkv, E, psm);

    // rinv[k] = 1/sum_q E[k,q]
    combine_kernel<<<(Bq*Hq*Pq)/256, 256>>>(psm, riv);

    // out1 = x + E^T (rinv*V)   — pure GEMM, no exp
    attn_o_mma<<<dim3(1, Pq/128, Bq*Hq), 256>>>(E, qkv, out1, x, riv);

    // LN2
    ln_reduce_kernel<<<dim3(NB_RED, Bq), 256>>>(out1);
    ln_final_kernel<<<Bq, 256>>>();
    ln_apply_kernel<<<(Bq*PE/4 + 255)/256, 256>>>(out1, g2, b2, h);

    // t = gelu(h @ Wa^T + ba)   [8192,1536], K=512
    gemm_nt_mma<true><<<dim3(E3/128, (Bq*Pq)/128, 1), 256, SM_SPLIT>>>(
        h, Wa, tbuf, Eq, Eq, Eq, E3, 1.0f, ba, (const float*)0, 1);

    // out = gelu(t @ Wb^T + bb) + out1   [8192,512], K=1536
    gemm_nt_mma<true><<<dim3(Eq/128, (Bq*Pq)/128, 1), 256, SM_SPLIT>>>(
        tbuf, Wb, out, E3, E3, E3, Eq, 1.0f, bb, out1, 1);
}

// round 9
// speedup vs baseline: 2.7688x; 1.3877x over previous
#include <cuda_runtime.h>
#include <cuda_fp16.h>
#include <math.h>
#include <stdint.h>

#define Bq 2
#define Pq 4096
#define Eq 512
#define Hq 8
#define E3 1536
#define PE (Pq*Eq)
#define NB_RED 256

// ------------------------------------------------------------- scratch
__device__ float  g_h   [(size_t)Bq*Pq*Eq];
__device__ float  g_qkv [(size_t)Bq*Pq*E3];
__device__ __half g_E   [(size_t)Bq*Hq*Pq*Pq];   // exp(S)[q][k] fp16 (0.5 GB)
__device__ float  g_out1[(size_t)Bq*Pq*Eq];
__device__ float  g_t   [(size_t)Bq*Pq*E3];
__device__ float  g_rinv[(size_t)Bq*Hq*Pq];
__device__ float  g_psum[(size_t)Bq*Hq*Pq*32];   // per-(k, q-block) partials
__device__ double g_part[Bq*NB_RED*2];
__device__ float  g_stats[Bq*2];

// ------------------------------------------------------------- helpers
__device__ __forceinline__ uint32_t h2u(__half2 h){ return *reinterpret_cast<uint32_t*>(&h); }
__device__ __forceinline__ uint2 h4(float4 v){
    __half2 h01 = __floats2half2_rn(v.x, v.y);
    __half2 h23 = __floats2half2_rn(v.z, v.w);
    return make_uint2(h2u(h01), h2u(h23));
}
__device__ __forceinline__ void splith4(float4 v, uint2& hi, uint2& lo){
    __half2 h01 = __floats2half2_rn(v.x, v.y);
    __half2 h23 = __floats2half2_rn(v.z, v.w);
    float2 f01 = __half22float2(h01);
    float2 f23 = __half22float2(h23);
    __half2 l01 = __floats2half2_rn(v.x - f01.x, v.y - f01.y);
    __half2 l23 = __floats2half2_rn(v.z - f23.x, v.w - f23.y);
    hi = make_uint2(h2u(h01), h2u(h23));
    lo = make_uint2(h2u(l01), h2u(l23));
}
__device__ __forceinline__ void mma16(float d[4], const uint32_t a[4], const uint32_t b[2]){
    asm volatile(
        "mma.sync.aligned.m16n8k16.row.col.f32.f16.f16.f32 "
        "{%0,%1,%2,%3}, {%4,%5,%6,%7}, {%8,%9}, {%0,%1,%2,%3};"
        : "+f"(d[0]), "+f"(d[1]), "+f"(d[2]), "+f"(d[3])
        : "r"(a[0]), "r"(a[1]), "r"(a[2]), "r"(a[3]), "r"(b[0]), "r"(b[1]));
}
__device__ __forceinline__ float gelu_f(float v){
    return 0.5f * v * (1.0f + erff(v * 0.70710678118654752440f));
}

// ============================================================== LayerNorm
__global__ void ln_reduce_kernel(const float* __restrict__ x)
{
    int b = blockIdx.y;
    const float4* xb = (const float4*)(x + (size_t)b * PE);
    const int n4 = PE / 4;
    double s = 0.0, s2 = 0.0;
    for (int i = blockIdx.x * blockDim.x + threadIdx.x; i < n4;
         i += gridDim.x * blockDim.x) {
        float4 v = xb[i];
        s  += (double)v.x + (double)v.y + (double)v.z + (double)v.w;
        s2 += (double)v.x*v.x + (double)v.y*v.y + (double)v.z*v.z + (double)v.w*v.w;
    }
    __shared__ double ss[256], ss2[256];
    int t = threadIdx.x;
    ss[t] = s; ss2[t] = s2;
    __syncthreads();
    for (int o = 128; o > 0; o >>= 1) {
        if (t < o) { ss[t] += ss[t+o]; ss2[t] += ss2[t+o]; }
        __syncthreads();
    }
    if (t == 0) {
        g_part[(b*NB_RED + blockIdx.x)*2 + 0] = ss[0];
        g_part[(b*NB_RED + blockIdx.x)*2 + 1] = ss2[0];
    }
}

__global__ void ln_final_kernel()
{
    int b = blockIdx.x, t = threadIdx.x;
    __shared__ double ss[256], ss2[256];
    ss[t]  = g_part[(b*NB_RED + t)*2 + 0];
    ss2[t] = g_part[(b*NB_RED + t)*2 + 1];
    __syncthreads();
    for (int o = 128; o > 0; o >>= 1) {
        if (t < o) { ss[t] += ss[t+o]; ss2[t] += ss2[t+o]; }
        __syncthreads();
    }
    if (t == 0) {
        double mean = ss[0] / (double)PE;
        double var  = ss2[0] / (double)PE - mean * mean;
        g_stats[b*2 + 0] = (float)mean;
        g_stats[b*2 + 1] = (float)(1.0 / sqrt(var + 1e-5));
    }
}

__global__ void ln_apply_kernel(const float* __restrict__ x,
                                const float* __restrict__ gam,
                                const float* __restrict__ bet,
                                float* __restrict__ out)
{
    const int n4 = PE / 4;
    int i = blockIdx.x * blockDim.x + threadIdx.x;
    if (i >= Bq * n4) return;
    int b = i / n4, pe = i - b * n4;
    float mean = g_stats[b*2 + 0], inv = g_stats[b*2 + 1];
    float4 xv = ((const float4*)x)[i];
    float4 gv = ((const float4*)gam)[pe];
    float4 bv = ((const float4*)bet)[pe];
    float4 o;
    o.x = (xv.x - mean) * inv * gv.x + bv.x;
    o.y = (xv.y - mean) * inv * gv.y + bv.y;
    o.z = (xv.z - mean) * inv * gv.z + bv.z;
    o.w = (xv.w - mean) * inv * gv.w + bv.w;
    ((float4*)out)[i] = o;
}

// ============================================================== NT GEMM fp16-split
// C[m,n] = sum_k A[m,k] B[n,k]  (+bias, +gelu, +resid). 128x128 block,
// 256 threads (8 warps, 64x32 each), KT=32 halves, m16n8k16 fp16 mma.
// 2-term fp16 split (hh + lh + hl): residual ~2^-22.
__global__ __launch_bounds__(256)
void gemm_nt_h(const float* __restrict__ A, const float* __restrict__ B,
               float* __restrict__ C, int K, int lda, int ldb, int ldc,
               const float* __restrict__ bias,
               const float* __restrict__ resid, int do_gelu)
{
    extern __shared__ uint32_t sm[];
    uint32_t* Ah = sm;            // [128][20] (16 pairs used + pad)
    uint32_t* Bh = sm + 2560;
    uint32_t* Al = sm + 5120;
    uint32_t* Bl = sm + 7680;

    int tid = threadIdx.x, lane = tid & 31, wid = tid >> 5;
    int gid = lane >> 2, tig = lane & 3;
    int wm = (wid >> 2) * 64, wn = (wid & 3) * 32;
    long row0 = (long)blockIdx.y * 128, col0 = (long)blockIdx.x * 128;
    const float* Ab = A + row0 * lda;
    const float* Bb = B + col0 * ldb;

    float acc[4][4][4];
    #pragma unroll
    for (int i = 0; i < 4; i++)
        #pragma unroll
        for (int j = 0; j < 4; j++)
            #pragma unroll
            for (int u = 0; u < 4; u++) acc[i][j][u] = 0.0f;

    for (int kt = 0; kt < K; kt += 32) {
        __syncthreads();
        #pragma unroll
        for (int i = 0; i < 4; i++) {
            int idx = tid + i * 256;          // 1024 float4 per matrix
            int row = idx >> 3, c8 = idx & 7; // float4 slot in 32-float row
            float4 va = *(const float4*)(Ab + (long)row * lda + kt + c8*4);
            float4 vb = *(const float4*)(Bb + (long)row * ldb + kt + c8*4);
            uint2 h, l;
            splith4(va, h, l);
            *(uint2*)&Ah[row*20 + c8*2] = h; *(uint2*)&Al[row*20 + c8*2] = l;
            splith4(vb, h, l);
            *(uint2*)&Bh[row*20 + c8*2] = h; *(uint2*)&Bl[row*20 + c8*2] = l;
        }
        __syncthreads();
        #pragma unroll
        for (int po = 0; po < 16; po += 8) {   // two k16 steps
            uint32_t bh[4][2], bl[4][2];
            #pragma unroll
            for (int tn = 0; tn < 4; tn++) {
                int n = wn + tn*8 + gid;
                bh[tn][0] = Bh[n*20 + po + tig]; bh[tn][1] = Bh[n*20 + po + tig + 4];
                bl[tn][0] = Bl[n*20 + po + tig]; bl[tn][1] = Bl[n*20 + po + tig + 4];
            }
            #pragma unroll
            for (int tm = 0; tm < 4; tm++) {
                int m = wm + tm*16 + gid;
                uint32_t ah[4], al[4];
                ah[0] = Ah[m*20 + po + tig];     ah[1] = Ah[(m+8)*20 + po + tig];
                ah[2] = Ah[m*20 + po + tig + 4]; ah[3] = Ah[(m+8)*20 + po + tig + 4];
                al[0] = Al[m*20 + po + tig];     al[1] = Al[(m+8)*20 + po + tig];
                al[2] = Al[m*20 + po + tig + 4]; al[3] = Al[(m+8)*20 + po + tig + 4];
                #pragma unroll
                for (int tn = 0; tn < 4; tn++) {
                    mma16(acc[tm][tn], ah, bh[tn]);
                    mma16(acc[tm][tn], al, bh[tn]);
                    mma16(acc[tm][tn], ah, bl[tn]);
                }
            }
        }
    }

    #pragma unroll
    for (int tm = 0; tm < 4; tm++) {
        #pragma unroll
        for (int tn = 0; tn < 4; tn++) {
            long row = row0 + wm + tm*16 + gid;
            long col = col0 + wn + tn*8 + tig*2;
            #pragma unroll
            for (int half = 0; half < 2; half++) {
                long r = row + half*8;
                float v0 = acc[tm][tn][half*2+0];
                float v1 = acc[tm][tn][half*2+1];
                if (bias) { v0 += bias[col]; v1 += bias[col+1]; }
                if (do_gelu) { v0 = gelu_f(v0); v1 = gelu_f(v1); }
                if (resid) {
                    float2 rv = *(const float2*)(resid + r*ldc + col);
                    v0 += rv.x; v1 += rv.y;
                }
                float2 o; o.x = v0; o.y = v1;
                *(float2*)(C + r*ldc + col) = o;
            }
        }
    }
}

// ============================================================== S GEMM + exp (fp16)
// E[q,k] = exp(0.125 * Q[q]·K[k]) fp16 row-major [q][k]; column partial sums
// over q (per 128-q block) -> psum. fp16 operands (same 10-bit mantissa as tf32).
__global__ __launch_bounds__(256)
void s_gemm_exp_h(const float* __restrict__ qkv, __half* __restrict__ Eo,
                  float* __restrict__ psum)
{
    int z = blockIdx.z, zo = z >> 3, zi = z & 7;
    const float* A = qkv + (size_t)zo*Pq*E3       + (size_t)zi*64;  // Q rows (m=q)
    const float* B = qkv + (size_t)zo*Pq*E3 + Eq  + (size_t)zi*64;  // K rows (n=k)
    __half* C = Eo + (size_t)z * Pq * Pq;

    __shared__ uint32_t Ah[128*20], Bh[128*20];
    __shared__ float ps[128][2];

    int tid = threadIdx.x, lane = tid & 31, wid = tid >> 5;
    int gid = lane >> 2, tig = lane & 3;
    int wm = (wid >> 2) * 64, wn = (wid & 3) * 32;
    long row0 = (long)blockIdx.y * 128;   // q
    long col0 = (long)blockIdx.x * 128;   // k
    const float* Ab = A + row0 * E3;
    const float* Bb = B + col0 * E3;

    float acc[4][4][4];
    #pragma unroll
    for (int i = 0; i < 4; i++)
        #pragma unroll
        for (int j = 0; j < 4; j++)
            #pragma unroll
            for (int u = 0; u < 4; u++) acc[i][j][u] = 0.0f;

    #pragma unroll
    for (int kt = 0; kt < 64; kt += 32) {
        __syncthreads();
        #pragma unroll
        for (int i = 0; i < 4; i++) {
            int idx = tid + i * 256;
            int row = idx >> 3, c8 = idx & 7;
            *(uint2*)&Ah[row*20 + c8*2] = h4(*(const float4*)(Ab + (long)row*E3 + kt + c8*4));
            *(uint2*)&Bh[row*20 + c8*2] = h4(*(const float4*)(Bb + (long)row*E3 + kt + c8*4));
        }
        __syncthreads();
        #pragma unroll
        for (int po = 0; po < 16; po += 8) {
            uint32_t bh[4][2];
            #pragma unroll
            for (int tn = 0; tn < 4; tn++) {
                int n = wn + tn*8 + gid;
                bh[tn][0] = Bh[n*20 + po + tig]; bh[tn][1] = Bh[n*20 + po + tig + 4];
            }
            #pragma unroll
            for (int tm = 0; tm < 4; tm++) {
                int m = wm + tm*16 + gid;
                uint32_t ah[4];
                ah[0] = Ah[m*20 + po + tig];     ah[1] = Ah[(m+8)*20 + po + tig];
                ah[2] = Ah[m*20 + po + tig + 4]; ah[3] = Ah[(m+8)*20 + po + tig + 4];
                #pragma unroll
                for (int tn = 0; tn < 4; tn++) mma16(acc[tm][tn], ah, bh[tn]);
            }
        }
    }

    // epilogue: E = 2^(s*0.125*log2e) fp16 store + column sums (over q)
    const float SC = 0.125f * 1.44269504088896f;
    float cs[4][2];
    #pragma unroll
    for (int tn = 0; tn < 4; tn++) { cs[tn][0] = 0.0f; cs[tn][1] = 0.0f; }
    #pragma unroll
    for (int tm = 0; tm < 4; tm++) {
        #pragma unroll
        for (int half = 0; half < 2; half++) {
            long r = row0 + wm + tm*16 + gid + half*8;   // q
            #pragma unroll
            for (int tn = 0; tn < 4; tn++) {
                float y0 = acc[tm][tn][half*2+0] * SC;
                float y1 = acc[tm][tn][half*2+1] * SC;
                __half2 e2 = h2exp2(__floats2half2_rn(y0, y1));
                long col = col0 + wn + tn*8 + tig*2;     // k
                *(__half2*)(C + r*Pq + col) = e2;
                float2 f = __half22float2(e2);
                cs[tn][0] += f.x; cs[tn][1] += f.y;
            }
        }
    }
    #pragma unroll
    for (int tn = 0; tn < 4; tn++) {
        #pragma unroll
        for (int u = 0; u < 2; u++) {
            float v = cs[tn][u];
            v += __shfl_xor_sync(0xffffffffu, v, 4);
            v += __shfl_xor_sync(0xffffffffu, v, 8);
            v += __shfl_xor_sync(0xffffffffu, v, 16);
            if (gid == 0) ps[wn + tn*8 + tig*2 + u][wid >> 2] = v;
        }
    }
    __syncthreads();
    if (tid < 128) {
        float tot = ps[tid][0] + ps[tid][1];
        psum[((size_t)z*Pq + col0 + tid) * 32 + blockIdx.y] = tot;
    }
}

// ============================================================== combine
__global__ void combine_kernel(const float* __restrict__ psum,
                               float* __restrict__ rinv)
{
    size_t r = (size_t)blockIdx.x * 256 + threadIdx.x;   // z*Pq + k
    const float4* p = (const float4*)(psum + (r << 5));
    float s = 0.0f;
    #pragma unroll
    for (int i = 0; i < 8; i++) {
        float4 v = p[i];
        s += v.x + v.y + v.z + v.w;
    }
    rinv[r] = 1.0f / s;
}

// ============================================================== attention O
// out1[q, zi*64+d] = x + sum_k E[q,k] * (rinv[k]*V[k,d]) — fp16 mma,
// E staged raw (no cvt/transpose), V register-transposed into [d][kpair].
__global__ __launch_bounds__(256)
void attn_o_h(const __half* __restrict__ Et, const float* __restrict__ qkv,
              float* __restrict__ out1, const float* __restrict__ x,
              const float* __restrict__ rinv)
{
    int z = blockIdx.z, zo = z >> 3, zi = z & 7;
    const __half* Eb = Et   + (size_t)z * Pq * Pq;
    const float*  Vb = qkv  + (size_t)zo * Pq * E3 + 2*Eq + (size_t)zi*64;
    float*        Cb = out1 + (size_t)zo * PE + (size_t)zi*64;
    const float*  Rb = x    + (size_t)zo * PE + (size_t)zi*64;
    const float* riv = rinv + (size_t)z * Pq;

    __shared__ uint32_t stP[128*20];   // [q][kpair], 16 pairs + pad
    __shared__ uint32_t stVT[64*20];   // [d][kpair]

    int tid = threadIdx.x, lane = tid & 31, wid = tid >> 5;
    int gid = lane >> 2, tig = lane & 3;
    int wm = (wid >> 2) * 64, wn = (wid & 3) * 16;
    long q0 = (long)blockIdx.y * 128;

    float acc[4][2][4];
    #pragma unroll
    for (int i = 0; i < 4; i++)
        #pragma unroll
        for (int j = 0; j < 2; j++)
            #pragma unroll
            for (int u = 0; u < 4; u++) acc[i][j][u] = 0.0f;

    for (int k0 = 0; k0 < Pq; k0 += 32) {
        __syncthreads();
        // stage E: raw fp16 bits, [q][kpair]
        #pragma unroll
        for (int i = 0; i < 2; i++) {
            int idx = tid + i * 256;        // 512 uint4
            int q = idx >> 2, kq = idx & 3;
            uint4 raw = *(const uint4*)(Eb + (size_t)(q0 + q) * Pq + k0 + kq*8);
            *(uint4*)&stP[q*20 + kq*4] = raw;
        }
        // stage V transposed: thread (db, kp) loads rows 2kp,2kp+1 x 4 floats,
        // packs k-pairs.  db fastest -> coalesced loads AND conflict-free stores.
        {
            int db = tid & 15, kp = tid >> 4;
            float iv0 = riv[k0 + 2*kp], iv1 = riv[k0 + 2*kp + 1];
            const float* r0p = Vb + (size_t)(k0 + 2*kp) * E3 + db*4;
            float4 v0 = *(const float4*)r0p;
            float4 v1 = *(const float4*)(r0p + E3);
            v0.x *= iv0; v0.y *= iv0; v0.z *= iv0; v0.w *= iv0;
            v1.x *= iv1; v1.y *= iv1; v1.z *= iv1; v1.w *= iv1;
            stVT[(db*4+0)*20 + kp] = h2u(__floats2half2_rn(v0.x, v1.x));
            stVT[(db*4+1)*20 + kp] = h2u(__floats2half2_rn(v0.y, v1.y));
            stVT[(db*4+2)*20 + kp] = h2u(__floats2half2_rn(v0.z, v1.z));
            stVT[(db*4+3)*20 + kp] = h2u(__floats2half2_rn(v0.w, v1.w));
        }
        __syncthreads();
        #pragma unroll
        for (int po = 0; po < 16; po += 8) {
            uint32_t b[2][2];
            #pragma unroll
            for (int tn = 0; tn < 2; tn++) {
                int n = wn + tn*8 + gid;
                b[tn][0] = stVT[n*20 + po + tig];
                b[tn][1] = stVT[n*20 + po + tig + 4];
            }
            #pragma unroll
            for (int tm = 0; tm < 4; tm++) {
                int q = wm + tm*16 + gid;
                uint32_t a[4];
                a[0] = stP[q*20 + po + tig];     a[1] = stP[(q+8)*20 + po + tig];
                a[2] = stP[q*20 + po + tig + 4]; a[3] = stP[(q+8)*20 + po + tig + 4];
                #pragma unroll
                for (int tn = 0; tn < 2; tn++)
                    mma16(acc[tm][tn], a, b[tn]);
            }
        }
    }

    #pragma unroll
    for (int tm = 0; tm < 4; tm++) {
        #pragma unroll
        for (int tn = 0; tn < 2; tn++) {
            long q = q0 + wm + tm*16 + gid;
            int  d = wn + tn*8 + tig*2;
            #pragma unroll
            for (int half = 0; half < 2; half++) {
                long r = q + half*8;
                float2 rv = *(const float2*)(Rb + r*Eq + d);
                float2 o;
                o.x = acc[tm][tn][half*2+0] + rv.x;
                o.y = acc[tm][tn][half*2+1] + rv.y;
                *(float2*)(Cb + r*Eq + d) = o;
            }
        }
    }
}

// ============================================================== launcher
extern "C" void kernel_launch(void* const* d_in, const int* in_sizes, int n_in,
                              void* d_out, int out_size)
{
    const float* x  = (const float*)d_in[0];
    const float* g1 = (const float*)d_in[1];
    const float* b1 = (const float*)d_in[2];
    const float* W1 = (const float*)d_in[3];
    const float* g2 = (const float*)d_in[4];
    const float* b2 = (const float*)d_in[5];
    const float* Wa = (const float*)d_in[6];
    const float* ba = (const float*)d_in[7];
    const float* Wb = (const float*)d_in[8];
    const float* bb = (const float*)d_in[9];
    float* out = (float*)d_out;

    float *h, *qkv, *out1, *tbuf, *riv, *psm;
    __half* E;
    cudaGetSymbolAddress((void**)&h,    g_h);
    cudaGetSymbolAddress((void**)&qkv,  g_qkv);
    cudaGetSymbolAddress((void**)&E,    g_E);
    cudaGetSymbolAddress((void**)&out1, g_out1);
    cudaGetSymbolAddress((void**)&tbuf, g_t);
    cudaGetSymbolAddress((void**)&riv,  g_rinv);
    cudaGetSymbolAddress((void**)&psm,  g_psum);

    const int SM_H = 10240 * 4;   // 4 arrays of 128x20 uint32

    // LN1
    ln_reduce_kernel<<<dim3(NB_RED, Bq), 256>>>(x);
    ln_final_kernel<<<Bq, 256>>>();
    ln_apply_kernel<<<(Bq*PE/4 + 255)/256, 256>>>(x, g1, b1, h);

    // QKV = h @ W1^T   [8192,1536], K=512
    gemm_nt_h<<<dim3(E3/128, (Bq*Pq)/128, 1), 256, SM_H>>>(
        h, W1, qkv, Eq, Eq, Eq, E3, (const float*)0, (const float*)0, 0);

    // E[q,k] = exp(0.125 Q·K) fp16 + column partial sums
    s_gemm_exp_h<<<dim3(Pq/128, Pq/128, Bq*Hq), 256>>>(qkv, E, psm);

    // rinv[k] = 1/sum_q E[q,k]
    combine_kernel<<<(Bq*Hq*Pq)/256, 256>>>(psm, riv);

    // out1 = x + E (rinv*V)
    attn_o_h<<<dim3(1, Pq/128, Bq*Hq), 256>>>(E, qkv, out1, x, riv);

    // LN2
    ln_reduce_kernel<<<dim3(NB_RED, Bq), 256>>>(out1);
    ln_final_kernel<<<Bq, 256>>>();
    ln_apply_kernel<<<(Bq*PE/4 + 255)/256, 256>>>(out1, g2, b2, h);

    // t = gelu(h @ Wa^T + ba)   [8192,1536], K=512
    gemm_nt_h<<<dim3(E3/128, (Bq*Pq)/128, 1), 256, SM_H>>>(
        h, Wa, tbuf, Eq, Eq, Eq, E3, ba, (const float*)0, 1);

    // out = gelu(t @ Wb^T + bb) + out1   [8192,512], K=1536
    gemm_nt_h<<<dim3(Eq/128, (Bq*Pq)/128, 1), 256, SM_H>>>(
        tbuf, Wb, out, E3, E3, E3, Eq, bb, out1, 1);
}

// round 10
// speedup vs baseline: 3.0579x; 1.1044x over previous
#include <cuda_runtime.h>
#include <cuda_fp16.h>
#include <math.h>
#include <stdint.h>

#define Bq 2
#define Pq 4096
#define Eq 512
#define Hq 8
#define E3 1536
#define PE (Pq*Eq)
#define NB_RED 256

// ------------------------------------------------------------- scratch
__device__ __align__(16) __half g_hh [(size_t)Bq*Pq*Eq];    // LN out hi
__device__ __align__(16) __half g_hl [(size_t)Bq*Pq*Eq];    // LN out lo
__device__ __align__(16) __half g_W1h[(size_t)E3*Eq];
__device__ __align__(16) __half g_W1l[(size_t)E3*Eq];
__device__ __align__(16) __half g_Wah[(size_t)E3*Eq];
__device__ __align__(16) __half g_Wal[(size_t)E3*Eq];
__device__ __align__(16) __half g_Wbh[(size_t)Eq*E3];
__device__ __align__(16) __half g_Wbl[(size_t)Eq*E3];
__device__ __align__(16) float  g_qkv [(size_t)Bq*Pq*E3];   // float (V path)
__device__ __align__(16) __half g_qkvh[(size_t)Bq*Pq*E3];   // fp16 (Q,K path)
__device__ __align__(16) __half g_th [(size_t)Bq*Pq*E3];    // MLP hidden hi
__device__ __align__(16) __half g_tl [(size_t)Bq*Pq*E3];    // MLP hidden lo
__device__ __align__(16) __half g_E  [(size_t)Bq*Hq*Pq*Pq]; // exp(S)[q][k]
__device__ float  g_out1[(size_t)Bq*Pq*Eq];
__device__ float  g_rinv[(size_t)Bq*Hq*Pq];
__device__ float  g_psum[(size_t)Bq*Hq*Pq*32];
__device__ double g_part[Bq*NB_RED*2];
__device__ float  g_stats[Bq*2];

// ------------------------------------------------------------- helpers
__device__ __forceinline__ uint32_t smem_u32(const void* p){
    uint32_t a;
    asm("{ .reg .u64 t; cvta.to.shared.u64 t, %1; cvt.u32.u64 %0, t; }"
        : "=r"(a) : "l"(p));
    return a;
}
__device__ __forceinline__ uint32_t h2u(__half2 h){ return *reinterpret_cast<uint32_t*>(&h); }
__device__ __forceinline__ void splith4(float4 v, uint2& hi, uint2& lo){
    __half2 h01 = __floats2half2_rn(v.x, v.y);
    __half2 h23 = __floats2half2_rn(v.z, v.w);
    float2 f01 = __half22float2(h01);
    float2 f23 = __half22float2(h23);
    __half2 l01 = __floats2half2_rn(v.x - f01.x, v.y - f01.y);
    __half2 l23 = __floats2half2_rn(v.z - f23.x, v.w - f23.y);
    hi = make_uint2(h2u(h01), h2u(h23));
    lo = make_uint2(h2u(l01), h2u(l23));
}
__device__ __forceinline__ void mma16(float d[4], const uint32_t a[4], const uint32_t b[2]){
    asm volatile(
        "mma.sync.aligned.m16n8k16.row.col.f32.f16.f16.f32 "
        "{%0,%1,%2,%3}, {%4,%5,%6,%7}, {%8,%9}, {%0,%1,%2,%3};"
        : "+f"(d[0]), "+f"(d[1]), "+f"(d[2]), "+f"(d[3])
        : "r"(a[0]), "r"(a[1]), "r"(a[2]), "r"(a[3]), "r"(b[0]), "r"(b[1]));
}
__device__ __forceinline__ float gelu_f(float v){
    return 0.5f * v * (1.0f + erff(v * 0.70710678118654752440f));
}
#define CPA(dst, src) \
    asm volatile("cp.async.cg.shared.global [%0], [%1], 16;" :: "r"(dst), "l"(src))
#define CPCOMMIT() asm volatile("cp.async.commit_group;" ::: "memory")
#define CPWAIT0()  asm volatile("cp.async.wait_group 0;"  ::: "memory")

// ============================================================== LayerNorm
__global__ void ln_reduce_kernel(const float* __restrict__ x)
{
    int b = blockIdx.y;
    const float4* xb = (const float4*)(x + (size_t)b * PE);
    const int n4 = PE / 4;
    double s = 0.0, s2 = 0.0;
    for (int i = blockIdx.x * blockDim.x + threadIdx.x; i < n4;
         i += gridDim.x * blockDim.x) {
        float4 v = xb[i];
        s  += (double)v.x + (double)v.y + (double)v.z + (double)v.w;
        s2 += (double)v.x*v.x + (double)v.y*v.y + (double)v.z*v.z + (double)v.w*v.w;
    }
    __shared__ double ss[256], ss2[256];
    int t = threadIdx.x;
    ss[t] = s; ss2[t] = s2;
    __syncthreads();
    for (int o = 128; o > 0; o >>= 1) {
        if (t < o) { ss[t] += ss[t+o]; ss2[t] += ss2[t+o]; }
        __syncthreads();
    }
    if (t == 0) {
        g_part[(b*NB_RED + blockIdx.x)*2 + 0] = ss[0];
        g_part[(b*NB_RED + blockIdx.x)*2 + 1] = ss2[0];
    }
}

__global__ void ln_final_kernel()
{
    int b = blockIdx.x, t = threadIdx.x;
    __shared__ double ss[256], ss2[256];
    ss[t]  = g_part[(b*NB_RED + t)*2 + 0];
    ss2[t] = g_part[(b*NB_RED + t)*2 + 1];
    __syncthreads();
    for (int o = 128; o > 0; o >>= 1) {
        if (t < o) { ss[t] += ss[t+o]; ss2[t] += ss2[t+o]; }
        __syncthreads();
    }
    if (t == 0) {
        double mean = ss[0] / (double)PE;
        double var  = ss2[0] / (double)PE - mean * mean;
        g_stats[b*2 + 0] = (float)mean;
        g_stats[b*2 + 1] = (float)(1.0 / sqrt(var + 1e-5));
    }
}

// LN apply -> hi/lo fp16 split directly
__global__ void ln_apply_split(const float* __restrict__ x,
                               const float* __restrict__ gam,
                               const float* __restrict__ bet,
                               __half* __restrict__ hh, __half* __restrict__ hl)
{
    const int n4 = PE / 4;
    int i = blockIdx.x * blockDim.x + threadIdx.x;
    if (i >= Bq * n4) return;
    int b = i / n4, pe = i - b * n4;
    float mean = g_stats[b*2 + 0], inv = g_stats[b*2 + 1];
    float4 xv = ((const float4*)x)[i];
    float4 gv = ((const float4*)gam)[pe];
    float4 bv = ((const float4*)bet)[pe];
    float4 o;
    o.x = (xv.x - mean) * inv * gv.x + bv.x;
    o.y = (xv.y - mean) * inv * gv.y + bv.y;
    o.z = (xv.z - mean) * inv * gv.z + bv.z;
    o.w = (xv.w - mean) * inv * gv.w + bv.w;
    uint2 h, l;
    splith4(o, h, l);
    ((uint2*)hh)[i] = h;
    ((uint2*)hl)[i] = l;
}

// float -> hi/lo fp16 split (weights)
__global__ void cvt_split(const float* __restrict__ src,
                          __half* __restrict__ hi, __half* __restrict__ lo, int n4)
{
    int i = blockIdx.x * blockDim.x + threadIdx.x;
    if (i >= n4) return;
    uint2 h, l;
    splith4(((const float4*)src)[i], h, l);
    ((uint2*)hi)[i] = h;
    ((uint2*)lo)[i] = l;
}

// ============================================================== fp16-split GEMM
// C[m,n] = sum_k A[m,k] B[n,k] with A,B pre-split hi/lo fp16.
// 128x128 block, 256 threads, KT=32, cp.async 2-stage pipeline, 3x mma split.
// MODE 0: write float C + fp16 copy Ch (QKV)
// MODE 1: bias+gelu -> hi/lo halves Th/Tl (MLP1)
// MODE 2: bias+gelu+resid -> float C (MLP2)
template<int MODE>
__global__ __launch_bounds__(256)
void gemm_fp16(const __half* __restrict__ Ahh, const __half* __restrict__ Alo,
               const __half* __restrict__ Bhh, const __half* __restrict__ Blo,
               int K, int lda, int ldb, int ldc,
               float* __restrict__ Cf, __half* __restrict__ Ch,
               __half* __restrict__ Th, __half* __restrict__ Tl,
               const float* __restrict__ bias, const float* __restrict__ resid)
{
    extern __shared__ uint32_t sm[];
    uint32_t sb = smem_u32(sm);
    int tid = threadIdx.x, lane = tid & 31, wid = tid >> 5;
    int gid = lane >> 2, tig = lane & 3;
    int wm = (wid >> 2) * 64, wn = (wid & 3) * 32;
    long row0 = (long)blockIdx.y * 128, col0 = (long)blockIdx.x * 128;
    const __half* A0 = Ahh + row0 * lda;
    const __half* A1 = Alo + row0 * lda;
    const __half* B0 = Bhh + col0 * ldb;
    const __half* B1 = Blo + col0 * ldb;

    float acc[4][4][4];
    #pragma unroll
    for (int i = 0; i < 4; i++)
        #pragma unroll
        for (int j = 0; j < 4; j++)
            #pragma unroll
            for (int u = 0; u < 4; u++) acc[i][j][u] = 0.0f;

    // stage: 4 matrices x 128 rows x 16 data u32 (+4 pad) = 10240 u32/stage
    const int T = K >> 5;
    {   // prologue stage 0
        #pragma unroll
        for (int j = 0; j < 2; j++) {
            int idx = tid + j*256;
            int row = idx >> 2, q = idx & 3;
            uint32_t d = sb + (row*20 + q*4) * 4;
            long ao = (long)row * lda + q*8;
            long bo = (long)row * ldb + q*8;
            CPA(d,           A0 + ao);
            CPA(d + 10240,   A1 + ao);
            CPA(d + 20480,   B0 + bo);
            CPA(d + 30720,   B1 + bo);
        }
        CPCOMMIT();
    }

    for (int t = 0; t < T; t++) {
        int s = t & 1;
        CPWAIT0();
        __syncthreads();
        if (t + 1 < T) {
            int kt = (t + 1) << 5;
            int so = (1 - s) * 10240 * 4;
            #pragma unroll
            for (int j = 0; j < 2; j++) {
                int idx = tid + j*256;
                int row = idx >> 2, q = idx & 3;
                uint32_t d = sb + so + (row*20 + q*4) * 4;
                long ao = (long)row * lda + kt + q*8;
                long bo = (long)row * ldb + kt + q*8;
                CPA(d,           A0 + ao);
                CPA(d + 10240,   A1 + ao);
                CPA(d + 20480,   B0 + bo);
                CPA(d + 30720,   B1 + bo);
            }
            CPCOMMIT();
        }
        const uint32_t* Ah = sm + s * 10240;
        const uint32_t* Al = Ah + 2560;
        const uint32_t* Bh = Ah + 5120;
        const uint32_t* Bl = Ah + 7680;
        #pragma unroll
        for (int po = 0; po < 16; po += 8) {
            uint32_t bh[4][2], bl[4][2];
            #pragma unroll
            for (int tn = 0; tn < 4; tn++) {
                int n = wn + tn*8 + gid;
                bh[tn][0] = Bh[n*20 + po + tig]; bh[tn][1] = Bh[n*20 + po + tig + 4];
                bl[tn][0] = Bl[n*20 + po + tig]; bl[tn][1] = Bl[n*20 + po + tig + 4];
            }
            #pragma unroll
            for (int tm = 0; tm < 4; tm++) {
                int m = wm + tm*16 + gid;
                uint32_t ah[4], al[4];
                ah[0] = Ah[m*20 + po + tig];     ah[1] = Ah[(m+8)*20 + po + tig];
                ah[2] = Ah[m*20 + po + tig + 4]; ah[3] = Ah[(m+8)*20 + po + tig + 4];
                al[0] = Al[m*20 + po + tig];     al[1] = Al[(m+8)*20 + po + tig];
                al[2] = Al[m*20 + po + tig + 4]; al[3] = Al[(m+8)*20 + po + tig + 4];
                #pragma unroll
                for (int tn = 0; tn < 4; tn++) {
                    mma16(acc[tm][tn], ah, bh[tn]);
                    mma16(acc[tm][tn], al, bh[tn]);
                    mma16(acc[tm][tn], ah, bl[tn]);
                }
            }
        }
    }

    #pragma unroll
    for (int tm = 0; tm < 4; tm++) {
        #pragma unroll
        for (int tn = 0; tn < 4; tn++) {
            long row = row0 + wm + tm*16 + gid;
            long col = col0 + wn + tn*8 + tig*2;
            #pragma unroll
            for (int half = 0; half < 2; half++) {
                long r = row + half*8;
                float v0 = acc[tm][tn][half*2+0];
                float v1 = acc[tm][tn][half*2+1];
                if (MODE == 0) {
                    float2 o; o.x = v0; o.y = v1;
                    *(float2*)(Cf + r*ldc + col) = o;
                    *(__half2*)(Ch + r*ldc + col) = __floats2half2_rn(v0, v1);
                } else {
                    v0 += bias[col]; v1 += bias[col+1];
                    v0 = gelu_f(v0); v1 = gelu_f(v1);
                    if (MODE == 2) {
                        float2 rv = *(const float2*)(resid + r*ldc + col);
                        float2 o; o.x = v0 + rv.x; o.y = v1 + rv.y;
                        *(float2*)(Cf + r*ldc + col) = o;
                    } else {
                        __half2 hv = __floats2half2_rn(v0, v1);
                        float2 hf = __half22float2(hv);
                        __half2 lv = __floats2half2_rn(v0 - hf.x, v1 - hf.y);
                        *(__half2*)(Th + r*ldc + col) = hv;
                        *(__half2*)(Tl + r*ldc + col) = lv;
                    }
                }
            }
        }
    }
}

// ============================================================== S GEMM + exp
// E[q,k] = exp(0.125 Q·K) fp16 [q][k]; column partial sums over q-blocks.
// Plain fp16 operands via cp.async, 2-stage (K=64 -> 2 tiles).
__global__ __launch_bounds__(256)
void s_gemm_exp_h(const __half* __restrict__ qkvh, __half* __restrict__ Eo,
                  float* __restrict__ psum)
{
    int z = blockIdx.z, zo = z >> 3, zi = z & 7;
    const __half* A = qkvh + (size_t)zo*Pq*E3      + (size_t)zi*64;  // Q
    const __half* B = qkvh + (size_t)zo*Pq*E3 + Eq + (size_t)zi*64;  // K
    __half* C = Eo + (size_t)z * Pq * Pq;

    extern __shared__ uint32_t sm[];
    uint32_t sb = smem_u32(sm);
    __shared__ float ps[128][2];

    int tid = threadIdx.x, lane = tid & 31, wid = tid >> 5;
    int gid = lane >> 2, tig = lane & 3;
    int wm = (wid >> 2) * 64, wn = (wid & 3) * 32;
    long row0 = (long)blockIdx.y * 128;   // q
    long col0 = (long)blockIdx.x * 128;   // k
    const __half* Ab = A + row0 * E3;
    const __half* Bb = B + col0 * E3;

    float acc[4][4][4];
    #pragma unroll
    for (int i = 0; i < 4; i++)
        #pragma unroll
        for (int j = 0; j < 4; j++)
            #pragma unroll
            for (int u = 0; u < 4; u++) acc[i][j][u] = 0.0f;

    {   // stage 0
        #pragma unroll
        for (int j = 0; j < 2; j++) {
            int idx = tid + j*256;
            int row = idx >> 2, q = idx & 3;
            uint32_t d = sb + (row*20 + q*4) * 4;
            CPA(d,         Ab + (long)row*E3 + q*8);
            CPA(d + 10240, Bb + (long)row*E3 + q*8);
        }
        CPCOMMIT();
    }
    #pragma unroll
    for (int t = 0; t < 2; t++) {
        int s = t & 1;
        CPWAIT0();
        __syncthreads();
        if (t == 0) {
            #pragma unroll
            for (int j = 0; j < 2; j++) {
                int idx = tid + j*256;
                int row = idx >> 2, q = idx & 3;
                uint32_t d = sb + 5120*4 + (row*20 + q*4) * 4;
                CPA(d,         Ab + (long)row*E3 + 32 + q*8);
                CPA(d + 10240, Bb + (long)row*E3 + 32 + q*8);
            }
            CPCOMMIT();
        }
        const uint32_t* Ah = sm + s * 5120;
        const uint32_t* Bh = Ah + 2560;
        #pragma unroll
        for (int po = 0; po < 16; po += 8) {
            uint32_t bh[4][2];
            #pragma unroll
            for (int tn = 0; tn < 4; tn++) {
                int n = wn + tn*8 + gid;
                bh[tn][0] = Bh[n*20 + po + tig]; bh[tn][1] = Bh[n*20 + po + tig + 4];
            }
            #pragma unroll
            for (int tm = 0; tm < 4; tm++) {
                int m = wm + tm*16 + gid;
                uint32_t ah[4];
                ah[0] = Ah[m*20 + po + tig];     ah[1] = Ah[(m+8)*20 + po + tig];
                ah[2] = Ah[m*20 + po + tig + 4]; ah[3] = Ah[(m+8)*20 + po + tig + 4];
                #pragma unroll
                for (int tn = 0; tn < 4; tn++) mma16(acc[tm][tn], ah, bh[tn]);
            }
        }
    }

    const float SC = 0.125f * 1.44269504088896f;
    float cs[4][2];
    #pragma unroll
    for (int tn = 0; tn < 4; tn++) { cs[tn][0] = 0.0f; cs[tn][1] = 0.0f; }
    #pragma unroll
    for (int tm = 0; tm < 4; tm++) {
        #pragma unroll
        for (int half = 0; half < 2; half++) {
            long r = row0 + wm + tm*16 + gid + half*8;
            #pragma unroll
            for (int tn = 0; tn < 4; tn++) {
                float y0 = acc[tm][tn][half*2+0] * SC;
                float y1 = acc[tm][tn][half*2+1] * SC;
                __half2 e2 = h2exp2(__floats2half2_rn(y0, y1));
                long col = col0 + wn + tn*8 + tig*2;
                *(__half2*)(C + r*Pq + col) = e2;
                float2 f = __half22float2(e2);
                cs[tn][0] += f.x; cs[tn][1] += f.y;
            }
        }
    }
    #pragma unroll
    for (int tn = 0; tn < 4; tn++) {
        #pragma unroll
        for (int u = 0; u < 2; u++) {
            float v = cs[tn][u];
            v += __shfl_xor_sync(0xffffffffu, v, 4);
            v += __shfl_xor_sync(0xffffffffu, v, 8);
            v += __shfl_xor_sync(0xffffffffu, v, 16);
            if (gid == 0) ps[wn + tn*8 + tig*2 + u][wid >> 2] = v;
        }
    }
    __syncthreads();
    if (tid < 128) {
        float tot = ps[tid][0] + ps[tid][1];
        psum[((size_t)z*Pq + col0 + tid) * 32 + blockIdx.y] = tot;
    }
}

// ============================================================== combine
__global__ void combine_kernel(const float* __restrict__ psum,
                               float* __restrict__ rinv)
{
    size_t r = (size_t)blockIdx.x * 256 + threadIdx.x;
    const float4* p = (const float4*)(psum + (r << 5));
    float s = 0.0f;
    #pragma unroll
    for (int i = 0; i < 8; i++) {
        float4 v = p[i];
        s += v.x + v.y + v.z + v.w;
    }
    rinv[r] = 1.0f / s;
}

// ============================================================== attention O
// out1[q, zi*64+d] = x + sum_k E[q,k]*(rinv[k]*V[k,d]).
// E staged via cp.async (raw fp16); V register-transposed; 2-stage pipeline.
__global__ __launch_bounds__(256)
void attn_o_h(const __half* __restrict__ Et, const float* __restrict__ qkv,
              float* __restrict__ out1, const float* __restrict__ x,
              const float* __restrict__ rinv)
{
    int z = blockIdx.z, zo = z >> 3, zi = z & 7;
    const __half* Eb = Et   + (size_t)z * Pq * Pq;
    const float*  Vb = qkv  + (size_t)zo * Pq * E3 + 2*Eq + (size_t)zi*64;
    float*        Cb = out1 + (size_t)zo * PE + (size_t)zi*64;
    const float*  Rb = x    + (size_t)zo * PE + (size_t)zi*64;
    const float* riv = rinv + (size_t)z * Pq;

    extern __shared__ uint32_t sm[];   // stage: E 2560 + V 1280 = 3840 u32
    uint32_t sb = smem_u32(sm);

    int tid = threadIdx.x, lane = tid & 31, wid = tid >> 5;
    int gid = lane >> 2, tig = lane & 3;
    int wm = (wid >> 2) * 64, wn = (wid & 3) * 16;
    long q0 = (long)blockIdx.y * 128;

    float acc[4][2][4];
    #pragma unroll
    for (int i = 0; i < 4; i++)
        #pragma unroll
        for (int j = 0; j < 2; j++)
            #pragma unroll
            for (int u = 0; u < 4; u++) acc[i][j][u] = 0.0f;

    // prologue: stage 0 (E via cp.async, V via register transform)
    {
        #pragma unroll
        for (int j = 0; j < 2; j++) {
            int idx = tid + j*256;
            int row = idx >> 2, c = idx & 3;
            CPA(sb + (row*20 + c*4)*4, Eb + (size_t)(q0 + row) * Pq + c*8);
        }
        CPCOMMIT();
        int db = tid & 15, kp = tid >> 4;
        uint32_t* stVT = sm + 2560;
        float iv0 = riv[2*kp], iv1 = riv[2*kp + 1];
        const float* r0p = Vb + (size_t)(2*kp) * E3 + db*4;
        float4 v0 = *(const float4*)r0p;
        float4 v1 = *(const float4*)(r0p + E3);
        v0.x *= iv0; v0.y *= iv0; v0.z *= iv0; v0.w *= iv0;
        v1.x *= iv1; v1.y *= iv1; v1.z *= iv1; v1.w *= iv1;
        stVT[(db*4+0)*20 + kp] = h2u(__floats2half2_rn(v0.x, v1.x));
        stVT[(db*4+1)*20 + kp] = h2u(__floats2half2_rn(v0.y, v1.y));
        stVT[(db*4+2)*20 + kp] = h2u(__floats2half2_rn(v0.z, v1.z));
        stVT[(db*4+3)*20 + kp] = h2u(__floats2half2_rn(v0.w, v1.w));
    }

    for (int t = 0; t < 128; t++) {
        int s = t & 1;
        CPWAIT0();
        __syncthreads();
        if (t < 127) {
            int k0 = (t + 1) * 32;
            int so = (1 - s) * 3840;
            #pragma unroll
            for (int j = 0; j < 2; j++) {
                int idx = tid + j*256;
                int row = idx >> 2, c = idx & 3;
                CPA(sb + (so + row*20 + c*4)*4,
                    Eb + (size_t)(q0 + row) * Pq + k0 + c*8);
            }
            CPCOMMIT();
            int db = tid & 15, kp = tid >> 4;
            uint32_t* stVT = sm + so + 2560;
            float iv0 = riv[k0 + 2*kp], iv1 = riv[k0 + 2*kp + 1];
            const float* r0p = Vb + (size_t)(k0 + 2*kp) * E3 + db*4;
            float4 v0 = *(const float4*)r0p;
            float4 v1 = *(const float4*)(r0p + E3);
            v0.x *= iv0; v0.y *= iv0; v0.z *= iv0; v0.w *= iv0;
            v1.x *= iv1; v1.y *= iv1; v1.z *= iv1; v1.w *= iv1;
            stVT[(db*4+0)*20 + kp] = h2u(__floats2half2_rn(v0.x, v1.x));
            stVT[(db*4+1)*20 + kp] = h2u(__floats2half2_rn(v0.y, v1.y));
            stVT[(db*4+2)*20 + kp] = h2u(__floats2half2_rn(v0.z, v1.z));
            stVT[(db*4+3)*20 + kp] = h2u(__floats2half2_rn(v0.w, v1.w));
        }
        const uint32_t* stP  = sm + s * 3840;
        const uint32_t* stVT = stP + 2560;
        #pragma unroll
        for (int po = 0; po < 16; po += 8) {
            uint32_t b[2][2];
            #pragma unroll
            for (int tn = 0; tn < 2; tn++) {
                int n = wn + tn*8 + gid;
                b[tn][0] = stVT[n*20 + po + tig];
                b[tn][1] = stVT[n*20 + po + tig + 4];
            }
            #pragma unroll
            for (int tm = 0; tm < 4; tm++) {
                int q = wm + tm*16 + gid;
                uint32_t a[4];
                a[0] = stP[q*20 + po + tig];     a[1] = stP[(q+8)*20 + po + tig];
                a[2] = stP[q*20 + po + tig + 4]; a[3] = stP[(q+8)*20 + po + tig + 4];
                #pragma unroll
                for (int tn = 0; tn < 2; tn++)
                    mma16(acc[tm][tn], a, b[tn]);
            }
        }
    }

    #pragma unroll
    for (int tm = 0; tm < 4; tm++) {
        #pragma unroll
        for (int tn = 0; tn < 2; tn++) {
            long q = q0 + wm + tm*16 + gid;
            int  d = wn + tn*8 + tig*2;
            #pragma unroll
            for (int half = 0; half < 2; half++) {
                long r = q + half*8;
                float2 rv = *(const float2*)(Rb + r*Eq + d);
                float2 o;
                o.x = acc[tm][tn][half*2+0] + rv.x;
                o.y = acc[tm][tn][half*2+1] + rv.y;
                *(float2*)(Cb + r*Eq + d) = o;
            }
        }
    }
}

// ============================================================== launcher
extern "C" void kernel_launch(void* const* d_in, const int* in_sizes, int n_in,
                              void* d_out, int out_size)
{
    const float* x  = (const float*)d_in[0];
    const float* g1 = (const float*)d_in[1];
    const float* b1 = (const float*)d_in[2];
    const float* W1 = (const float*)d_in[3];
    const float* g2 = (const float*)d_in[4];
    const float* b2 = (const float*)d_in[5];
    const float* Wa = (const float*)d_in[6];
    const float* ba = (const float*)d_in[7];
    const float* Wb = (const float*)d_in[8];
    const float* bb = (const float*)d_in[9];
    float* out = (float*)d_out;

    __half *hh, *hl, *W1h, *W1l, *Wah, *Wal, *Wbh, *Wbl, *qkvh, *th, *tl, *E;
    float *qkv, *out1, *riv, *psm;
    cudaGetSymbolAddress((void**)&hh,   g_hh);
    cudaGetSymbolAddress((void**)&hl,   g_hl);
    cudaGetSymbolAddress((void**)&W1h,  g_W1h);
    cudaGetSymbolAddress((void**)&W1l,  g_W1l);
    cudaGetSymbolAddress((void**)&Wah,  g_Wah);
    cudaGetSymbolAddress((void**)&Wal,  g_Wal);
    cudaGetSymbolAddress((void**)&Wbh,  g_Wbh);
    cudaGetSymbolAddress((void**)&Wbl,  g_Wbl);
    cudaGetSymbolAddress((void**)&qkv,  g_qkv);
    cudaGetSymbolAddress((void**)&qkvh, g_qkvh);
    cudaGetSymbolAddress((void**)&th,   g_th);
    cudaGetSymbolAddress((void**)&tl,   g_tl);
    cudaGetSymbolAddress((void**)&E,    g_E);
    cudaGetSymbolAddress((void**)&out1, g_out1);
    cudaGetSymbolAddress((void**)&riv,  g_rinv);
    cudaGetSymbolAddress((void**)&psm,  g_psum);

    const int SM_GEMM = 2 * 10240 * 4;   // 81920 B
    const int SM_S    = 2 * 5120 * 4;    // 40960 B
    const int SM_AO   = 2 * 3840 * 4;    // 30720 B
    cudaFuncSetAttribute(gemm_fp16<0>, cudaFuncAttributeMaxDynamicSharedMemorySize, SM_GEMM);
    cudaFuncSetAttribute(gemm_fp16<1>, cudaFuncAttributeMaxDynamicSharedMemorySize, SM_GEMM);
    cudaFuncSetAttribute(gemm_fp16<2>, cudaFuncAttributeMaxDynamicSharedMemorySize, SM_GEMM);
    cudaFuncSetAttribute(s_gemm_exp_h, cudaFuncAttributeMaxDynamicSharedMemorySize, SM_S);
    cudaFuncSetAttribute(attn_o_h,     cudaFuncAttributeMaxDynamicSharedMemorySize, SM_AO);

    const int W_N4 = (E3 * Eq) / 4;

    // weight splits (independent of LN)
    cvt_split<<<(W_N4 + 255)/256, 256>>>(W1, W1h, W1l, W_N4);
    cvt_split<<<(W_N4 + 255)/256, 256>>>(Wa, Wah, Wal, W_N4);
    cvt_split<<<(W_N4 + 255)/256, 256>>>(Wb, Wbh, Wbl, W_N4);

    // LN1 -> hi/lo fp16
    ln_reduce_kernel<<<dim3(NB_RED, Bq), 256>>>(x);
    ln_final_kernel<<<Bq, 256>>>();
    ln_apply_split<<<(Bq*PE/4 + 255)/256, 256>>>(x, g1, b1, hh, hl);

    // QKV = h @ W1^T  -> float qkv + fp16 qkvh
    gemm_fp16<0><<<dim3(E3/128, (Bq*Pq)/128, 1), 256, SM_GEMM>>>(
        hh, hl, W1h, W1l, Eq, Eq, Eq, E3,
        qkv, qkvh, (__half*)0, (__half*)0, (const float*)0, (const float*)0);

    // E[q,k] = exp(0.125 Q·K) + column partials
    s_gemm_exp_h<<<dim3(Pq/128, Pq/128, Bq*Hq), 256, SM_S>>>(qkvh, E, psm);

    // rinv
    combine_kernel<<<(Bq*Hq*Pq)/256, 256>>>(psm, riv);

    // out1 = x + E (rinv*V)
    attn_o_h<<<dim3(1, Pq/128, Bq*Hq), 256, SM_AO>>>(E, qkv, out1, x, riv);

    // LN2 -> hi/lo fp16
    ln_reduce_kernel<<<dim3(NB_RED, Bq), 256>>>(out1);
    ln_final_kernel<<<Bq, 256>>>();
    ln_apply_split<<<(Bq*PE/4 + 255)/256, 256>>>(out1, g2, b2, hh, hl);

    // t = gelu(h @ Wa^T + ba) -> hi/lo fp16 (no float roundtrip)
    gemm_fp16<1><<<dim3(E3/128, (Bq*Pq)/128, 1), 256, SM_GEMM>>>(
        hh, hl, Wah, Wal, Eq, Eq, Eq, E3,
        (float*)0, (__half*)0, th, tl, ba, (const float*)0);

    // out = gelu(t @ Wb^T + bb) + out1
    gemm_fp16<2><<<dim3(Eq/128, (Bq*Pq)/128, 1), 256, SM_GEMM>>>(
        th, tl, Wbh, Wbl, E3, E3, E3, Eq,
        out, (__half*)0, (__half*)0, (__half*)0, bb, out1);
}

// round 11
// speedup vs baseline: 3.1275x; 1.0228x over previous
#include <cuda_runtime.h>
#include <cuda_fp16.h>
#include <math.h>
#include <stdint.h>

#define Bq 2
#define Pq 4096
#define Eq 512
#define Hq 8
#define E3 1536
#define PE (Pq*Eq)
#define NB_RED 256

// ------------------------------------------------------------- scratch
__device__ __align__(16) __half g_hh [(size_t)Bq*Pq*Eq];
__device__ __align__(16) __half g_hl [(size_t)Bq*Pq*Eq];
__device__ __align__(16) __half g_W1h[(size_t)E3*Eq];
__device__ __align__(16) __half g_W1l[(size_t)E3*Eq];
__device__ __align__(16) __half g_Wah[(size_t)E3*Eq];
__device__ __align__(16) __half g_Wal[(size_t)E3*Eq];
__device__ __align__(16) __half g_Wbh[(size_t)Eq*E3];
__device__ __align__(16) __half g_Wbl[(size_t)Eq*E3];
__device__ __align__(16) float  g_qkv [(size_t)Bq*Pq*E3];
__device__ __align__(16) __half g_qkvh[(size_t)Bq*Pq*E3];
__device__ __align__(16) __half g_th [(size_t)Bq*Pq*E3];
__device__ __align__(16) __half g_tl [(size_t)Bq*Pq*E3];
__device__ __align__(16) __half g_E  [(size_t)Bq*Hq*Pq*Pq];
__device__ float  g_out1[(size_t)Bq*Pq*Eq];
__device__ float  g_rinv[(size_t)Bq*Hq*Pq];
__device__ float  g_psum[(size_t)Bq*Hq*Pq*32];
__device__ double g_part[Bq*NB_RED*2];
__device__ float  g_stats[Bq*2];

// ------------------------------------------------------------- helpers
__device__ __forceinline__ uint32_t smem_u32(const void* p){
    uint32_t a;
    asm("{ .reg .u64 t; cvta.to.shared.u64 t, %1; cvt.u32.u64 %0, t; }"
        : "=r"(a) : "l"(p));
    return a;
}
__device__ __forceinline__ uint32_t h2u(__half2 h){ return *reinterpret_cast<uint32_t*>(&h); }
__device__ __forceinline__ void splith4(float4 v, uint2& hi, uint2& lo){
    __half2 h01 = __floats2half2_rn(v.x, v.y);
    __half2 h23 = __floats2half2_rn(v.z, v.w);
    float2 f01 = __half22float2(h01);
    float2 f23 = __half22float2(h23);
    __half2 l01 = __floats2half2_rn(v.x - f01.x, v.y - f01.y);
    __half2 l23 = __floats2half2_rn(v.z - f23.x, v.w - f23.y);
    hi = make_uint2(h2u(h01), h2u(h23));
    lo = make_uint2(h2u(l01), h2u(l23));
}
__device__ __forceinline__ void mma16(float d[4], const uint32_t a[4], const uint32_t b[2]){
    asm volatile(
        "mma.sync.aligned.m16n8k16.row.col.f32.f16.f16.f32 "
        "{%0,%1,%2,%3}, {%4,%5,%6,%7}, {%8,%9}, {%0,%1,%2,%3};"
        : "+f"(d[0]), "+f"(d[1]), "+f"(d[2]), "+f"(d[3])
        : "r"(a[0]), "r"(a[1]), "r"(a[2]), "r"(a[3]), "r"(b[0]), "r"(b[1]));
}
__device__ __forceinline__ float gelu_f(float v){
    return 0.5f * v * (1.0f + erff(v * 0.70710678118654752440f));
}
// 2^y on the FMA/ALU pipes (no MUFU). |rel err| ~4e-5, below fp16 rounding.
__device__ __forceinline__ float fexp2f(float y){
    y = fmaxf(y, -100.0f);
    float t = y + 12582912.0f;                 // 1.5*2^23: low bits = rint(y)
    int   e = __float_as_int(t) - 0x4B400000;  // rint(y) as int
    float r = t - 12582912.0f;                 // rint(y) as float
    float f = y - r;                           // [-0.5, 0.5]
    float p = 1.3333558e-3f;
    p = fmaf(p, f, 9.6181291e-3f);
    p = fmaf(p, f, 5.5504109e-2f);
    p = fmaf(p, f, 2.4022651e-1f);
    p = fmaf(p, f, 6.9314718e-1f);
    p = fmaf(p, f, 1.0f);
    return __int_as_float((e + 127) << 23) * p;
}
#define CPA(dst, src) \
    asm volatile("cp.async.cg.shared.global [%0], [%1], 16;" :: "r"(dst), "l"(src))
#define CPCOMMIT() asm volatile("cp.async.commit_group;" ::: "memory")
#define CPWAIT0()  asm volatile("cp.async.wait_group 0;"  ::: "memory")

// ============================================================== LayerNorm
__global__ void ln_reduce_kernel(const float* __restrict__ x)
{
    int b = blockIdx.y;
    const float4* xb = (const float4*)(x + (size_t)b * PE);
    int base = blockIdx.x * blockDim.x + threadIdx.x;   // 65536 threads
    float s = 0.0f, s2 = 0.0f;
    #pragma unroll
    for (int j = 0; j < 8; j++) {
        float4 v = xb[base + j * (NB_RED * 256)];
        s += (v.x + v.y) + (v.z + v.w);
        s2 = fmaf(v.x, v.x, s2); s2 = fmaf(v.y, v.y, s2);
        s2 = fmaf(v.z, v.z, s2); s2 = fmaf(v.w, v.w, s2);
    }
    __shared__ double ss[256], ss2[256];
    int t = threadIdx.x;
    ss[t] = (double)s; ss2[t] = (double)s2;
    __syncthreads();
    for (int o = 128; o > 0; o >>= 1) {
        if (t < o) { ss[t] += ss[t+o]; ss2[t] += ss2[t+o]; }
        __syncthreads();
    }
    if (t == 0) {
        g_part[(b*NB_RED + blockIdx.x)*2 + 0] = ss[0];
        g_part[(b*NB_RED + blockIdx.x)*2 + 1] = ss2[0];
    }
}

__global__ void ln_final_kernel()
{
    int b = blockIdx.x, t = threadIdx.x;
    __shared__ double ss[256], ss2[256];
    ss[t]  = g_part[(b*NB_RED + t)*2 + 0];
    ss2[t] = g_part[(b*NB_RED + t)*2 + 1];
    __syncthreads();
    for (int o = 128; o > 0; o >>= 1) {
        if (t < o) { ss[t] += ss[t+o]; ss2[t] += ss2[t+o]; }
        __syncthreads();
    }
    if (t == 0) {
        double mean = ss[0] / (double)PE;
        double var  = ss2[0] / (double)PE - mean * mean;
        g_stats[b*2 + 0] = (float)mean;
        g_stats[b*2 + 1] = (float)(1.0 / sqrt(var + 1e-5));
    }
}

__global__ void ln_apply_split(const float* __restrict__ x,
                               const float* __restrict__ gam,
                               const float* __restrict__ bet,
                               __half* __restrict__ hh, __half* __restrict__ hl)
{
    const int n4 = PE / 4;
    int i = blockIdx.x * blockDim.x + threadIdx.x;
    if (i >= Bq * n4) return;
    int b = i / n4, pe = i - b * n4;
    float mean = g_stats[b*2 + 0], inv = g_stats[b*2 + 1];
    float4 xv = ((const float4*)x)[i];
    float4 gv = ((const float4*)gam)[pe];
    float4 bv = ((const float4*)bet)[pe];
    float4 o;
    o.x = (xv.x - mean) * inv * gv.x + bv.x;
    o.y = (xv.y - mean) * inv * gv.y + bv.y;
    o.z = (xv.z - mean) * inv * gv.z + bv.z;
    o.w = (xv.w - mean) * inv * gv.w + bv.w;
    uint2 h, l;
    splith4(o, h, l);
    ((uint2*)hh)[i] = h;
    ((uint2*)hl)[i] = l;
}

__global__ void cvt_split(const float* __restrict__ src,
                          __half* __restrict__ hi, __half* __restrict__ lo, int n4)
{
    int i = blockIdx.x * blockDim.x + threadIdx.x;
    if (i >= n4) return;
    uint2 h, l;
    splith4(((const float4*)src)[i], h, l);
    ((uint2*)hi)[i] = h;
    ((uint2*)lo)[i] = l;
}

// ============================================================== fp16-split GEMM
// MODE 0: float C + fp16 copy (QKV); MODE 1: bias+gelu -> hi/lo (MLP1);
// MODE 2: bias+gelu+resid -> float (MLP2). cp.async 2-stage, 3x mma split.
template<int MODE>
__global__ __launch_bounds__(256)
void gemm_fp16(const __half* __restrict__ Ahh, const __half* __restrict__ Alo,
               const __half* __restrict__ Bhh, const __half* __restrict__ Blo,
               int K, int lda, int ldb, int ldc,
               float* __restrict__ Cf, __half* __restrict__ Ch,
               __half* __restrict__ Th, __half* __restrict__ Tl,
               const float* __restrict__ bias, const float* __restrict__ resid)
{
    extern __shared__ uint32_t sm[];
    uint32_t sb = smem_u32(sm);
    int tid = threadIdx.x, lane = tid & 31, wid = tid >> 5;
    int gid = lane >> 2, tig = lane & 3;
    int wm = (wid >> 2) * 64, wn = (wid & 3) * 32;
    long row0 = (long)blockIdx.y * 128, col0 = (long)blockIdx.x * 128;
    const __half* A0 = Ahh + row0 * lda;
    const __half* A1 = Alo + row0 * lda;
    const __half* B0 = Bhh + col0 * ldb;
    const __half* B1 = Blo + col0 * ldb;

    float acc[4][4][4];
    #pragma unroll
    for (int i = 0; i < 4; i++)
        #pragma unroll
        for (int j = 0; j < 4; j++)
            #pragma unroll
            for (int u = 0; u < 4; u++) acc[i][j][u] = 0.0f;

    const int T = K >> 5;
    {
        #pragma unroll
        for (int j = 0; j < 2; j++) {
            int idx = tid + j*256;
            int row = idx >> 2, q = idx & 3;
            uint32_t d = sb + (row*20 + q*4) * 4;
            long ao = (long)row * lda + q*8;
            long bo = (long)row * ldb + q*8;
            CPA(d,           A0 + ao);
            CPA(d + 10240,   A1 + ao);
            CPA(d + 20480,   B0 + bo);
            CPA(d + 30720,   B1 + bo);
        }
        CPCOMMIT();
    }

    for (int t = 0; t < T; t++) {
        int s = t & 1;
        CPWAIT0();
        __syncthreads();
        if (t + 1 < T) {
            int kt = (t + 1) << 5;
            int so = (1 - s) * 10240 * 4;
            #pragma unroll
            for (int j = 0; j < 2; j++) {
                int idx = tid + j*256;
                int row = idx >> 2, q = idx & 3;
                uint32_t d = sb + so + (row*20 + q*4) * 4;
                long ao = (long)row * lda + kt + q*8;
                long bo = (long)row * ldb + kt + q*8;
                CPA(d,           A0 + ao);
                CPA(d + 10240,   A1 + ao);
                CPA(d + 20480,   B0 + bo);
                CPA(d + 30720,   B1 + bo);
            }
            CPCOMMIT();
        }
        const uint32_t* Ah = sm + s * 10240;
        const uint32_t* Al = Ah + 2560;
        const uint32_t* Bh = Ah + 5120;
        const uint32_t* Bl = Ah + 7680;
        #pragma unroll
        for (int po = 0; po < 16; po += 8) {
            uint32_t bh[4][2], bl[4][2];
            #pragma unroll
            for (int tn = 0; tn < 4; tn++) {
                int n = wn + tn*8 + gid;
                bh[tn][0] = Bh[n*20 + po + tig]; bh[tn][1] = Bh[n*20 + po + tig + 4];
                bl[tn][0] = Bl[n*20 + po + tig]; bl[tn][1] = Bl[n*20 + po + tig + 4];
            }
            #pragma unroll
            for (int tm = 0; tm < 4; tm++) {
                int m = wm + tm*16 + gid;
                uint32_t ah[4], al[4];
                ah[0] = Ah[m*20 + po + tig];     ah[1] = Ah[(m+8)*20 + po + tig];
                ah[2] = Ah[m*20 + po + tig + 4]; ah[3] = Ah[(m+8)*20 + po + tig + 4];
                al[0] = Al[m*20 + po + tig];     al[1] = Al[(m+8)*20 + po + tig];
                al[2] = Al[m*20 + po + tig + 4]; al[3] = Al[(m+8)*20 + po + tig + 4];
                #pragma unroll
                for (int tn = 0; tn < 4; tn++) {
                    mma16(acc[tm][tn], ah, bh[tn]);
                    mma16(acc[tm][tn], al, bh[tn]);
                    mma16(acc[tm][tn], ah, bl[tn]);
                }
            }
        }
    }

    #pragma unroll
    for (int tm = 0; tm < 4; tm++) {
        #pragma unroll
        for (int tn = 0; tn < 4; tn++) {
            long row = row0 + wm + tm*16 + gid;
            long col = col0 + wn + tn*8 + tig*2;
            #pragma unroll
            for (int half = 0; half < 2; half++) {
                long r = row + half*8;
                float v0 = acc[tm][tn][half*2+0];
                float v1 = acc[tm][tn][half*2+1];
                if (MODE == 0) {
                    float2 o; o.x = v0; o.y = v1;
                    *(float2*)(Cf + r*ldc + col) = o;
                    *(__half2*)(Ch + r*ldc + col) = __floats2half2_rn(v0, v1);
                } else {
                    v0 += bias[col]; v1 += bias[col+1];
                    v0 = gelu_f(v0); v1 = gelu_f(v1);
                    if (MODE == 2) {
                        float2 rv = *(const float2*)(resid + r*ldc + col);
                        float2 o; o.x = v0 + rv.x; o.y = v1 + rv.y;
                        *(float2*)(Cf + r*ldc + col) = o;
                    } else {
                        __half2 hv = __floats2half2_rn(v0, v1);
                        float2 hf = __half22float2(hv);
                        __half2 lv = __floats2half2_rn(v0 - hf.x, v1 - hf.y);
                        *(__half2*)(Th + r*ldc + col) = hv;
                        *(__half2*)(Tl + r*ldc + col) = lv;
                    }
                }
            }
        }
    }
}

// ============================================================== S GEMM + exp
__global__ __launch_bounds__(256)
void s_gemm_exp_h(const __half* __restrict__ qkvh, __half* __restrict__ Eo,
                  float* __restrict__ psum)
{
    int z = blockIdx.z, zo = z >> 3, zi = z & 7;
    const __half* A = qkvh + (size_t)zo*Pq*E3      + (size_t)zi*64;  // Q
    const __half* B = qkvh + (size_t)zo*Pq*E3 + Eq + (size_t)zi*64;  // K
    __half* C = Eo + (size_t)z * Pq * Pq;

    extern __shared__ uint32_t sm[];
    uint32_t sb = smem_u32(sm);
    __shared__ float ps[128][2];

    int tid = threadIdx.x, lane = tid & 31, wid = tid >> 5;
    int gid = lane >> 2, tig = lane & 3;
    int wm = (wid >> 2) * 64, wn = (wid & 3) * 32;
    long row0 = (long)blockIdx.y * 128;   // q
    long col0 = (long)blockIdx.x * 128;   // k
    const __half* Ab = A + row0 * E3;
    const __half* Bb = B + col0 * E3;

    float acc[4][4][4];
    #pragma unroll
    for (int i = 0; i < 4; i++)
        #pragma unroll
        for (int j = 0; j < 4; j++)
            #pragma unroll
            for (int u = 0; u < 4; u++) acc[i][j][u] = 0.0f;

    {
        #pragma unroll
        for (int j = 0; j < 2; j++) {
            int idx = tid + j*256;
            int row = idx >> 2, q = idx & 3;
            uint32_t d = sb + (row*20 + q*4) * 4;
            CPA(d,         Ab + (long)row*E3 + q*8);
            CPA(d + 10240, Bb + (long)row*E3 + q*8);
        }
        CPCOMMIT();
    }
    #pragma unroll
    for (int t = 0; t < 2; t++) {
        int s = t & 1;
        CPWAIT0();
        __syncthreads();
        if (t == 0) {
            #pragma unroll
            for (int j = 0; j < 2; j++) {
                int idx = tid + j*256;
                int row = idx >> 2, q = idx & 3;
                uint32_t d = sb + 5120*4 + (row*20 + q*4) * 4;
                CPA(d,         Ab + (long)row*E3 + 32 + q*8);
                CPA(d + 10240, Bb + (long)row*E3 + 32 + q*8);
            }
            CPCOMMIT();
        }
        const uint32_t* Ah = sm + s * 5120;
        const uint32_t* Bh = Ah + 2560;
        #pragma unroll
        for (int po = 0; po < 16; po += 8) {
            uint32_t bh[4][2];
            #pragma unroll
            for (int tn = 0; tn < 4; tn++) {
                int n = wn + tn*8 + gid;
                bh[tn][0] = Bh[n*20 + po + tig]; bh[tn][1] = Bh[n*20 + po + tig + 4];
            }
            #pragma unroll
            for (int tm = 0; tm < 4; tm++) {
                int m = wm + tm*16 + gid;
                uint32_t ah[4];
                ah[0] = Ah[m*20 + po + tig];     ah[1] = Ah[(m+8)*20 + po + tig];
                ah[2] = Ah[m*20 + po + tig + 4]; ah[3] = Ah[(m+8)*20 + po + tig + 4];
                #pragma unroll
                for (int tn = 0; tn < 4; tn++) mma16(acc[tm][tn], ah, bh[tn]);
            }
        }
    }

    const float SC = 0.125f * 1.44269504088896f;
    float cs[4][2];
    #pragma unroll
    for (int tn = 0; tn < 4; tn++) { cs[tn][0] = 0.0f; cs[tn][1] = 0.0f; }
    #pragma unroll
    for (int tm = 0; tm < 4; tm++) {
        #pragma unroll
        for (int half = 0; half < 2; half++) {
            long r = row0 + wm + tm*16 + gid + half*8;
            #pragma unroll
            for (int tn = 0; tn < 4; tn++) {
                float e0 = fexp2f(acc[tm][tn][half*2+0] * SC);
                float e1 = fexp2f(acc[tm][tn][half*2+1] * SC);
                __half2 e2 = __floats2half2_rn(e0, e1);
                long col = col0 + wn + tn*8 + tig*2;
                *(__half2*)(C + r*Pq + col) = e2;
                float2 f = __half22float2(e2);
                cs[tn][0] += f.x; cs[tn][1] += f.y;
            }
        }
    }
    #pragma unroll
    for (int tn = 0; tn < 4; tn++) {
        #pragma unroll
        for (int u = 0; u < 2; u++) {
            float v = cs[tn][u];
            v += __shfl_xor_sync(0xffffffffu, v, 4);
            v += __shfl_xor_sync(0xffffffffu, v, 8);
            v += __shfl_xor_sync(0xffffffffu, v, 16);
            if (gid == 0) ps[wn + tn*8 + tig*2 + u][wid >> 2] = v;
        }
    }
    __syncthreads();
    if (tid < 128) {
        float tot = ps[tid][0] + ps[tid][1];
        psum[((size_t)z*Pq + col0 + tid) * 32 + blockIdx.y] = tot;
    }
}

// ============================================================== combine
__global__ void combine_kernel(const float* __restrict__ psum,
                               float* __restrict__ rinv)
{
    size_t r = (size_t)blockIdx.x * 256 + threadIdx.x;
    const float4* p = (const float4*)(psum + (r << 5));
    float s = 0.0f;
    #pragma unroll
    for (int i = 0; i < 8; i++) {
        float4 v = p[i];
        s += v.x + v.y + v.z + v.w;
    }
    rinv[r] = 1.0f / s;
}

// ============================================================== attention O
// KT=64, 2-stage. E staged raw via cp.async [q][36]; V transposed to
// [kpair][72] with one STS.128 per thread; conflict-free fragment reads.
__global__ __launch_bounds__(256)
void attn_o_h(const __half* __restrict__ Et, const float* __restrict__ qkv,
              float* __restrict__ out1, const float* __restrict__ x,
              const float* __restrict__ rinv)
{
    int z = blockIdx.z, zo = z >> 3, zi = z & 7;
    const __half* Eb = Et   + (size_t)z * Pq * Pq;
    const float*  Vb = qkv  + (size_t)zo * Pq * E3 + 2*Eq + (size_t)zi*64;
    float*        Cb = out1 + (size_t)zo * PE + (size_t)zi*64;
    const float*  Rb = x    + (size_t)zo * PE + (size_t)zi*64;
    const float* riv = rinv + (size_t)z * Pq;

    extern __shared__ uint32_t sm[];   // stage: stP 128*36=4608 + stVT 32*72=2304
    uint32_t sb = smem_u32(sm);

    int tid = threadIdx.x, lane = tid & 31, wid = tid >> 5;
    int gid = lane >> 2, tig = lane & 3;
    int wm = (wid >> 2) * 64, wn = (wid & 3) * 16;
    long q0 = (long)blockIdx.y * 128;
    int db = tid & 15, kpb = tid >> 4;

    float acc[4][2][4];
    #pragma unroll
    for (int i = 0; i < 4; i++)
        #pragma unroll
        for (int j = 0; j < 2; j++)
            #pragma unroll
            for (int u = 0; u < 4; u++) acc[i][j][u] = 0.0f;

    auto load_stage = [&](int s, int k0){
        int so = s * 6912;
        #pragma unroll
        for (int j = 0; j < 4; j++) {
            int idx = tid + j*256;
            int row = idx >> 3, c = idx & 7;
            CPA(sb + (so + row*36 + c*4)*4, Eb + (size_t)(q0 + row) * Pq + k0 + c*8);
        }
        CPCOMMIT();
        #pragma unroll
        for (int kk = 0; kk < 2; kk++) {
            int kp = kpb + kk*16;
            float iv0 = riv[k0 + 2*kp], iv1 = riv[k0 + 2*kp + 1];
            const float* r0p = Vb + (size_t)(k0 + 2*kp) * E3 + db*4;
            float4 v0 = *(const float4*)r0p;
            float4 v1 = *(const float4*)(r0p + E3);
            uint4 w;
            w.x = h2u(__floats2half2_rn(v0.x*iv0, v1.x*iv1));
            w.y = h2u(__floats2half2_rn(v0.y*iv0, v1.y*iv1));
            w.z = h2u(__floats2half2_rn(v0.z*iv0, v1.z*iv1));
            w.w = h2u(__floats2half2_rn(v0.w*iv0, v1.w*iv1));
            *(uint4*)&sm[so + 4608 + kp*72 + db*4] = w;
        }
    };

    load_stage(0, 0);
    for (int t = 0; t < 64; t++) {
        int s = t & 1;
        CPWAIT0();
        __syncthreads();
        if (t < 63) load_stage(1 - s, (t + 1) * 64);
        const uint32_t* stP = sm + s * 6912;
        const uint32_t* stV = stP + 4608;
        #pragma unroll
        for (int po = 0; po < 32; po += 8) {
            uint32_t b[2][2];
            #pragma unroll
            for (int tn = 0; tn < 2; tn++) {
                int n = wn + tn*8 + gid;
                b[tn][0] = stV[(po + tig)*72 + n];
                b[tn][1] = stV[(po + tig + 4)*72 + n];
            }
            #pragma unroll
            for (int tm = 0; tm < 4; tm++) {
                int q = wm + tm*16 + gid;
                uint32_t a[4];
                a[0] = stP[q*36 + po + tig];     a[1] = stP[(q+8)*36 + po + tig];
                a[2] = stP[q*36 + po + tig + 4]; a[3] = stP[(q+8)*36 + po + tig + 4];
                #pragma unroll
                for (int tn = 0; tn < 2; tn++)
                    mma16(acc[tm][tn], a, b[tn]);
            }
        }
    }

    #pragma unroll
    for (int tm = 0; tm < 4; tm++) {
        #pragma unroll
        for (int tn = 0; tn < 2; tn++) {
            long q = q0 + wm + tm*16 + gid;
            int  d = wn + tn*8 + tig*2;
            #pragma unroll
            for (int half = 0; half < 2; half++) {
                long r = q + half*8;
                float2 rv = *(const float2*)(Rb + r*Eq + d);
                float2 o;
                o.x = acc[tm][tn][half*2+0] + rv.x;
                o.y = acc[tm][tn][half*2+1] + rv.y;
                *(float2*)(Cb + r*Eq + d) = o;
            }
        }
    }
}

// ============================================================== launcher
extern "C" void kernel_launch(void* const* d_in, const int* in_sizes, int n_in,
                              void* d_out, int out_size)
{
    const float* x  = (const float*)d_in[0];
    const float* g1 = (const float*)d_in[1];
    const float* b1 = (const float*)d_in[2];
    const float* W1 = (const float*)d_in[3];
    const float* g2 = (const float*)d_in[4];
    const float* b2 = (const float*)d_in[5];
    const float* Wa = (const float*)d_in[6];
    const float* ba = (const float*)d_in[7];
    const float* Wb = (const float*)d_in[8];
    const float* bb = (const float*)d_in[9];
    float* out = (float*)d_out;

    __half *hh, *hl, *W1h, *W1l, *Wah, *Wal, *Wbh, *Wbl, *qkvh, *th, *tl, *E;
    float *qkv, *out1, *riv, *psm;
    cudaGetSymbolAddress((void**)&hh,   g_hh);
    cudaGetSymbolAddress((void**)&hl,   g_hl);
    cudaGetSymbolAddress((void**)&W1h,  g_W1h);
    cudaGetSymbolAddress((void**)&W1l,  g_W1l);
    cudaGetSymbolAddress((void**)&Wah,  g_Wah);
    cudaGetSymbolAddress((void**)&Wal,  g_Wal);
    cudaGetSymbolAddress((void**)&Wbh,  g_Wbh);
    cudaGetSymbolAddress((void**)&Wbl,  g_Wbl);
    cudaGetSymbolAddress((void**)&qkv,  g_qkv);
    cudaGetSymbolAddress((void**)&qkvh, g_qkvh);
    cudaGetSymbolAddress((void**)&th,   g_th);
    cudaGetSymbolAddress((void**)&tl,   g_tl);
    cudaGetSymbolAddress((void**)&E,    g_E);
    cudaGetSymbolAddress((void**)&out1, g_out1);
    cudaGetSymbolAddress((void**)&riv,  g_rinv);
    cudaGetSymbolAddress((void**)&psm,  g_psum);

    const int SM_GEMM = 2 * 10240 * 4;
    const int SM_S    = 2 * 5120 * 4;
    const int SM_AO   = 2 * 6912 * 4;
    cudaFuncSetAttribute(gemm_fp16<0>, cudaFuncAttributeMaxDynamicSharedMemorySize, SM_GEMM);
    cudaFuncSetAttribute(gemm_fp16<1>, cudaFuncAttributeMaxDynamicSharedMemorySize, SM_GEMM);
    cudaFuncSetAttribute(gemm_fp16<2>, cudaFuncAttributeMaxDynamicSharedMemorySize, SM_GEMM);
    cudaFuncSetAttribute(s_gemm_exp_h, cudaFuncAttributeMaxDynamicSharedMemorySize, SM_S);
    cudaFuncSetAttribute(attn_o_h,     cudaFuncAttributeMaxDynamicSharedMemorySize, SM_AO);

    const int W_N4 = (E3 * Eq) / 4;

    cvt_split<<<(W_N4 + 255)/256, 256>>>(W1, W1h, W1l, W_N4);
    cvt_split<<<(W_N4 + 255)/256, 256>>>(Wa, Wah, Wal, W_N4);
    cvt_split<<<(W_N4 + 255)/256, 256>>>(Wb, Wbh, Wbl, W_N4);

    // LN1
    ln_reduce_kernel<<<dim3(NB_RED, Bq), 256>>>(x);
    ln_final_kernel<<<Bq, 256>>>();
    ln_apply_split<<<(Bq*PE/4 + 255)/256, 256>>>(x, g1, b1, hh, hl);

    // QKV
    gemm_fp16<0><<<dim3(E3/128, (Bq*Pq)/128, 1), 256, SM_GEMM>>>(
        hh, hl, W1h, W1l, Eq, Eq, Eq, E3,
        qkv, qkvh, (__half*)0, (__half*)0, (const float*)0, (const float*)0);

    // E + column partials
    s_gemm_exp_h<<<dim3(Pq/128, Pq/128, Bq*Hq), 256, SM_S>>>(qkvh, E, psm);

    combine_kernel<<<(Bq*Hq*Pq)/256, 256>>>(psm, riv);

    // out1 = x + E (rinv*V)
    attn_o_h<<<dim3(1, Pq/128, Bq*Hq), 256, SM_AO>>>(E, qkv, out1, x, riv);

    // LN2
    ln_reduce_kernel<<<dim3(NB_RED, Bq), 256>>>(out1);
    ln_final_kernel<<<Bq, 256>>>();
    ln_apply_split<<<(Bq*PE/4 + 255)/256, 256>>>(out1, g2, b2, hh, hl);

    // MLP1
    gemm_fp16<1><<<dim3(E3/128, (Bq*Pq)/128, 1), 256, SM_GEMM>>>(
        hh, hl, Wah, Wal, Eq, Eq, Eq, E3,
        (float*)0, (__half*)0, th, tl, ba, (const float*)0);

    // MLP2
    gemm_fp16<2><<<dim3(Eq/128, (Bq*Pq)/128, 1), 256, SM_GEMM>>>(
        th, tl, Wbh, Wbl, E3, E3, E3, Eq,
        out, (__half*)0, (__half*)0, (__half*)0, bb, out1);
}

// round 12
// speedup vs baseline: 3.2232x; 1.0306x over previous
#include <cuda_runtime.h>
#include <cuda_fp16.h>
#include <math.h>
#include <stdint.h>

#define Bq 2
#define Pq 4096
#define Eq 512
#define Hq 8
#define E3 1536
#define PE (Pq*Eq)
#define NB_RED 256

// ------------------------------------------------------------- scratch
__device__ __align__(16) __half g_hh [(size_t)Bq*Pq*Eq];
__device__ __align__(16) __half g_hl [(size_t)Bq*Pq*Eq];
__device__ __align__(16) __half g_W1h[(size_t)E3*Eq];
__device__ __align__(16) __half g_W1l[(size_t)E3*Eq];
__device__ __align__(16) __half g_Wah[(size_t)E3*Eq];
__device__ __align__(16) __half g_Wal[(size_t)E3*Eq];
__device__ __align__(16) __half g_Wbh[(size_t)Eq*E3];
__device__ __align__(16) __half g_Wbl[(size_t)Eq*E3];
__device__ __align__(16) __half g_qkvh[(size_t)Bq*Pq*E3];
__device__ __align__(16) __half g_th [(size_t)Bq*Pq*E3];
__device__ __align__(16) __half g_tl [(size_t)Bq*Pq*E3];
__device__ __align__(16) __half g_E  [(size_t)Bq*Hq*Pq*Pq];
__device__ float  g_out1[(size_t)Bq*Pq*Eq];
__device__ float  g_rinv[(size_t)Bq*Hq*Pq];
__device__ float  g_psum[(size_t)Bq*Hq*Pq*32];
__device__ double g_part[Bq*NB_RED*2];
__device__ float  g_stats[Bq*2];

// ------------------------------------------------------------- helpers
__device__ __forceinline__ uint32_t smem_u32(const void* p){
    uint32_t a;
    asm("{ .reg .u64 t; cvta.to.shared.u64 t, %1; cvt.u32.u64 %0, t; }"
        : "=r"(a) : "l"(p));
    return a;
}
__device__ __forceinline__ uint32_t h2u(__half2 h){ return *reinterpret_cast<uint32_t*>(&h); }
__device__ __forceinline__ void splith4(float4 v, uint2& hi, uint2& lo){
    __half2 h01 = __floats2half2_rn(v.x, v.y);
    __half2 h23 = __floats2half2_rn(v.z, v.w);
    float2 f01 = __half22float2(h01);
    float2 f23 = __half22float2(h23);
    __half2 l01 = __floats2half2_rn(v.x - f01.x, v.y - f01.y);
    __half2 l23 = __floats2half2_rn(v.z - f23.x, v.w - f23.y);
    hi = make_uint2(h2u(h01), h2u(h23));
    lo = make_uint2(h2u(l01), h2u(l23));
}
__device__ __forceinline__ void mma16(float d[4], const uint32_t a[4], const uint32_t b[2]){
    asm volatile(
        "mma.sync.aligned.m16n8k16.row.col.f32.f16.f16.f32 "
        "{%0,%1,%2,%3}, {%4,%5,%6,%7}, {%8,%9}, {%0,%1,%2,%3};"
        : "+f"(d[0]), "+f"(d[1]), "+f"(d[2]), "+f"(d[3])
        : "r"(a[0]), "r"(a[1]), "r"(a[2]), "r"(a[3]), "r"(b[0]), "r"(b[1]));
}
__device__ __forceinline__ void ldm_x4(uint32_t r[4], uint32_t addr){
    asm volatile("ldmatrix.sync.aligned.m8n8.x4.shared.b16 {%0,%1,%2,%3}, [%4];"
        : "=r"(r[0]), "=r"(r[1]), "=r"(r[2]), "=r"(r[3]) : "r"(addr));
}
__device__ __forceinline__ void ldm_x2(uint32_t r[2], uint32_t addr){
    asm volatile("ldmatrix.sync.aligned.m8n8.x2.shared.b16 {%0,%1}, [%2];"
        : "=r"(r[0]), "=r"(r[1]) : "r"(addr));
}
__device__ __forceinline__ float gelu_f(float v){
    return 0.5f * v * (1.0f + erff(v * 0.70710678118654752440f));
}
// 2^y on the FMA/ALU pipes. |rel err| ~4e-5, below fp16 rounding.
__device__ __forceinline__ float fexp2f(float y){
    y = fmaxf(y, -100.0f);
    float t = y + 12582912.0f;
    int   e = __float_as_int(t) - 0x4B400000;
    float r = t - 12582912.0f;
    float f = y - r;
    float p = 1.3333558e-3f;
    p = fmaf(p, f, 9.6181291e-3f);
    p = fmaf(p, f, 5.5504109e-2f);
    p = fmaf(p, f, 2.4022651e-1f);
    p = fmaf(p, f, 6.9314718e-1f);
    p = fmaf(p, f, 1.0f);
    return __int_as_float((e + 127) << 23) * p;
}
#define CPA(dst, src) \
    asm volatile("cp.async.cg.shared.global [%0], [%1], 16;" :: "r"(dst), "l"(src))
#define CPCOMMIT() asm volatile("cp.async.commit_group;" ::: "memory")
#define CPWAIT0()  asm volatile("cp.async.wait_group 0;"  ::: "memory")

// ============================================================== LayerNorm
__global__ void ln_reduce_kernel(const float* __restrict__ x)
{
    int b = blockIdx.y;
    const float4* xb = (const float4*)(x + (size_t)b * PE);
    int base = blockIdx.x * blockDim.x + threadIdx.x;
    float s = 0.0f, s2 = 0.0f;
    #pragma unroll
    for (int j = 0; j < 8; j++) {
        float4 v = xb[base + j * (NB_RED * 256)];
        s += (v.x + v.y) + (v.z + v.w);
        s2 = fmaf(v.x, v.x, s2); s2 = fmaf(v.y, v.y, s2);
        s2 = fmaf(v.z, v.z, s2); s2 = fmaf(v.w, v.w, s2);
    }
    __shared__ double ss[256], ss2[256];
    int t = threadIdx.x;
    ss[t] = (double)s; ss2[t] = (double)s2;
    __syncthreads();
    for (int o = 128; o > 0; o >>= 1) {
        if (t < o) { ss[t] += ss[t+o]; ss2[t] += ss2[t+o]; }
        __syncthreads();
    }
    if (t == 0) {
        g_part[(b*NB_RED + blockIdx.x)*2 + 0] = ss[0];
        g_part[(b*NB_RED + blockIdx.x)*2 + 1] = ss2[0];
    }
}

__global__ void ln_final_kernel()
{
    int b = blockIdx.x, t = threadIdx.x;
    __shared__ double ss[256], ss2[256];
    ss[t]  = g_part[(b*NB_RED + t)*2 + 0];
    ss2[t] = g_part[(b*NB_RED + t)*2 + 1];
    __syncthreads();
    for (int o = 128; o > 0; o >>= 1) {
        if (t < o) { ss[t] += ss[t+o]; ss2[t] += ss2[t+o]; }
        __syncthreads();
    }
    if (t == 0) {
        double mean = ss[0] / (double)PE;
        double var  = ss2[0] / (double)PE - mean * mean;
        g_stats[b*2 + 0] = (float)mean;
        g_stats[b*2 + 1] = (float)(1.0 / sqrt(var + 1e-5));
    }
}

__global__ void ln_apply_split(const float* __restrict__ x,
                               const float* __restrict__ gam,
                               const float* __restrict__ bet,
                               __half* __restrict__ hh, __half* __restrict__ hl)
{
    const int n4 = PE / 4;
    int i = blockIdx.x * blockDim.x + threadIdx.x;
    if (i >= Bq * n4) return;
    int b = i / n4, pe = i - b * n4;
    float mean = g_stats[b*2 + 0], inv = g_stats[b*2 + 1];
    float4 xv = ((const float4*)x)[i];
    float4 gv = ((const float4*)gam)[pe];
    float4 bv = ((const float4*)bet)[pe];
    float4 o;
    o.x = (xv.x - mean) * inv * gv.x + bv.x;
    o.y = (xv.y - mean) * inv * gv.y + bv.y;
    o.z = (xv.z - mean) * inv * gv.z + bv.z;
    o.w = (xv.w - mean) * inv * gv.w + bv.w;
    uint2 h, l;
    splith4(o, h, l);
    ((uint2*)hh)[i] = h;
    ((uint2*)hl)[i] = l;
}

__global__ void cvt_split(const float* __restrict__ src,
                          __half* __restrict__ hi, __half* __restrict__ lo, int n4)
{
    int i = blockIdx.x * blockDim.x + threadIdx.x;
    if (i >= n4) return;
    uint2 h, l;
    splith4(((const float4*)src)[i], h, l);
    ((uint2*)hi)[i] = h;
    ((uint2*)lo)[i] = l;
}

// ============================================================== fp16-split GEMM
// MODE 0: fp16 C (QKV); MODE 1: bias+gelu -> hi/lo (MLP1);
// MODE 2: bias+gelu+resid -> float (MLP2). cp.async 2-stage + ldmatrix.
template<int MODE>
__global__ __launch_bounds__(256)
void gemm_fp16(const __half* __restrict__ Ahh, const __half* __restrict__ Alo,
               const __half* __restrict__ Bhh, const __half* __restrict__ Blo,
               int K, int lda, int ldb, int ldc,
               float* __restrict__ Cf, __half* __restrict__ Ch,
               __half* __restrict__ Th, __half* __restrict__ Tl,
               const float* __restrict__ bias, const float* __restrict__ resid)
{
    extern __shared__ uint32_t sm[];
    uint32_t sb = smem_u32(sm);
    int tid = threadIdx.x, lane = tid & 31, wid = tid >> 5;
    int gid = lane >> 2, tig = lane & 3;
    int wm = (wid >> 2) * 64, wn = (wid & 3) * 32;
    long row0 = (long)blockIdx.y * 128, col0 = (long)blockIdx.x * 128;
    const __half* A0 = Ahh + row0 * lda;
    const __half* A1 = Alo + row0 * lda;
    const __half* B0 = Bhh + col0 * ldb;
    const __half* B1 = Blo + col0 * ldb;

    // per-thread ldmatrix byte offsets (within one matrix plane)
    uint32_t aoff[4], boff[4];
    #pragma unroll
    for (int tm = 0; tm < 4; tm++)
        aoff[tm] = ((wm + tm*16 + (lane & 15))*20 + (lane >> 4)*4) * 4;
    #pragma unroll
    for (int tn = 0; tn < 4; tn++)
        boff[tn] = ((wn + tn*8 + (lane & 7))*20 + ((lane >> 3) & 1)*4) * 4;

    float acc[4][4][4];
    #pragma unroll
    for (int i = 0; i < 4; i++)
        #pragma unroll
        for (int j = 0; j < 4; j++)
            #pragma unroll
            for (int u = 0; u < 4; u++) acc[i][j][u] = 0.0f;

    const int T = K >> 5;
    {
        #pragma unroll
        for (int j = 0; j < 2; j++) {
            int idx = tid + j*256;
            int row = idx >> 2, q = idx & 3;
            uint32_t d = sb + (row*20 + q*4) * 4;
            long ao = (long)row * lda + q*8;
            long bo = (long)row * ldb + q*8;
            CPA(d,           A0 + ao);
            CPA(d + 10240,   A1 + ao);
            CPA(d + 20480,   B0 + bo);
            CPA(d + 30720,   B1 + bo);
        }
        CPCOMMIT();
    }

    for (int t = 0; t < T; t++) {
        int s = t & 1;
        CPWAIT0();
        __syncthreads();
        if (t + 1 < T) {
            int kt = (t + 1) << 5;
            int so = (1 - s) * 40960;
            #pragma unroll
            for (int j = 0; j < 2; j++) {
                int idx = tid + j*256;
                int row = idx >> 2, q = idx & 3;
                uint32_t d = sb + so + (row*20 + q*4) * 4;
                long ao = (long)row * lda + kt + q*8;
                long bo = (long)row * ldb + kt + q*8;
                CPA(d,           A0 + ao);
                CPA(d + 10240,   A1 + ao);
                CPA(d + 20480,   B0 + bo);
                CPA(d + 30720,   B1 + bo);
            }
            CPCOMMIT();
        }
        uint32_t baseA = sb + s * 40960;
        #pragma unroll
        for (int po = 0; po < 16; po += 8) {
            uint32_t bh[4][2], bl[4][2];
            #pragma unroll
            for (int tn = 0; tn < 4; tn++) {
                ldm_x2(bh[tn], baseA + 20480 + boff[tn] + po*4);
                ldm_x2(bl[tn], baseA + 30720 + boff[tn] + po*4);
            }
            #pragma unroll
            for (int tm = 0; tm < 4; tm++) {
                uint32_t ah[4], al[4];
                ldm_x4(ah, baseA + aoff[tm] + po*4);
                ldm_x4(al, baseA + 10240 + aoff[tm] + po*4);
                #pragma unroll
                for (int tn = 0; tn < 4; tn++) {
                    mma16(acc[tm][tn], ah, bh[tn]);
                    mma16(acc[tm][tn], al, bh[tn]);
                    mma16(acc[tm][tn], ah, bl[tn]);
                }
            }
        }
    }

    #pragma unroll
    for (int tm = 0; tm < 4; tm++) {
        #pragma unroll
        for (int tn = 0; tn < 4; tn++) {
            long row = row0 + wm + tm*16 + gid;
            long col = col0 + wn + tn*8 + tig*2;
            #pragma unroll
            for (int half = 0; half < 2; half++) {
                long r = row + half*8;
                float v0 = acc[tm][tn][half*2+0];
                float v1 = acc[tm][tn][half*2+1];
                if (MODE == 0) {
                    *(__half2*)(Ch + r*ldc + col) = __floats2half2_rn(v0, v1);
                } else {
                    v0 += bias[col]; v1 += bias[col+1];
                    v0 = gelu_f(v0); v1 = gelu_f(v1);
                    if (MODE == 2) {
                        float2 rv = *(const float2*)(resid + r*ldc + col);
                        float2 o; o.x = v0 + rv.x; o.y = v1 + rv.y;
                        *(float2*)(Cf + r*ldc + col) = o;
                    } else {
                        __half2 hv = __floats2half2_rn(v0, v1);
                        float2 hf = __half22float2(hv);
                        __half2 lv = __floats2half2_rn(v0 - hf.x, v1 - hf.y);
                        *(__half2*)(Th + r*ldc + col) = hv;
                        *(__half2*)(Tl + r*ldc + col) = lv;
                    }
                }
            }
        }
    }
}

// ============================================================== S GEMM + exp
__global__ __launch_bounds__(256)
void s_gemm_exp_h(const __half* __restrict__ qkvh, __half* __restrict__ Eo,
                  float* __restrict__ psum)
{
    int z = blockIdx.z, zo = z >> 3, zi = z & 7;
    const __half* A = qkvh + (size_t)zo*Pq*E3      + (size_t)zi*64;  // Q
    const __half* B = qkvh + (size_t)zo*Pq*E3 + Eq + (size_t)zi*64;  // K
    __half* C = Eo + (size_t)z * Pq * Pq;

    extern __shared__ uint32_t sm[];
    uint32_t sb = smem_u32(sm);
    __shared__ float ps[128][2];

    int tid = threadIdx.x, lane = tid & 31, wid = tid >> 5;
    int gid = lane >> 2, tig = lane & 3;
    int wm = (wid >> 2) * 64, wn = (wid & 3) * 32;
    long row0 = (long)blockIdx.y * 128;   // q
    long col0 = (long)blockIdx.x * 128;   // k
    const __half* Ab = A + row0 * E3;
    const __half* Bb = B + col0 * E3;

    uint32_t aoff[4], boff[4];
    #pragma unroll
    for (int tm = 0; tm < 4; tm++)
        aoff[tm] = ((wm + tm*16 + (lane & 15))*20 + (lane >> 4)*4) * 4;
    #pragma unroll
    for (int tn = 0; tn < 4; tn++)
        boff[tn] = ((wn + tn*8 + (lane & 7))*20 + ((lane >> 3) & 1)*4) * 4;

    float acc[4][4][4];
    #pragma unroll
    for (int i = 0; i < 4; i++)
        #pragma unroll
        for (int j = 0; j < 4; j++)
            #pragma unroll
            for (int u = 0; u < 4; u++) acc[i][j][u] = 0.0f;

    {
        #pragma unroll
        for (int j = 0; j < 2; j++) {
            int idx = tid + j*256;
            int row = idx >> 2, q = idx & 3;
            uint32_t d = sb + (row*20 + q*4) * 4;
            CPA(d,         Ab + (long)row*E3 + q*8);
            CPA(d + 10240, Bb + (long)row*E3 + q*8);
        }
        CPCOMMIT();
    }
    #pragma unroll
    for (int t = 0; t < 2; t++) {
        int s = t & 1;
        CPWAIT0();
        __syncthreads();
        if (t == 0) {
            #pragma unroll
            for (int j = 0; j < 2; j++) {
                int idx = tid + j*256;
                int row = idx >> 2, q = idx & 3;
                uint32_t d = sb + 20480 + (row*20 + q*4) * 4;
                CPA(d,         Ab + (long)row*E3 + 32 + q*8);
                CPA(d + 10240, Bb + (long)row*E3 + 32 + q*8);
            }
            CPCOMMIT();
        }
        uint32_t baseA = sb + s * 20480;
        #pragma unroll
        for (int po = 0; po < 16; po += 8) {
            uint32_t bh[4][2];
            #pragma unroll
            for (int tn = 0; tn < 4; tn++)
                ldm_x2(bh[tn], baseA + 10240 + boff[tn] + po*4);
            #pragma unroll
            for (int tm = 0; tm < 4; tm++) {
                uint32_t ah[4];
                ldm_x4(ah, baseA + aoff[tm] + po*4);
                #pragma unroll
                for (int tn = 0; tn < 4; tn++) mma16(acc[tm][tn], ah, bh[tn]);
            }
        }
    }

    const float SC = 0.125f * 1.44269504088896f;
    float cs[4][2];
    #pragma unroll
    for (int tn = 0; tn < 4; tn++) { cs[tn][0] = 0.0f; cs[tn][1] = 0.0f; }
    #pragma unroll
    for (int tm = 0; tm < 4; tm++) {
        #pragma unroll
        for (int half = 0; half < 2; half++) {
            long r = row0 + wm + tm*16 + gid + half*8;
            #pragma unroll
            for (int tn = 0; tn < 4; tn++) {
                float e0 = fexp2f(acc[tm][tn][half*2+0] * SC);
                float e1 = fexp2f(acc[tm][tn][half*2+1] * SC);
                __half2 e2 = __floats2half2_rn(e0, e1);
                long col = col0 + wn + tn*8 + tig*2;
                *(__half2*)(C + r*Pq + col) = e2;
                float2 f = __half22float2(e2);
                cs[tn][0] += f.x; cs[tn][1] += f.y;
            }
        }
    }
    #pragma unroll
    for (int tn = 0; tn < 4; tn++) {
        #pragma unroll
        for (int u = 0; u < 2; u++) {
            float v = cs[tn][u];
            v += __shfl_xor_sync(0xffffffffu, v, 4);
            v += __shfl_xor_sync(0xffffffffu, v, 8);
            v += __shfl_xor_sync(0xffffffffu, v, 16);
            if (gid == 0) ps[wn + tn*8 + tig*2 + u][wid >> 2] = v;
        }
    }
    __syncthreads();
    if (tid < 128) {
        float tot = ps[tid][0] + ps[tid][1];
        psum[((size_t)z*Pq + col0 + tid) * 32 + blockIdx.y] = tot;
    }
}

// ============================================================== combine
__global__ void combine_kernel(const float* __restrict__ psum,
                               float* __restrict__ rinv)
{
    size_t r = (size_t)blockIdx.x * 256 + threadIdx.x;
    const float4* p = (const float4*)(psum + (r << 5));
    float s = 0.0f;
    #pragma unroll
    for (int i = 0; i < 8; i++) {
        float4 v = p[i];
        s += v.x + v.y + v.z + v.w;
    }
    rinv[r] = 1.0f / s;
}

// ============================================================== attention O
// KT=64, 2-stage. E staged raw via cp.async [q][36] (ldmatrix A-fragments);
// V read fp16, scaled by rinv, transposed to [kpair][72] (one STS.128/thread).
__global__ __launch_bounds__(256)
void attn_o_h(const __half* __restrict__ Et, const __half* __restrict__ qkvh,
              float* __restrict__ out1, const float* __restrict__ x,
              const float* __restrict__ rinv)
{
    int z = blockIdx.z, zo = z >> 3, zi = z & 7;
    const __half* Eb = Et   + (size_t)z * Pq * Pq;
    const __half* Vb = qkvh + (size_t)zo * Pq * E3 + 2*Eq + (size_t)zi*64;
    float*        Cb = out1 + (size_t)zo * PE + (size_t)zi*64;
    const float*  Rb = x    + (size_t)zo * PE + (size_t)zi*64;
    const float* riv = rinv + (size_t)z * Pq;

    extern __shared__ uint32_t sm[];   // stage: stP 128*36 + stVT 32*72 = 6912 u32
    uint32_t sb = smem_u32(sm);

    int tid = threadIdx.x, lane = tid & 31, wid = tid >> 5;
    int gid = lane >> 2, tig = lane & 3;
    int wm = (wid >> 2) * 64, wn = (wid & 3) * 16;
    long q0 = (long)blockIdx.y * 128;
    int db = tid & 15, kpb = tid >> 4;

    uint32_t poff[4];
    #pragma unroll
    for (int tm = 0; tm < 4; tm++)
        poff[tm] = ((wm + tm*16 + (lane & 15))*36 + (lane >> 4)*4) * 4;

    float acc[4][2][4];
    #pragma unroll
    for (int i = 0; i < 4; i++)
        #pragma unroll
        for (int j = 0; j < 2; j++)
            #pragma unroll
            for (int u = 0; u < 4; u++) acc[i][j][u] = 0.0f;

    auto load_stage = [&](int s, int k0){
        int so = s * 6912;
        #pragma unroll
        for (int j = 0; j < 4; j++) {
            int idx = tid + j*256;
            int row = idx >> 3, c = idx & 7;
            CPA(sb + (so + row*36 + c*4)*4, Eb + (size_t)(q0 + row) * Pq + k0 + c*8);
        }
        CPCOMMIT();
        #pragma unroll
        for (int kk = 0; kk < 2; kk++) {
            int kp = kpb + kk*16;
            float iv0 = riv[k0 + 2*kp], iv1 = riv[k0 + 2*kp + 1];
            const __half* rp = Vb + (size_t)(k0 + 2*kp) * E3 + db*4;
            uint2 r0 = *(const uint2*)rp;
            uint2 r1 = *(const uint2*)(rp + E3);
            const __half2* h0 = (const __half2*)&r0;
            const __half2* h1 = (const __half2*)&r1;
            float2 a01 = __half22float2(h0[0]), a23 = __half22float2(h0[1]);
            float2 c01 = __half22float2(h1[0]), c23 = __half22float2(h1[1]);
            uint4 w;
            w.x = h2u(__floats2half2_rn(a01.x*iv0, c01.x*iv1));
            w.y = h2u(__floats2half2_rn(a01.y*iv0, c01.y*iv1));
            w.z = h2u(__floats2half2_rn(a23.x*iv0, c23.x*iv1));
            w.w = h2u(__floats2half2_rn(a23.y*iv0, c23.y*iv1));
            *(uint4*)&sm[so + 4608 + kp*72 + db*4] = w;
        }
    };

    load_stage(0, 0);
    for (int t = 0; t < 64; t++) {
        int s = t & 1;
        CPWAIT0();
        __syncthreads();
        if (t < 63) load_stage(1 - s, (t + 1) * 64);
        uint32_t basstP = sb + s * 6912 * 4;
        const uint32_t* stV = sm + s * 6912 + 4608;
        #pragma unroll
        for (int po = 0; po < 32; po += 8) {
            uint32_t b[2][2];
            #pragma unroll
            for (int tn = 0; tn < 2; tn++) {
                int n = wn + tn*8 + gid;
                b[tn][0] = stV[(po + tig)*72 + n];
                b[tn][1] = stV[(po + tig + 4)*72 + n];
            }
            #pragma unroll
            for (int tm = 0; tm < 4; tm++) {
                uint32_t a[4];
                ldm_x4(a, basstP + poff[tm] + po*4);
                #pragma unroll
                for (int tn = 0; tn < 2; tn++)
                    mma16(acc[tm][tn], a, b[tn]);
            }
        }
    }

    #pragma unroll
    for (int tm = 0; tm < 4; tm++) {
        #pragma unroll
        for (int tn = 0; tn < 2; tn++) {
            long q = q0 + wm + tm*16 + gid;
            int  d = wn + tn*8 + tig*2;
            #pragma unroll
            for (int half = 0; half < 2; half++) {
                long r = q + half*8;
                float2 rv = *(const float2*)(Rb + r*Eq + d);
                float2 o;
                o.x = acc[tm][tn][half*2+0] + rv.x;
                o.y = acc[tm][tn][half*2+1] + rv.y;
                *(float2*)(Cb + r*Eq + d) = o;
            }
        }
    }
}

// ============================================================== launcher
extern "C" void kernel_launch(void* const* d_in, const int* in_sizes, int n_in,
                              void* d_out, int out_size)
{
    const float* x  = (const float*)d_in[0];
    const float* g1 = (const float*)d_in[1];
    const float* b1 = (const float*)d_in[2];
    const float* W1 = (const float*)d_in[3];
    const float* g2 = (const float*)d_in[4];
    const float* b2 = (const float*)d_in[5];
    const float* Wa = (const float*)d_in[6];
    const float* ba = (const float*)d_in[7];
    const float* Wb = (const float*)d_in[8];
    const float* bb = (const float*)d_in[9];
    float* out = (float*)d_out;

    __half *hh, *hl, *W1h, *W1l, *Wah, *Wal, *Wbh, *Wbl, *qkvh, *th, *tl, *E;
    float *out1, *riv, *psm;
    cudaGetSymbolAddress((void**)&hh,   g_hh);
    cudaGetSymbolAddress((void**)&hl,   g_hl);
    cudaGetSymbolAddress((void**)&W1h,  g_W1h);
    cudaGetSymbolAddress((void**)&W1l,  g_W1l);
    cudaGetSymbolAddress((void**)&Wah,  g_Wah);
    cudaGetSymbolAddress((void**)&Wal,  g_Wal);
    cudaGetSymbolAddress((void**)&Wbh,  g_Wbh);
    cudaGetSymbolAddress((void**)&Wbl,  g_Wbl);
    cudaGetSymbolAddress((void**)&qkvh, g_qkvh);
    cudaGetSymbolAddress((void**)&th,   g_th);
    cudaGetSymbolAddress((void**)&tl,   g_tl);
    cudaGetSymbolAddress((void**)&E,    g_E);
    cudaGetSymbolAddress((void**)&out1, g_out1);
    cudaGetSymbolAddress((void**)&riv,  g_rinv);
    cudaGetSymbolAddress((void**)&psm,  g_psum);

    const int SM_GEMM = 2 * 10240 * 4;
    const int SM_S    = 2 * 5120 * 4;
    const int SM_AO   = 2 * 6912 * 4;
    cudaFuncSetAttribute(gemm_fp16<0>, cudaFuncAttributeMaxDynamicSharedMemorySize, SM_GEMM);
    cudaFuncSetAttribute(gemm_fp16<1>, cudaFuncAttributeMaxDynamicSharedMemorySize, SM_GEMM);
    cudaFuncSetAttribute(gemm_fp16<2>, cudaFuncAttributeMaxDynamicSharedMemorySize, SM_GEMM);
    cudaFuncSetAttribute(s_gemm_exp_h, cudaFuncAttributeMaxDynamicSharedMemorySize, SM_S);
    cudaFuncSetAttribute(attn_o_h,     cudaFuncAttributeMaxDynamicSharedMemorySize, SM_AO);

    const int W_N4 = (E3 * Eq) / 4;

    cvt_split<<<(W_N4 + 255)/256, 256>>>(W1, W1h, W1l, W_N4);
    cvt_split<<<(W_N4 + 255)/256, 256>>>(Wa, Wah, Wal, W_N4);
    cvt_split<<<(W_N4 + 255)/256, 256>>>(Wb, Wbh, Wbl, W_N4);

    // LN1
    ln_reduce_kernel<<<dim3(NB_RED, Bq), 256>>>(x);
    ln_final_kernel<<<Bq, 256>>>();
    ln_apply_split<<<(Bq*PE/4 + 255)/256, 256>>>(x, g1, b1, hh, hl);

    // QKV (fp16 out only)
    gemm_fp16<0><<<dim3(E3/128, (Bq*Pq)/128, 1), 256, SM_GEMM>>>(
        hh, hl, W1h, W1l, Eq, Eq, Eq, E3,
        (float*)0, qkvh, (__half*)0, (__half*)0, (const float*)0, (const float*)0);

    // E + column partials
    s_gemm_exp_h<<<dim3(Pq/128, Pq/128, Bq*Hq), 256, SM_S>>>(qkvh, E, psm);

    combine_kernel<<<(Bq*Hq*Pq)/256, 256>>>(psm, riv);

    // out1 = x + E (rinv*V)
    attn_o_h<<<dim3(1, Pq/128, Bq*Hq), 256, SM_AO>>>(E, qkvh, out1, x, riv);

    // LN2
    ln_reduce_kernel<<<dim3(NB_RED, Bq), 256>>>(out1);
    ln_final_kernel<<<Bq, 256>>>();
    ln_apply_split<<<(Bq*PE/4 + 255)/256, 256>>>(out1, g2, b2, hh, hl);

    // MLP1
    gemm_fp16<1><<<dim3(E3/128, (Bq*Pq)/128, 1), 256, SM_GEMM>>>(
        hh, hl, Wah, Wal, Eq, Eq, Eq, E3,
        (float*)0, (__half*)0, th, tl, ba, (const float*)0);

    // MLP2
    gemm_fp16<2><<<dim3(Eq/128, (Bq*Pq)/128, 1), 256, SM_GEMM>>>(
        th, tl, Wbh, Wbl, E3, E3, E3, Eq,
        out, (__half*)0, (__half*)0, (__half*)0, bb, out1);
}

// round 13
// speedup vs baseline: 3.6108x; 1.1202x over previous
#include <cuda_runtime.h>
#include <cuda_fp16.h>
#include <math.h>
#include <stdint.h>

#define Bq 2
#define Pq 4096
#define Eq 512
#define Hq 8
#define E3 1536
#define PE (Pq*Eq)
#define NB_RED 256

// ------------------------------------------------------------- scratch
__device__ __align__(16) __half g_hh [(size_t)Bq*Pq*Eq];
__device__ __align__(16) __half g_hl [(size_t)Bq*Pq*Eq];
__device__ __align__(16) __half g_W1h[(size_t)E3*Eq];
__device__ __align__(16) __half g_Wah[(size_t)E3*Eq];
__device__ __align__(16) __half g_Wbh[(size_t)Eq*E3];
__device__ __align__(16) __half g_qkvh[(size_t)Bq*Pq*E3];
__device__ __align__(16) __half g_th [(size_t)Bq*Pq*E3];
__device__ __align__(16) __half g_tl [(size_t)Bq*Pq*E3];
__device__ __align__(16) __half g_E  [(size_t)Bq*Hq*Pq*Pq];
__device__ float  g_out1[(size_t)Bq*Pq*Eq];
__device__ float  g_rinv[(size_t)Bq*Hq*Pq];
__device__ float  g_psum[(size_t)Bq*Hq*Pq*32];
__device__ double g_part[Bq*NB_RED*2];
__device__ float  g_stats[Bq*2];

// ------------------------------------------------------------- helpers
__device__ __forceinline__ uint32_t smem_u32(const void* p){
    uint32_t a;
    asm("{ .reg .u64 t; cvta.to.shared.u64 t, %1; cvt.u32.u64 %0, t; }"
        : "=r"(a) : "l"(p));
    return a;
}
__device__ __forceinline__ uint32_t h2u(__half2 h){ return *reinterpret_cast<uint32_t*>(&h); }
__device__ __forceinline__ void splith4(float4 v, uint2& hi, uint2& lo){
    __half2 h01 = __floats2half2_rn(v.x, v.y);
    __half2 h23 = __floats2half2_rn(v.z, v.w);
    float2 f01 = __half22float2(h01);
    float2 f23 = __half22float2(h23);
    __half2 l01 = __floats2half2_rn(v.x - f01.x, v.y - f01.y);
    __half2 l23 = __floats2half2_rn(v.z - f23.x, v.w - f23.y);
    hi = make_uint2(h2u(h01), h2u(h23));
    lo = make_uint2(h2u(l01), h2u(l23));
}
__device__ __forceinline__ void mma16(float d[4], const uint32_t a[4], const uint32_t b[2]){
    asm volatile(
        "mma.sync.aligned.m16n8k16.row.col.f32.f16.f16.f32 "
        "{%0,%1,%2,%3}, {%4,%5,%6,%7}, {%8,%9}, {%0,%1,%2,%3};"
        : "+f"(d[0]), "+f"(d[1]), "+f"(d[2]), "+f"(d[3])
        : "r"(a[0]), "r"(a[1]), "r"(a[2]), "r"(a[3]), "r"(b[0]), "r"(b[1]));
}
__device__ __forceinline__ void ldm_x4(uint32_t r[4], uint32_t addr){
    asm volatile("ldmatrix.sync.aligned.m8n8.x4.shared.b16 {%0,%1,%2,%3}, [%4];"
        : "=r"(r[0]), "=r"(r[1]), "=r"(r[2]), "=r"(r[3]) : "r"(addr));
}
__device__ __forceinline__ void ldm_x2(uint32_t r[2], uint32_t addr){
    asm volatile("ldmatrix.sync.aligned.m8n8.x2.shared.b16 {%0,%1}, [%2];"
        : "=r"(r[0]), "=r"(r[1]) : "r"(addr));
}
__device__ __forceinline__ float gelu_f(float v){
    return 0.5f * v * (1.0f + erff(v * 0.70710678118654752440f));
}
// 2^y on the FMA/ALU pipes. |rel err| ~4e-5, below fp16 rounding.
__device__ __forceinline__ float fexp2f(float y){
    y = fmaxf(y, -100.0f);
    float t = y + 12582912.0f;
    int   e = __float_as_int(t) - 0x4B400000;
    float r = t - 12582912.0f;
    float f = y - r;
    float p = 1.3333558e-3f;
    p = fmaf(p, f, 9.6181291e-3f);
    p = fmaf(p, f, 5.5504109e-2f);
    p = fmaf(p, f, 2.4022651e-1f);
    p = fmaf(p, f, 6.9314718e-1f);
    p = fmaf(p, f, 1.0f);
    return __int_as_float((e + 127) << 23) * p;
}
#define CPA(dst, src) \
    asm volatile("cp.async.cg.shared.global [%0], [%1], 16;" :: "r"(dst), "l"(src))
#define CPCOMMIT() asm volatile("cp.async.commit_group;" ::: "memory")
#define CPWAIT0()  asm volatile("cp.async.wait_group 0;"  ::: "memory")

// ============================================================== LayerNorm
__global__ void ln_reduce_kernel(const float* __restrict__ x)
{
    int b = blockIdx.y;
    const float4* xb = (const float4*)(x + (size_t)b * PE);
    int base = blockIdx.x * blockDim.x + threadIdx.x;
    float s = 0.0f, s2 = 0.0f;
    #pragma unroll
    for (int j = 0; j < 8; j++) {
        float4 v = xb[base + j * (NB_RED * 256)];
        s += (v.x + v.y) + (v.z + v.w);
        s2 = fmaf(v.x, v.x, s2); s2 = fmaf(v.y, v.y, s2);
        s2 = fmaf(v.z, v.z, s2); s2 = fmaf(v.w, v.w, s2);
    }
    __shared__ double ss[256], ss2[256];
    int t = threadIdx.x;
    ss[t] = (double)s; ss2[t] = (double)s2;
    __syncthreads();
    for (int o = 128; o > 0; o >>= 1) {
        if (t < o) { ss[t] += ss[t+o]; ss2[t] += ss2[t+o]; }
        __syncthreads();
    }
    if (t == 0) {
        g_part[(b*NB_RED + blockIdx.x)*2 + 0] = ss[0];
        g_part[(b*NB_RED + blockIdx.x)*2 + 1] = ss2[0];
    }
}

__global__ void ln_final_kernel()
{
    int b = blockIdx.x, t = threadIdx.x;
    __shared__ double ss[256], ss2[256];
    ss[t]  = g_part[(b*NB_RED + t)*2 + 0];
    ss2[t] = g_part[(b*NB_RED + t)*2 + 1];
    __syncthreads();
    for (int o = 128; o > 0; o >>= 1) {
        if (t < o) { ss[t] += ss[t+o]; ss2[t] += ss2[t+o]; }
        __syncthreads();
    }
    if (t == 0) {
        double mean = ss[0] / (double)PE;
        double var  = ss2[0] / (double)PE - mean * mean;
        g_stats[b*2 + 0] = (float)mean;
        g_stats[b*2 + 1] = (float)(1.0 / sqrt(var + 1e-5));
    }
}

__global__ void ln_apply_split(const float* __restrict__ x,
                               const float* __restrict__ gam,
                               const float* __restrict__ bet,
                               __half* __restrict__ hh, __half* __restrict__ hl)
{
    const int n4 = PE / 4;
    int i = blockIdx.x * blockDim.x + threadIdx.x;
    if (i >= Bq * n4) return;
    int b = i / n4, pe = i - b * n4;
    float mean = g_stats[b*2 + 0], inv = g_stats[b*2 + 1];
    float4 xv = ((const float4*)x)[i];
    float4 gv = ((const float4*)gam)[pe];
    float4 bv = ((const float4*)bet)[pe];
    float4 o;
    o.x = (xv.x - mean) * inv * gv.x + bv.x;
    o.y = (xv.y - mean) * inv * gv.y + bv.y;
    o.z = (xv.z - mean) * inv * gv.z + bv.z;
    o.w = (xv.w - mean) * inv * gv.w + bv.w;
    uint2 h, l;
    splith4(o, h, l);
    ((uint2*)hh)[i] = h;
    ((uint2*)hl)[i] = l;
}

// float -> fp16 (weights, hi only)
__global__ void cvt_h(const float* __restrict__ src, __half* __restrict__ hi, int n4)
{
    int i = blockIdx.x * blockDim.x + threadIdx.x;
    if (i >= n4) return;
    float4 v = ((const float4*)src)[i];
    uint2 h;
    h.x = h2u(__floats2half2_rn(v.x, v.y));
    h.y = h2u(__floats2half2_rn(v.z, v.w));
    ((uint2*)hi)[i] = h;
}

// ============================================================== fp16 2-term GEMM
// C[m,n] = sum_k (A_hi+A_lo)[m,k] * B_hi[n,k]  (+bias, +gelu, +resid).
// MODE 0: fp16 C (QKV); MODE 1: bias+gelu -> hi/lo (MLP1);
// MODE 2: bias+gelu+resid -> float (MLP2). cp.async 2-stage + ldmatrix.
// Stage = 3 planes (Ah, Al, Bh) x 10240 B.
template<int MODE>
__global__ __launch_bounds__(256)
void gemm_fp16(const __half* __restrict__ Ahh, const __half* __restrict__ Alo,
               const __half* __restrict__ Bhh,
               int K, int lda, int ldb, int ldc,
               float* __restrict__ Cf, __half* __restrict__ Ch,
               __half* __restrict__ Th, __half* __restrict__ Tl,
               const float* __restrict__ bias, const float* __restrict__ resid)
{
    extern __shared__ uint32_t sm[];
    uint32_t sb = smem_u32(sm);
    int tid = threadIdx.x, lane = tid & 31, wid = tid >> 5;
    int gid = lane >> 2, tig = lane & 3;
    int wm = (wid >> 2) * 64, wn = (wid & 3) * 32;
    long row0 = (long)blockIdx.y * 128, col0 = (long)blockIdx.x * 128;
    const __half* A0 = Ahh + row0 * lda;
    const __half* A1 = Alo + row0 * lda;
    const __half* B0 = Bhh + col0 * ldb;

    uint32_t aoff[4], boff[4];
    #pragma unroll
    for (int tm = 0; tm < 4; tm++)
        aoff[tm] = ((wm + tm*16 + (lane & 15))*20 + (lane >> 4)*4) * 4;
    #pragma unroll
    for (int tn = 0; tn < 4; tn++)
        boff[tn] = ((wn + tn*8 + (lane & 7))*20 + ((lane >> 3) & 1)*4) * 4;

    float acc[4][4][4];
    #pragma unroll
    for (int i = 0; i < 4; i++)
        #pragma unroll
        for (int j = 0; j < 4; j++)
            #pragma unroll
            for (int u = 0; u < 4; u++) acc[i][j][u] = 0.0f;

    const int T = K >> 5;
    {
        #pragma unroll
        for (int j = 0; j < 2; j++) {
            int idx = tid + j*256;
            int row = idx >> 2, q = idx & 3;
            uint32_t d = sb + (row*20 + q*4) * 4;
            long ao = (long)row * lda + q*8;
            long bo = (long)row * ldb + q*8;
            CPA(d,           A0 + ao);
            CPA(d + 10240,   A1 + ao);
            CPA(d + 20480,   B0 + bo);
        }
        CPCOMMIT();
    }

    for (int t = 0; t < T; t++) {
        int s = t & 1;
        CPWAIT0();
        __syncthreads();
        if (t + 1 < T) {
            int kt = (t + 1) << 5;
            int so = (1 - s) * 30720;
            #pragma unroll
            for (int j = 0; j < 2; j++) {
                int idx = tid + j*256;
                int row = idx >> 2, q = idx & 3;
                uint32_t d = sb + so + (row*20 + q*4) * 4;
                long ao = (long)row * lda + kt + q*8;
                long bo = (long)row * ldb + kt + q*8;
                CPA(d,           A0 + ao);
                CPA(d + 10240,   A1 + ao);
                CPA(d + 20480,   B0 + bo);
            }
            CPCOMMIT();
        }
        uint32_t baseA = sb + s * 30720;
        #pragma unroll
        for (int po = 0; po < 16; po += 8) {
            uint32_t bh[4][2];
            #pragma unroll
            for (int tn = 0; tn < 4; tn++)
                ldm_x2(bh[tn], baseA + 20480 + boff[tn] + po*4);
            #pragma unroll
            for (int tm = 0; tm < 4; tm++) {
                uint32_t ah[4], al[4];
                ldm_x4(ah, baseA + aoff[tm] + po*4);
                ldm_x4(al, baseA + 10240 + aoff[tm] + po*4);
                #pragma unroll
                for (int tn = 0; tn < 4; tn++) {
                    mma16(acc[tm][tn], ah, bh[tn]);
                    mma16(acc[tm][tn], al, bh[tn]);
                }
            }
        }
    }

    #pragma unroll
    for (int tm = 0; tm < 4; tm++) {
        #pragma unroll
        for (int tn = 0; tn < 4; tn++) {
            long row = row0 + wm + tm*16 + gid;
            long col = col0 + wn + tn*8 + tig*2;
            #pragma unroll
            for (int half = 0; half < 2; half++) {
                long r = row + half*8;
                float v0 = acc[tm][tn][half*2+0];
                float v1 = acc[tm][tn][half*2+1];
                if (MODE == 0) {
                    *(__half2*)(Ch + r*ldc + col) = __floats2half2_rn(v0, v1);
                } else {
                    v0 += bias[col]; v1 += bias[col+1];
                    v0 = gelu_f(v0); v1 = gelu_f(v1);
                    if (MODE == 2) {
                        float2 rv = *(const float2*)(resid + r*ldc + col);
                        float2 o; o.x = v0 + rv.x; o.y = v1 + rv.y;
                        *(float2*)(Cf + r*ldc + col) = o;
                    } else {
                        __half2 hv = __floats2half2_rn(v0, v1);
                        float2 hf = __half22float2(hv);
                        __half2 lv = __floats2half2_rn(v0 - hf.x, v1 - hf.y);
                        *(__half2*)(Th + r*ldc + col) = hv;
                        *(__half2*)(Tl + r*ldc + col) = lv;
                    }
                }
            }
        }
    }
}

// ============================================================== S GEMM + exp
__global__ __launch_bounds__(256)
void s_gemm_exp_h(const __half* __restrict__ qkvh, __half* __restrict__ Eo,
                  float* __restrict__ psum)
{
    int z = blockIdx.z, zo = z >> 3, zi = z & 7;
    const __half* A = qkvh + (size_t)zo*Pq*E3      + (size_t)zi*64;  // Q
    const __half* B = qkvh + (size_t)zo*Pq*E3 + Eq + (size_t)zi*64;  // K
    __half* C = Eo + (size_t)z * Pq * Pq;

    extern __shared__ uint32_t sm[];
    uint32_t sb = smem_u32(sm);
    __shared__ float ps[128][2];

    int tid = threadIdx.x, lane = tid & 31, wid = tid >> 5;
    int gid = lane >> 2, tig = lane & 3;
    int wm = (wid >> 2) * 64, wn = (wid & 3) * 32;
    long row0 = (long)blockIdx.y * 128;   // q
    long col0 = (long)blockIdx.x * 128;   // k
    const __half* Ab = A + row0 * E3;
    const __half* Bb = B + col0 * E3;

    uint32_t aoff[4], boff[4];
    #pragma unroll
    for (int tm = 0; tm < 4; tm++)
        aoff[tm] = ((wm + tm*16 + (lane & 15))*20 + (lane >> 4)*4) * 4;
    #pragma unroll
    for (int tn = 0; tn < 4; tn++)
        boff[tn] = ((wn + tn*8 + (lane & 7))*20 + ((lane >> 3) & 1)*4) * 4;

    float acc[4][4][4];
    #pragma unroll
    for (int i = 0; i < 4; i++)
        #pragma unroll
        for (int j = 0; j < 4; j++)
            #pragma unroll
            for (int u = 0; u < 4; u++) acc[i][j][u] = 0.0f;

    {
        #pragma unroll
        for (int j = 0; j < 2; j++) {
            int idx = tid + j*256;
            int row = idx >> 2, q = idx & 3;
            uint32_t d = sb + (row*20 + q*4) * 4;
            CPA(d,         Ab + (long)row*E3 + q*8);
            CPA(d + 10240, Bb + (long)row*E3 + q*8);
        }
        CPCOMMIT();
    }
    #pragma unroll
    for (int t = 0; t < 2; t++) {
        int s = t & 1;
        CPWAIT0();
        __syncthreads();
        if (t == 0) {
            #pragma unroll
            for (int j = 0; j < 2; j++) {
                int idx = tid + j*256;
                int row = idx >> 2, q = idx & 3;
                uint32_t d = sb + 20480 + (row*20 + q*4) * 4;
                CPA(d,         Ab + (long)row*E3 + 32 + q*8);
                CPA(d + 10240, Bb + (long)row*E3 + 32 + q*8);
            }
            CPCOMMIT();
        }
        uint32_t baseA = sb + s * 20480;
        #pragma unroll
        for (int po = 0; po < 16; po += 8) {
            uint32_t bh[4][2];
            #pragma unroll
            for (int tn = 0; tn < 4; tn++)
                ldm_x2(bh[tn], baseA + 10240 + boff[tn] + po*4);
            #pragma unroll
            for (int tm = 0; tm < 4; tm++) {
                uint32_t ah[4];
                ldm_x4(ah, baseA + aoff[tm] + po*4);
                #pragma unroll
                for (int tn = 0; tn < 4; tn++) mma16(acc[tm][tn], ah, bh[tn]);
            }
        }
    }

    const float SC = 0.125f * 1.44269504088896f;
    float cs[4][2];
    #pragma unroll
    for (int tn = 0; tn < 4; tn++) { cs[tn][0] = 0.0f; cs[tn][1] = 0.0f; }
    #pragma unroll
    for (int tm = 0; tm < 4; tm++) {
        #pragma unroll
        for (int half = 0; half < 2; half++) {
            long r = row0 + wm + tm*16 + gid + half*8;
            #pragma unroll
            for (int tn = 0; tn < 4; tn++) {
                float e0 = fexp2f(acc[tm][tn][half*2+0] * SC);
                float e1 = fexp2f(acc[tm][tn][half*2+1] * SC);
                __half2 e2 = __floats2half2_rn(e0, e1);
                long col = col0 + wn + tn*8 + tig*2;
                *(__half2*)(C + r*Pq + col) = e2;
                float2 f = __half22float2(e2);
                cs[tn][0] += f.x; cs[tn][1] += f.y;
            }
        }
    }
    #pragma unroll
    for (int tn = 0; tn < 4; tn++) {
        #pragma unroll
        for (int u = 0; u < 2; u++) {
            float v = cs[tn][u];
            v += __shfl_xor_sync(0xffffffffu, v, 4);
            v += __shfl_xor_sync(0xffffffffu, v, 8);
            v += __shfl_xor_sync(0xffffffffu, v, 16);
            if (gid == 0) ps[wn + tn*8 + tig*2 + u][wid >> 2] = v;
        }
    }
    __syncthreads();
    if (tid < 128) {
        float tot = ps[tid][0] + ps[tid][1];
        psum[((size_t)z*Pq + col0 + tid) * 32 + blockIdx.y] = tot;
    }
}

// ============================================================== combine
__global__ void combine_kernel(const float* __restrict__ psum,
                               float* __restrict__ rinv)
{
    size_t r = (size_t)blockIdx.x * 256 + threadIdx.x;
    const float4* p = (const float4*)(psum + (r << 5));
    float s = 0.0f;
    #pragma unroll
    for (int i = 0; i < 8; i++) {
        float4 v = p[i];
        s += v.x + v.y + v.z + v.w;
    }
    rinv[r] = 1.0f / s;
}

// ============================================================== attention O
__global__ __launch_bounds__(256)
void attn_o_h(const __half* __restrict__ Et, const __half* __restrict__ qkvh,
              float* __restrict__ out1, const float* __restrict__ x,
              const float* __restrict__ rinv)
{
    int z = blockIdx.z, zo = z >> 3, zi = z & 7;
    const __half* Eb = Et   + (size_t)z * Pq * Pq;
    const __half* Vb = qkvh + (size_t)zo * Pq * E3 + 2*Eq + (size_t)zi*64;
    float*        Cb = out1 + (size_t)zo * PE + (size_t)zi*64;
    const float*  Rb = x    + (size_t)zo * PE + (size_t)zi*64;
    const float* riv = rinv + (size_t)z * Pq;

    extern __shared__ uint32_t sm[];
    uint32_t sb = smem_u32(sm);

    int tid = threadIdx.x, lane = tid & 31, wid = tid >> 5;
    int gid = lane >> 2, tig = lane & 3;
    int wm = (wid >> 2) * 64, wn = (wid & 3) * 16;
    long q0 = (long)blockIdx.y * 128;
    int db = tid & 15, kpb = tid >> 4;

    uint32_t poff[4];
    #pragma unroll
    for (int tm = 0; tm < 4; tm++)
        poff[tm] = ((wm + tm*16 + (lane & 15))*36 + (lane >> 4)*4) * 4;

    float acc[4][2][4];
    #pragma unroll
    for (int i = 0; i < 4; i++)
        #pragma unroll
        for (int j = 0; j < 2; j++)
            #pragma unroll
            for (int u = 0; u < 4; u++) acc[i][j][u] = 0.0f;

    auto load_stage = [&](int s, int k0){
        int so = s * 6912;
        #pragma unroll
        for (int j = 0; j < 4; j++) {
            int idx = tid + j*256;
            int row = idx >> 3, c = idx & 7;
            CPA(sb + (so + row*36 + c*4)*4, Eb + (size_t)(q0 + row) * Pq + k0 + c*8);
        }
        CPCOMMIT();
        #pragma unroll
        for (int kk = 0; kk < 2; kk++) {
            int kp = kpb + kk*16;
            float iv0 = riv[k0 + 2*kp], iv1 = riv[k0 + 2*kp + 1];
            const __half* rp = Vb + (size_t)(k0 + 2*kp) * E3 + db*4;
            uint2 r0 = *(const uint2*)rp;
            uint2 r1 = *(const uint2*)(rp + E3);
            const __half2* h0 = (const __half2*)&r0;
            const __half2* h1 = (const __half2*)&r1;
            float2 a01 = __half22float2(h0[0]), a23 = __half22float2(h0[1]);
            float2 c01 = __half22float2(h1[0]), c23 = __half22float2(h1[1]);
            uint4 w;
            w.x = h2u(__floats2half2_rn(a01.x*iv0, c01.x*iv1));
            w.y = h2u(__floats2half2_rn(a01.y*iv0, c01.y*iv1));
            w.z = h2u(__floats2half2_rn(a23.x*iv0, c23.x*iv1));
            w.w = h2u(__floats2half2_rn(a23.y*iv0, c23.y*iv1));
            *(uint4*)&sm[so + 4608 + kp*72 + db*4] = w;
        }
    };

    load_stage(0, 0);
    for (int t = 0; t < 64; t++) {
        int s = t & 1;
        CPWAIT0();
        __syncthreads();
        if (t < 63) load_stage(1 - s, (t + 1) * 64);
        uint32_t basstP = sb + s * 6912 * 4;
        const uint32_t* stV = sm + s * 6912 + 4608;
        #pragma unroll
        for (int po = 0; po < 32; po += 8) {
            uint32_t b[2][2];
            #pragma unroll
            for (int tn = 0; tn < 2; tn++) {
                int n = wn + tn*8 + gid;
                b[tn][0] = stV[(po + tig)*72 + n];
                b[tn][1] = stV[(po + tig + 4)*72 + n];
            }
            #pragma unroll
            for (int tm = 0; tm < 4; tm++) {
                uint32_t a[4];
                ldm_x4(a, basstP + poff[tm] + po*4);
                #pragma unroll
                for (int tn = 0; tn < 2; tn++)
                    mma16(acc[tm][tn], a, b[tn]);
            }
        }
    }

    #pragma unroll
    for (int tm = 0; tm < 4; tm++) {
        #pragma unroll
        for (int tn = 0; tn < 2; tn++) {
            long q = q0 + wm + tm*16 + gid;
            int  d = wn + tn*8 + tig*2;
            #pragma unroll
            for (int half = 0; half < 2; half++) {
                long r = q + half*8;
                float2 rv = *(const float2*)(Rb + r*Eq + d);
                float2 o;
                o.x = acc[tm][tn][half*2+0] + rv.x;
                o.y = acc[tm][tn][half*2+1] + rv.y;
                *(float2*)(Cb + r*Eq + d) = o;
            }
        }
    }
}

// ============================================================== launcher
extern "C" void kernel_launch(void* const* d_in, const int* in_sizes, int n_in,
                              void* d_out, int out_size)
{
    const float* x  = (const float*)d_in[0];
    const float* g1 = (const float*)d_in[1];
    const float* b1 = (const float*)d_in[2];
    const float* W1 = (const float*)d_in[3];
    const float* g2 = (const float*)d_in[4];
    const float* b2 = (const float*)d_in[5];
    const float* Wa = (const float*)d_in[6];
    const float* ba = (const float*)d_in[7];
    const float* Wb = (const float*)d_in[8];
    const float* bb = (const float*)d_in[9];
    float* out = (float*)d_out;

    __half *hh, *hl, *W1h, *Wah, *Wbh, *qkvh, *th, *tl, *E;
    float *out1, *riv, *psm;
    cudaGetSymbolAddress((void**)&hh,   g_hh);
    cudaGetSymbolAddress((void**)&hl,   g_hl);
    cudaGetSymbolAddress((void**)&W1h,  g_W1h);
    cudaGetSymbolAddress((void**)&Wah,  g_Wah);
    cudaGetSymbolAddress((void**)&Wbh,  g_Wbh);
    cudaGetSymbolAddress((void**)&qkvh, g_qkvh);
    cudaGetSymbolAddress((void**)&th,   g_th);
    cudaGetSymbolAddress((void**)&tl,   g_tl);
    cudaGetSymbolAddress((void**)&E,    g_E);
    cudaGetSymbolAddress((void**)&out1, g_out1);
    cudaGetSymbolAddress((void**)&riv,  g_rinv);
    cudaGetSymbolAddress((void**)&psm,  g_psum);

    const int SM_GEMM = 2 * 7680 * 4;    // 61440 B (3 planes/stage)
    const int SM_S    = 2 * 5120 * 4;
    const int SM_AO   = 2 * 6912 * 4;
    cudaFuncSetAttribute(gemm_fp16<0>, cudaFuncAttributeMaxDynamicSharedMemorySize, SM_GEMM);
    cudaFuncSetAttribute(gemm_fp16<1>, cudaFuncAttributeMaxDynamicSharedMemorySize, SM_GEMM);
    cudaFuncSetAttribute(gemm_fp16<2>, cudaFuncAttributeMaxDynamicSharedMemorySize, SM_GEMM);
    cudaFuncSetAttribute(s_gemm_exp_h, cudaFuncAttributeMaxDynamicSharedMemorySize, SM_S);
    cudaFuncSetAttribute(attn_o_h,     cudaFuncAttributeMaxDynamicSharedMemorySize, SM_AO);

    const int W_N4 = (E3 * Eq) / 4;

    cvt_h<<<(W_N4 + 255)/256, 256>>>(W1, W1h, W_N4);
    cvt_h<<<(W_N4 + 255)/256, 256>>>(Wa, Wah, W_N4);
    cvt_h<<<(W_N4 + 255)/256, 256>>>(Wb, Wbh, W_N4);

    // LN1
    ln_reduce_kernel<<<dim3(NB_RED, Bq), 256>>>(x);
    ln_final_kernel<<<Bq, 256>>>();
    ln_apply_split<<<(Bq*PE/4 + 255)/256, 256>>>(x, g1, b1, hh, hl);

    // QKV
    gemm_fp16<0><<<dim3(E3/128, (Bq*Pq)/128, 1), 256, SM_GEMM>>>(
        hh, hl, W1h, Eq, Eq, Eq, E3,
        (float*)0, qkvh, (__half*)0, (__half*)0, (const float*)0, (const float*)0);

    // E + column partials
    s_gemm_exp_h<<<dim3(Pq/128, Pq/128, Bq*Hq), 256, SM_S>>>(qkvh, E, psm);

    combine_kernel<<<(Bq*Hq*Pq)/256, 256>>>(psm, riv);

    // out1 = x + E (rinv*V)
    attn_o_h<<<dim3(1, Pq/128, Bq*Hq), 256, SM_AO>>>(E, qkvh, out1, x, riv);

    // LN2
    ln_reduce_kernel<<<dim3(NB_RED, Bq), 256>>>(out1);
    ln_final_kernel<<<Bq, 256>>>();
    ln_apply_split<<<(Bq*PE/4 + 255)/256, 256>>>(out1, g2, b2, hh, hl);

    // MLP1
    gemm_fp16<1><<<dim3(E3/128, (Bq*Pq)/128, 1), 256, SM_GEMM>>>(
        hh, hl, Wah, Eq, Eq, Eq, E3,
        (float*)0, (__half*)0, th, tl, ba, (const float*)0);

    // MLP2
    gemm_fp16<2><<<dim3(Eq/128, (Bq*Pq)/128, 1), 256, SM_GEMM>>>(
        th, tl, Wbh, E3, E3, E3, Eq,
        out, (__half*)0, (__half*)0, (__half*)0, bb, out1);
}

// round 14
// speedup vs baseline: 4.3083x; 1.1932x over previous
#include <cuda_runtime.h>
#include <cuda_fp16.h>
#include <math.h>
#include <stdint.h>

#define Bq 2
#define Pq 4096
#define Eq 512
#define Hq 8
#define E3 1536
#define PE (Pq*Eq)
#define NB_RED 256

// ------------------------------------------------------------- scratch
__device__ __align__(16) __half g_hh [(size_t)Bq*Pq*Eq];
__device__ __align__(16) __half g_W1h[(size_t)E3*Eq];
__device__ __align__(16) __half g_Wah[(size_t)E3*Eq];
__device__ __align__(16) __half g_Wbh[(size_t)Eq*E3];
__device__ __align__(16) __half g_qkvh[(size_t)Bq*Pq*E3];
__device__ __align__(16) __half g_th [(size_t)Bq*Pq*E3];
__device__ __align__(16) __half g_E  [(size_t)Bq*Hq*Pq*Pq];
__device__ float  g_out1[(size_t)Bq*Pq*Eq];
__device__ float  g_rinv[(size_t)Bq*Hq*Pq];
__device__ float  g_psum[(size_t)Bq*Hq*Pq*32];
__device__ double g_part[Bq*NB_RED*2];
__device__ float  g_stats[Bq*2];

// ------------------------------------------------------------- helpers
__device__ __forceinline__ uint32_t smem_u32(const void* p){
    uint32_t a;
    asm("{ .reg .u64 t; cvta.to.shared.u64 t, %1; cvt.u32.u64 %0, t; }"
        : "=r"(a) : "l"(p));
    return a;
}
__device__ __forceinline__ uint32_t h2u(__half2 h){ return *reinterpret_cast<uint32_t*>(&h); }
__device__ __forceinline__ void mma16(float d[4], const uint32_t a[4], const uint32_t b[2]){
    asm volatile(
        "mma.sync.aligned.m16n8k16.row.col.f32.f16.f16.f32 "
        "{%0,%1,%2,%3}, {%4,%5,%6,%7}, {%8,%9}, {%0,%1,%2,%3};"
        : "+f"(d[0]), "+f"(d[1]), "+f"(d[2]), "+f"(d[3])
        : "r"(a[0]), "r"(a[1]), "r"(a[2]), "r"(a[3]), "r"(b[0]), "r"(b[1]));
}
__device__ __forceinline__ void ldm_x4(uint32_t r[4], uint32_t addr){
    asm volatile("ldmatrix.sync.aligned.m8n8.x4.shared.b16 {%0,%1,%2,%3}, [%4];"
        : "=r"(r[0]), "=r"(r[1]), "=r"(r[2]), "=r"(r[3]) : "r"(addr));
}
__device__ __forceinline__ void ldm_x2(uint32_t r[2], uint32_t addr){
    asm volatile("ldmatrix.sync.aligned.m8n8.x2.shared.b16 {%0,%1}, [%2];"
        : "=r"(r[0]), "=r"(r[1]) : "r"(addr));
}
__device__ __forceinline__ float gelu_f(float v){
    return 0.5f * v * (1.0f + erff(v * 0.70710678118654752440f));
}
// 2^y on the FMA/ALU pipes. |rel err| ~4e-5, below fp16 rounding.
__device__ __forceinline__ float fexp2f(float y){
    y = fmaxf(y, -100.0f);
    float t = y + 12582912.0f;
    int   e = __float_as_int(t) - 0x4B400000;
    float r = t - 12582912.0f;
    float f = y - r;
    float p = 1.3333558e-3f;
    p = fmaf(p, f, 9.6181291e-3f);
    p = fmaf(p, f, 5.5504109e-2f);
    p = fmaf(p, f, 2.4022651e-1f);
    p = fmaf(p, f, 6.9314718e-1f);
    p = fmaf(p, f, 1.0f);
    return __int_as_float((e + 127) << 23) * p;
}
#define CPA(dst, src) \
    asm volatile("cp.async.cg.shared.global [%0], [%1], 16;" :: "r"(dst), "l"(src))
#define CPCOMMIT() asm volatile("cp.async.commit_group;" ::: "memory")
#define CPWAIT0()  asm volatile("cp.async.wait_group 0;"  ::: "memory")

// ============================================================== LayerNorm
__global__ void ln_reduce_kernel(const float* __restrict__ x)
{
    int b = blockIdx.y;
    const float4* xb = (const float4*)(x + (size_t)b * PE);
    int base = blockIdx.x * blockDim.x + threadIdx.x;
    float s = 0.0f, s2 = 0.0f;
    #pragma unroll
    for (int j = 0; j < 8; j++) {
        float4 v = xb[base + j * (NB_RED * 256)];
        s += (v.x + v.y) + (v.z + v.w);
        s2 = fmaf(v.x, v.x, s2); s2 = fmaf(v.y, v.y, s2);
        s2 = fmaf(v.z, v.z, s2); s2 = fmaf(v.w, v.w, s2);
    }
    __shared__ double ss[256], ss2[256];
    int t = threadIdx.x;
    ss[t] = (double)s; ss2[t] = (double)s2;
    __syncthreads();
    for (int o = 128; o > 0; o >>= 1) {
        if (t < o) { ss[t] += ss[t+o]; ss2[t] += ss2[t+o]; }
        __syncthreads();
    }
    if (t == 0) {
        g_part[(b*NB_RED + blockIdx.x)*2 + 0] = ss[0];
        g_part[(b*NB_RED + blockIdx.x)*2 + 1] = ss2[0];
    }
}

__global__ void ln_final_kernel()
{
    int b = blockIdx.x, t = threadIdx.x;
    __shared__ double ss[256], ss2[256];
    ss[t]  = g_part[(b*NB_RED + t)*2 + 0];
    ss2[t] = g_part[(b*NB_RED + t)*2 + 1];
    __syncthreads();
    for (int o = 128; o > 0; o >>= 1) {
        if (t < o) { ss[t] += ss[t+o]; ss2[t] += ss2[t+o]; }
        __syncthreads();
    }
    if (t == 0) {
        double mean = ss[0] / (double)PE;
        double var  = ss2[0] / (double)PE - mean * mean;
        g_stats[b*2 + 0] = (float)mean;
        g_stats[b*2 + 1] = (float)(1.0 / sqrt(var + 1e-5));
    }
}

// LN apply -> fp16
__global__ void ln_apply_h(const float* __restrict__ x,
                           const float* __restrict__ gam,
                           const float* __restrict__ bet,
                           __half* __restrict__ hh)
{
    const int n4 = PE / 4;
    int i = blockIdx.x * blockDim.x + threadIdx.x;
    if (i >= Bq * n4) return;
    int b = i / n4, pe = i - b * n4;
    float mean = g_stats[b*2 + 0], inv = g_stats[b*2 + 1];
    float4 xv = ((const float4*)x)[i];
    float4 gv = ((const float4*)gam)[pe];
    float4 bv = ((const float4*)bet)[pe];
    float4 o;
    o.x = (xv.x - mean) * inv * gv.x + bv.x;
    o.y = (xv.y - mean) * inv * gv.y + bv.y;
    o.z = (xv.z - mean) * inv * gv.z + bv.z;
    o.w = (xv.w - mean) * inv * gv.w + bv.w;
    uint2 h;
    h.x = h2u(__floats2half2_rn(o.x, o.y));
    h.y = h2u(__floats2half2_rn(o.z, o.w));
    ((uint2*)hh)[i] = h;
}

// float -> fp16 (weights)
__global__ void cvt_h(const float* __restrict__ src, __half* __restrict__ hi, int n4)
{
    int i = blockIdx.x * blockDim.x + threadIdx.x;
    if (i >= n4) return;
    float4 v = ((const float4*)src)[i];
    uint2 h;
    h.x = h2u(__floats2half2_rn(v.x, v.y));
    h.y = h2u(__floats2half2_rn(v.z, v.w));
    ((uint2*)hi)[i] = h;
}

// ============================================================== fp16 GEMM
// C[m,n] = sum_k A[m,k] B[n,k]  (+bias, +gelu, +resid), plain fp16.
// MODE 0: fp16 C (QKV); MODE 1: bias+gelu -> fp16 (MLP1);
// MODE 2: bias+gelu+resid -> float (MLP2). cp.async 2-stage + ldmatrix.
// Stage = 2 planes (A, B) x 10240 B.
template<int MODE>
__global__ __launch_bounds__(256)
void gemm_fp16(const __half* __restrict__ Ah, const __half* __restrict__ Bh,
               int K, int lda, int ldb, int ldc,
               float* __restrict__ Cf, __half* __restrict__ Ch,
               const float* __restrict__ bias, const float* __restrict__ resid)
{
    extern __shared__ uint32_t sm[];
    uint32_t sb = smem_u32(sm);
    int tid = threadIdx.x, lane = tid & 31, wid = tid >> 5;
    int gid = lane >> 2, tig = lane & 3;
    int wm = (wid >> 2) * 64, wn = (wid & 3) * 32;
    long row0 = (long)blockIdx.y * 128, col0 = (long)blockIdx.x * 128;
    const __half* A0 = Ah + row0 * lda;
    const __half* B0 = Bh + col0 * ldb;

    uint32_t aoff[4], boff[4];
    #pragma unroll
    for (int tm = 0; tm < 4; tm++)
        aoff[tm] = ((wm + tm*16 + (lane & 15))*20 + (lane >> 4)*4) * 4;
    #pragma unroll
    for (int tn = 0; tn < 4; tn++)
        boff[tn] = ((wn + tn*8 + (lane & 7))*20 + ((lane >> 3) & 1)*4) * 4;

    float acc[4][4][4];
    #pragma unroll
    for (int i = 0; i < 4; i++)
        #pragma unroll
        for (int j = 0; j < 4; j++)
            #pragma unroll
            for (int u = 0; u < 4; u++) acc[i][j][u] = 0.0f;

    const int T = K >> 5;
    {
        #pragma unroll
        for (int j = 0; j < 2; j++) {
            int idx = tid + j*256;
            int row = idx >> 2, q = idx & 3;
            uint32_t d = sb + (row*20 + q*4) * 4;
            CPA(d,         A0 + (long)row * lda + q*8);
            CPA(d + 10240, B0 + (long)row * ldb + q*8);
        }
        CPCOMMIT();
    }

    for (int t = 0; t < T; t++) {
        int s = t & 1;
        CPWAIT0();
        __syncthreads();
        if (t + 1 < T) {
            int kt = (t + 1) << 5;
            int so = (1 - s) * 20480;
            #pragma unroll
            for (int j = 0; j < 2; j++) {
                int idx = tid + j*256;
                int row = idx >> 2, q = idx & 3;
                uint32_t d = sb + so + (row*20 + q*4) * 4;
                CPA(d,         A0 + (long)row * lda + kt + q*8);
                CPA(d + 10240, B0 + (long)row * ldb + kt + q*8);
            }
            CPCOMMIT();
        }
        uint32_t baseA = sb + s * 20480;
        #pragma unroll
        for (int po = 0; po < 16; po += 8) {
            uint32_t bh[4][2];
            #pragma unroll
            for (int tn = 0; tn < 4; tn++)
                ldm_x2(bh[tn], baseA + 10240 + boff[tn] + po*4);
            #pragma unroll
            for (int tm = 0; tm < 4; tm++) {
                uint32_t ah[4];
                ldm_x4(ah, baseA + aoff[tm] + po*4);
                #pragma unroll
                for (int tn = 0; tn < 4; tn++)
                    mma16(acc[tm][tn], ah, bh[tn]);
            }
        }
    }

    #pragma unroll
    for (int tm = 0; tm < 4; tm++) {
        #pragma unroll
        for (int tn = 0; tn < 4; tn++) {
            long row = row0 + wm + tm*16 + gid;
            long col = col0 + wn + tn*8 + tig*2;
            #pragma unroll
            for (int half = 0; half < 2; half++) {
                long r = row + half*8;
                float v0 = acc[tm][tn][half*2+0];
                float v1 = acc[tm][tn][half*2+1];
                if (MODE == 0) {
                    *(__half2*)(Ch + r*ldc + col) = __floats2half2_rn(v0, v1);
                } else {
                    v0 += bias[col]; v1 += bias[col+1];
                    v0 = gelu_f(v0); v1 = gelu_f(v1);
                    if (MODE == 2) {
                        float2 rv = *(const float2*)(resid + r*ldc + col);
                        float2 o; o.x = v0 + rv.x; o.y = v1 + rv.y;
                        *(float2*)(Cf + r*ldc + col) = o;
                    } else {
                        *(__half2*)(Ch + r*ldc + col) = __floats2half2_rn(v0, v1);
                    }
                }
            }
        }
    }
}

// ============================================================== S GEMM + exp
__global__ __launch_bounds__(256)
void s_gemm_exp_h(const __half* __restrict__ qkvh, __half* __restrict__ Eo,
                  float* __restrict__ psum)
{
    int z = blockIdx.z, zo = z >> 3, zi = z & 7;
    const __half* A = qkvh + (size_t)zo*Pq*E3      + (size_t)zi*64;  // Q
    const __half* B = qkvh + (size_t)zo*Pq*E3 + Eq + (size_t)zi*64;  // K
    __half* C = Eo + (size_t)z * Pq * Pq;

    extern __shared__ uint32_t sm[];
    uint32_t sb = smem_u32(sm);
    __shared__ float ps[128][2];

    int tid = threadIdx.x, lane = tid & 31, wid = tid >> 5;
    int gid = lane >> 2, tig = lane & 3;
    int wm = (wid >> 2) * 64, wn = (wid & 3) * 32;
    long row0 = (long)blockIdx.y * 128;   // q
    long col0 = (long)blockIdx.x * 128;   // k
    const __half* Ab = A + row0 * E3;
    const __half* Bb = B + col0 * E3;

    uint32_t aoff[4], boff[4];
    #pragma unroll
    for (int tm = 0; tm < 4; tm++)
        aoff[tm] = ((wm + tm*16 + (lane & 15))*20 + (lane >> 4)*4) * 4;
    #pragma unroll
    for (int tn = 0; tn < 4; tn++)
        boff[tn] = ((wn + tn*8 + (lane & 7))*20 + ((lane >> 3) & 1)*4) * 4;

    float acc[4][4][4];
    #pragma unroll
    for (int i = 0; i < 4; i++)
        #pragma unroll
        for (int j = 0; j < 4; j++)
            #pragma unroll
            for (int u = 0; u < 4; u++) acc[i][j][u] = 0.0f;

    {
        #pragma unroll
        for (int j = 0; j < 2; j++) {
            int idx = tid + j*256;
            int row = idx >> 2, q = idx & 3;
            uint32_t d = sb + (row*20 + q*4) * 4;
            CPA(d,         Ab + (long)row*E3 + q*8);
            CPA(d + 10240, Bb + (long)row*E3 + q*8);
        }
        CPCOMMIT();
    }
    #pragma unroll
    for (int t = 0; t < 2; t++) {
        int s = t & 1;
        CPWAIT0();
        __syncthreads();
        if (t == 0) {
            #pragma unroll
            for (int j = 0; j < 2; j++) {
                int idx = tid + j*256;
                int row = idx >> 2, q = idx & 3;
                uint32_t d = sb + 20480 + (row*20 + q*4) * 4;
                CPA(d,         Ab + (long)row*E3 + 32 + q*8);
                CPA(d + 10240, Bb + (long)row*E3 + 32 + q*8);
            }
            CPCOMMIT();
        }
        uint32_t baseA = sb + s * 20480;
        #pragma unroll
        for (int po = 0; po < 16; po += 8) {
            uint32_t bh[4][2];
            #pragma unroll
            for (int tn = 0; tn < 4; tn++)
                ldm_x2(bh[tn], baseA + 10240 + boff[tn] + po*4);
            #pragma unroll
            for (int tm = 0; tm < 4; tm++) {
                uint32_t ah[4];
                ldm_x4(ah, baseA + aoff[tm] + po*4);
                #pragma unroll
                for (int tn = 0; tn < 4; tn++) mma16(acc[tm][tn], ah, bh[tn]);
            }
        }
    }

    const float SC = 0.125f * 1.44269504088896f;
    float cs[4][2];
    #pragma unroll
    for (int tn = 0; tn < 4; tn++) { cs[tn][0] = 0.0f; cs[tn][1] = 0.0f; }
    #pragma unroll
    for (int tm = 0; tm < 4; tm++) {
        #pragma unroll
        for (int half = 0; half < 2; half++) {
            long r = row0 + wm + tm*16 + gid + half*8;
            #pragma unroll
            for (int tn = 0; tn < 4; tn++) {
                float e0 = fexp2f(acc[tm][tn][half*2+0] * SC);
                float e1 = fexp2f(acc[tm][tn][half*2+1] * SC);
                __half2 e2 = __floats2half2_rn(e0, e1);
                long col = col0 + wn + tn*8 + tig*2;
                *(__half2*)(C + r*Pq + col) = e2;
                float2 f = __half22float2(e2);
                cs[tn][0] += f.x; cs[tn][1] += f.y;
            }
        }
    }
    #pragma unroll
    for (int tn = 0; tn < 4; tn++) {
        #pragma unroll
        for (int u = 0; u < 2; u++) {
            float v = cs[tn][u];
            v += __shfl_xor_sync(0xffffffffu, v, 4);
            v += __shfl_xor_sync(0xffffffffu, v, 8);
            v += __shfl_xor_sync(0xffffffffu, v, 16);
            if (gid == 0) ps[wn + tn*8 + tig*2 + u][wid >> 2] = v;
        }
    }
    __syncthreads();
    if (tid < 128) {
        float tot = ps[tid][0] + ps[tid][1];
        psum[((size_t)z*Pq + col0 + tid) * 32 + blockIdx.y] = tot;
    }
}

// ============================================================== combine
__global__ void combine_kernel(const float* __restrict__ psum,
                               float* __restrict__ rinv)
{
    size_t r = (size_t)blockIdx.x * 256 + threadIdx.x;
    const float4* p = (const float4*)(psum + (r << 5));
    float s = 0.0f;
    #pragma unroll
    for (int i = 0; i < 8; i++) {
        float4 v = p[i];
        s += v.x + v.y + v.z + v.w;
    }
    rinv[r] = 1.0f / s;
}

// ============================================================== attention O
__global__ __launch_bounds__(256)
void attn_o_h(const __half* __restrict__ Et, const __half* __restrict__ qkvh,
              float* __restrict__ out1, const float* __restrict__ x,
              const float* __restrict__ rinv)
{
    int z = blockIdx.z, zo = z >> 3, zi = z & 7;
    const __half* Eb = Et   + (size_t)z * Pq * Pq;
    const __half* Vb = qkvh + (size_t)zo * Pq * E3 + 2*Eq + (size_t)zi*64;
    float*        Cb = out1 + (size_t)zo * PE + (size_t)zi*64;
    const float*  Rb = x    + (size_t)zo * PE + (size_t)zi*64;
    const float* riv = rinv + (size_t)z * Pq;

    extern __shared__ uint32_t sm[];
    uint32_t sb = smem_u32(sm);

    int tid = threadIdx.x, lane = tid & 31, wid = tid >> 5;
    int gid = lane >> 2, tig = lane & 3;
    int wm = (wid >> 2) * 64, wn = (wid & 3) * 16;
    long q0 = (long)blockIdx.y * 128;
    int db = tid & 15, kpb = tid >> 4;

    uint32_t poff[4];
    #pragma unroll
    for (int tm = 0; tm < 4; tm++)
        poff[tm] = ((wm + tm*16 + (lane & 15))*36 + (lane >> 4)*4) * 4;

    float acc[4][2][4];
    #pragma unroll
    for (int i = 0; i < 4; i++)
        #pragma unroll
        for (int j = 0; j < 2; j++)
            #pragma unroll
            for (int u = 0; u < 4; u++) acc[i][j][u] = 0.0f;

    auto load_stage = [&](int s, int k0){
        int so = s * 6912;
        #pragma unroll
        for (int j = 0; j < 4; j++) {
            int idx = tid + j*256;
            int row = idx >> 3, c = idx & 7;
            CPA(sb + (so + row*36 + c*4)*4, Eb + (size_t)(q0 + row) * Pq + k0 + c*8);
        }
        CPCOMMIT();
        #pragma unroll
        for (int kk = 0; kk < 2; kk++) {
            int kp = kpb + kk*16;
            float iv0 = riv[k0 + 2*kp], iv1 = riv[k0 + 2*kp + 1];
            const __half* rp = Vb + (size_t)(k0 + 2*kp) * E3 + db*4;
            uint2 r0 = *(const uint2*)rp;
            uint2 r1 = *(const uint2*)(rp + E3);
            const __half2* h0 = (const __half2*)&r0;
            const __half2* h1 = (const __half2*)&r1;
            float2 a01 = __half22float2(h0[0]), a23 = __half22float2(h0[1]);
            float2 c01 = __half22float2(h1[0]), c23 = __half22float2(h1[1]);
            uint4 w;
            w.x = h2u(__floats2half2_rn(a01.x*iv0, c01.x*iv1));
            w.y = h2u(__floats2half2_rn(a01.y*iv0, c01.y*iv1));
            w.z = h2u(__floats2half2_rn(a23.x*iv0, c23.x*iv1));
            w.w = h2u(__floats2half2_rn(a23.y*iv0, c23.y*iv1));
            *(uint4*)&sm[so + 4608 + kp*72 + db*4] = w;
        }
    };

    load_stage(0, 0);
    for (int t = 0; t < 64; t++) {
        int s = t & 1;
        CPWAIT0();
        __syncthreads();
        if (t < 63) load_stage(1 - s, (t + 1) * 64);
        uint32_t basstP = sb + s * 6912 * 4;
        const uint32_t* stV = sm + s * 6912 + 4608;
        #pragma unroll
        for (int po = 0; po < 32; po += 8) {
            uint32_t b[2][2];
            #pragma unroll
            for (int tn = 0; tn < 2; tn++) {
                int n = wn + tn*8 + gid;
                b[tn][0] = stV[(po + tig)*72 + n];
                b[tn][1] = stV[(po + tig + 4)*72 + n];
            }
            #pragma unroll
            for (int tm = 0; tm < 4; tm++) {
                uint32_t a[4];
                ldm_x4(a, basstP + poff[tm] + po*4);
                #pragma unroll
                for (int tn = 0; tn < 2; tn++)
                    mma16(acc[tm][tn], a, b[tn]);
            }
        }
    }

    #pragma unroll
    for (int tm = 0; tm < 4; tm++) {
        #pragma unroll
        for (int tn = 0; tn < 2; tn++) {
            long q = q0 + wm + tm*16 + gid;
            int  d = wn + tn*8 + tig*2;
            #pragma unroll
            for (int half = 0; half < 2; half++) {
                long r = q + half*8;
                float2 rv = *(const float2*)(Rb + r*Eq + d);
                float2 o;
                o.x = acc[tm][tn][half*2+0] + rv.x;
                o.y = acc[tm][tn][half*2+1] + rv.y;
                *(float2*)(Cb + r*Eq + d) = o;
            }
        }
    }
}

// ============================================================== launcher
extern "C" void kernel_launch(void* const* d_in, const int* in_sizes, int n_in,
                              void* d_out, int out_size)
{
    const float* x  = (const float*)d_in[0];
    const float* g1 = (const float*)d_in[1];
    const float* b1 = (const float*)d_in[2];
    const float* W1 = (const float*)d_in[3];
    const float* g2 = (const float*)d_in[4];
    const float* b2 = (const float*)d_in[5];
    const float* Wa = (const float*)d_in[6];
    const float* ba = (const float*)d_in[7];
    const float* Wb = (const float*)d_in[8];
    const float* bb = (const float*)d_in[9];
    float* out = (float*)d_out;

    __half *hh, *W1h, *Wah, *Wbh, *qkvh, *th, *E;
    float *out1, *riv, *psm;
    cudaGetSymbolAddress((void**)&hh,   g_hh);
    cudaGetSymbolAddress((void**)&W1h,  g_W1h);
    cudaGetSymbolAddress((void**)&Wah,  g_Wah);
    cudaGetSymbolAddress((void**)&Wbh,  g_Wbh);
    cudaGetSymbolAddress((void**)&qkvh, g_qkvh);
    cudaGetSymbolAddress((void**)&th,   g_th);
    cudaGetSymbolAddress((void**)&E,    g_E);
    cudaGetSymbolAddress((void**)&out1, g_out1);
    cudaGetSymbolAddress((void**)&riv,  g_rinv);
    cudaGetSymbolAddress((void**)&psm,  g_psum);

    const int SM_GEMM = 2 * 5120 * 4;    // 40960 B (2 planes/stage)
    const int SM_S    = 2 * 5120 * 4;
    const int SM_AO   = 2 * 6912 * 4;
    cudaFuncSetAttribute(gemm_fp16<0>, cudaFuncAttributeMaxDynamicSharedMemorySize, SM_GEMM);
    cudaFuncSetAttribute(gemm_fp16<1>, cudaFuncAttributeMaxDynamicSharedMemorySize, SM_GEMM);
    cudaFuncSetAttribute(gemm_fp16<2>, cudaFuncAttributeMaxDynamicSharedMemorySize, SM_GEMM);
    cudaFuncSetAttribute(s_gemm_exp_h, cudaFuncAttributeMaxDynamicSharedMemorySize, SM_S);
    cudaFuncSetAttribute(attn_o_h,     cudaFuncAttributeMaxDynamicSharedMemorySize, SM_AO);

    const int W_N4 = (E3 * Eq) / 4;

    cvt_h<<<(W_N4 + 255)/256, 256>>>(W1, W1h, W_N4);
    cvt_h<<<(W_N4 + 255)/256, 256>>>(Wa, Wah, W_N4);
    cvt_h<<<(W_N4 + 255)/256, 256>>>(Wb, Wbh, W_N4);

    // LN1
    ln_reduce_kernel<<<dim3(NB_RED, Bq), 256>>>(x);
    ln_final_kernel<<<Bq, 256>>>();
    ln_apply_h<<<(Bq*PE/4 + 255)/256, 256>>>(x, g1, b1, hh);

    // QKV
    gemm_fp16<0><<<dim3(E3/128, (Bq*Pq)/128, 1), 256, SM_GEMM>>>(
        hh, W1h, Eq, Eq, Eq, E3,
        (float*)0, qkvh, (const float*)0, (const float*)0);

    // E + column partials
    s_gemm_exp_h<<<dim3(Pq/128, Pq/128, Bq*Hq), 256, SM_S>>>(qkvh, E, psm);

    combine_kernel<<<(Bq*Hq*Pq)/256, 256>>>(psm, riv);

    // out1 = x + E (rinv*V)
    attn_o_h<<<dim3(1, Pq/128, Bq*Hq), 256, SM_AO>>>(E, qkvh, out1, x, riv);

    // LN2
    ln_reduce_kernel<<<dim3(NB_RED, Bq), 256>>>(out1);
    ln_final_kernel<<<Bq, 256>>>();
    ln_apply_h<<<(Bq*PE/4 + 255)/256, 256>>>(out1, g2, b2, hh);

    // MLP1: t = gelu(h @ Wa^T + ba) -> fp16
    gemm_fp16<1><<<dim3(E3/128, (Bq*Pq)/128, 1), 256, SM_GEMM>>>(
        hh, Wah, Eq, Eq, Eq, E3,
        (float*)0, th, ba, (const float*)0);

    // MLP2: out = gelu(t @ Wb^T + bb) + out1
    gemm_fp16<2><<<dim3(Eq/128, (Bq*Pq)/128, 1), 256, SM_GEMM>>>(
        th, Wbh, E3, E3, E3, Eq,
        out, (__half*)0, bb, out1);
}

// round 17
// speedup vs baseline: 4.9194x; 1.1419x over previous
#include <cuda_runtime.h>
#include <cuda_fp16.h>
#include <math.h>
#include <stdint.h>

#define Bq 2
#define Pq 4096
#define Eq 512
#define Hq 8
#define E3 1536
#define PE (Pq*Eq)
#define NB_RED 256

// ------------------------------------------------------------- scratch
__device__ __align__(16) __half g_hh [(size_t)Bq*Pq*Eq];
__device__ __align__(16) __half g_W1h[(size_t)E3*Eq];
__device__ __align__(16) __half g_Wah[(size_t)E3*Eq];
__device__ __align__(16) __half g_Wbh[(size_t)Eq*E3];
__device__ __align__(16) __half g_qkvh[(size_t)Bq*Pq*E3];
__device__ __align__(16) __half g_th [(size_t)Bq*Pq*E3];
__device__ __align__(16) __half g_E  [(size_t)Bq*Hq*Pq*Pq];
__device__ __align__(16) __half g_VT [(size_t)Bq*Hq*64*Pq];   // rinv-scaled V^T
__device__ float  g_out1[(size_t)Bq*Pq*Eq];
__device__ float  g_rinv[(size_t)Bq*Hq*Pq];
__device__ float  g_psum[(size_t)Bq*Hq*Pq*32];
__device__ double g_part[Bq*NB_RED*2];
__device__ float  g_stats[Bq*2];

// ------------------------------------------------------------- helpers
__device__ __forceinline__ uint32_t smem_u32(const void* p){
    uint32_t a;
    asm("{ .reg .u64 t; cvta.to.shared.u64 t, %1; cvt.u32.u64 %0, t; }"
        : "=r"(a) : "l"(p));
    return a;
}
__device__ __forceinline__ uint32_t h2u(__half2 h){ return *reinterpret_cast<uint32_t*>(&h); }
__device__ __forceinline__ void mma16(float d[4], const uint32_t a[4], const uint32_t b[2]){
    asm volatile(
        "mma.sync.aligned.m16n8k16.row.col.f32.f16.f16.f32 "
        "{%0,%1,%2,%3}, {%4,%5,%6,%7}, {%8,%9}, {%0,%1,%2,%3};"
        : "+f"(d[0]), "+f"(d[1]), "+f"(d[2]), "+f"(d[3])
        : "r"(a[0]), "r"(a[1]), "r"(a[2]), "r"(a[3]), "r"(b[0]), "r"(b[1]));
}
__device__ __forceinline__ void ldm_x4(uint32_t r[4], uint32_t addr){
    asm volatile("ldmatrix.sync.aligned.m8n8.x4.shared.b16 {%0,%1,%2,%3}, [%4];"
        : "=r"(r[0]), "=r"(r[1]), "=r"(r[2]), "=r"(r[3]) : "r"(addr));
}
__device__ __forceinline__ void ldm_x2(uint32_t r[2], uint32_t addr){
    asm volatile("ldmatrix.sync.aligned.m8n8.x2.shared.b16 {%0,%1}, [%2];"
        : "=r"(r[0]), "=r"(r[1]) : "r"(addr));
}
__device__ __forceinline__ float gelu_f(float v){
    return 0.5f * v * (1.0f + erff(v * 0.70710678118654752440f));
}
// 2^y on the FMA/ALU pipes. |rel err| ~4e-5, below fp16 rounding.
__device__ __forceinline__ float fexp2f(float y){
    y = fmaxf(y, -100.0f);
    float t = y + 12582912.0f;
    int   e = __float_as_int(t) - 0x4B400000;
    float r = t - 12582912.0f;
    float f = y - r;
    float p = 1.3333558e-3f;
    p = fmaf(p, f, 9.6181291e-3f);
    p = fmaf(p, f, 5.5504109e-2f);
    p = fmaf(p, f, 2.4022651e-1f);
    p = fmaf(p, f, 6.9314718e-1f);
    p = fmaf(p, f, 1.0f);
    return __int_as_float((e + 127) << 23) * p;
}
#define CPA(dst, src) \
    asm volatile("cp.async.cg.shared.global [%0], [%1], 16;" :: "r"(dst), "l"(src))
#define CPCOMMIT() asm volatile("cp.async.commit_group;" ::: "memory")
#define CPWAIT0()  asm volatile("cp.async.wait_group 0;"  ::: "memory")
#define CPWAIT1()  asm volatile("cp.async.wait_group 1;"  ::: "memory")

// ============================================================== LayerNorm
__global__ void ln_reduce_kernel(const float* __restrict__ x)
{
    int b = blockIdx.y;
    const float4* xb = (const float4*)(x + (size_t)b * PE);
    int base = blockIdx.x * blockDim.x + threadIdx.x;
    float s = 0.0f, s2 = 0.0f;
    #pragma unroll
    for (int j = 0; j < 8; j++) {
        float4 v = xb[base + j * (NB_RED * 256)];
        s += (v.x + v.y) + (v.z + v.w);
        s2 = fmaf(v.x, v.x, s2); s2 = fmaf(v.y, v.y, s2);
        s2 = fmaf(v.z, v.z, s2); s2 = fmaf(v.w, v.w, s2);
    }
    __shared__ double ss[256], ss2[256];
    int t = threadIdx.x;
    ss[t] = (double)s; ss2[t] = (double)s2;
    __syncthreads();
    for (int o = 128; o > 0; o >>= 1) {
        if (t < o) { ss[t] += ss[t+o]; ss2[t] += ss2[t+o]; }
        __syncthreads();
    }
    if (t == 0) {
        g_part[(b*NB_RED + blockIdx.x)*2 + 0] = ss[0];
        g_part[(b*NB_RED + blockIdx.x)*2 + 1] = ss2[0];
    }
}

__global__ void ln_final_kernel()
{
    int b = blockIdx.x, t = threadIdx.x;
    __shared__ double ss[256], ss2[256];
    ss[t]  = g_part[(b*NB_RED + t)*2 + 0];
    ss2[t] = g_part[(b*NB_RED + t)*2 + 1];
    __syncthreads();
    for (int o = 128; o > 0; o >>= 1) {
        if (t < o) { ss[t] += ss[t+o]; ss2[t] += ss2[t+o]; }
        __syncthreads();
    }
    if (t == 0) {
        double mean = ss[0] / (double)PE;
        double var  = ss2[0] / (double)PE - mean * mean;
        g_stats[b*2 + 0] = (float)mean;
        g_stats[b*2 + 1] = (float)(1.0 / sqrt(var + 1e-5));
    }
}

__global__ void ln_apply_h(const float* __restrict__ x,
                           const float* __restrict__ gam,
                           const float* __restrict__ bet,
                           __half* __restrict__ hh)
{
    const int n4 = PE / 4;
    int i = blockIdx.x * blockDim.x + threadIdx.x;
    if (i >= Bq * n4) return;
    int b = i / n4, pe = i - b * n4;
    float mean = g_stats[b*2 + 0], inv = g_stats[b*2 + 1];
    float4 xv = ((const float4*)x)[i];
    float4 gv = ((const float4*)gam)[pe];
    float4 bv = ((const float4*)bet)[pe];
    float4 o;
    o.x = (xv.x - mean) * inv * gv.x + bv.x;
    o.y = (xv.y - mean) * inv * gv.y + bv.y;
    o.z = (xv.z - mean) * inv * gv.z + bv.z;
    o.w = (xv.w - mean) * inv * gv.w + bv.w;
    uint2 h;
    h.x = h2u(__floats2half2_rn(o.x, o.y));
    h.y = h2u(__floats2half2_rn(o.z, o.w));
    ((uint2*)hh)[i] = h;
}

__global__ void cvt_h(const float* __restrict__ src, __half* __restrict__ hi, int n4)
{
    int i = blockIdx.x * blockDim.x + threadIdx.x;
    if (i >= n4) return;
    float4 v = ((const float4*)src)[i];
    uint2 h;
    h.x = h2u(__floats2half2_rn(v.x, v.y));
    h.y = h2u(__floats2half2_rn(v.z, v.w));
    ((uint2*)hi)[i] = h;
}

// ============================================================== fp16 GEMM
// C[m,n] = sum_k A[m,k] B[n,k]  (+bias, +gelu, +resid), plain fp16.
// MODE 0: fp16 C (QKV); MODE 1: bias+gelu -> fp16 (MLP1);
// MODE 2: bias+gelu+resid -> float (MLP2). cp.async 3-stage + ldmatrix.
template<int MODE>
__global__ __launch_bounds__(256)
void gemm_fp16(const __half* __restrict__ Ah, const __half* __restrict__ Bh,
               int K, int lda, int ldb, int ldc,
               float* __restrict__ Cf, __half* __restrict__ Ch,
               const float* __restrict__ bias, const float* __restrict__ resid)
{
    extern __shared__ uint32_t sm[];
    uint32_t sb = smem_u32(sm);
    int tid = threadIdx.x, lane = tid & 31, wid = tid >> 5;
    int gid = lane >> 2, tig = lane & 3;
    int wm = (wid >> 2) * 64, wn = (wid & 3) * 32;
    long row0 = (long)blockIdx.y * 128, col0 = (long)blockIdx.x * 128;
    const __half* A0 = Ah + row0 * lda;
    const __half* B0 = Bh + col0 * ldb;

    uint32_t aoff[4], boff[4];
    #pragma unroll
    for (int tm = 0; tm < 4; tm++)
        aoff[tm] = ((wm + tm*16 + (lane & 15))*20 + (lane >> 4)*4) * 4;
    #pragma unroll
    for (int tn = 0; tn < 4; tn++)
        boff[tn] = ((wn + tn*8 + (lane & 7))*20 + ((lane >> 3) & 1)*4) * 4;

    float acc[4][4][4];
    #pragma unroll
    for (int i = 0; i < 4; i++)
        #pragma unroll
        for (int j = 0; j < 4; j++)
            #pragma unroll
            for (int u = 0; u < 4; u++) acc[i][j][u] = 0.0f;

    const int T = K >> 5;
    // prologue: stages 0, 1
    #pragma unroll
    for (int p = 0; p < 2; p++) {
        int kt = p << 5;
        #pragma unroll
        for (int j = 0; j < 2; j++) {
            int idx = tid + j*256;
            int row = idx >> 2, q = idx & 3;
            uint32_t d = sb + p * 20480 + (row*20 + q*4) * 4;
            CPA(d,         A0 + (long)row * lda + kt + q*8);
            CPA(d + 10240, B0 + (long)row * ldb + kt + q*8);
        }
        CPCOMMIT();
    }

    int s = 0;
    for (int t = 0; t < T; t++) {
        CPWAIT1();
        __syncthreads();
        if (t + 2 < T) {
            int kt = (t + 2) << 5;
            int sn = s + 2; if (sn >= 3) sn -= 3;
            #pragma unroll
            for (int j = 0; j < 2; j++) {
                int idx = tid + j*256;
                int row = idx >> 2, q = idx & 3;
                uint32_t d = sb + sn * 20480 + (row*20 + q*4) * 4;
                CPA(d,         A0 + (long)row * lda + kt + q*8);
                CPA(d + 10240, B0 + (long)row * ldb + kt + q*8);
            }
        }
        CPCOMMIT();
        uint32_t baseA = sb + s * 20480;
        #pragma unroll
        for (int po = 0; po < 16; po += 8) {
            uint32_t bh[4][2];
            #pragma unroll
            for (int tn = 0; tn < 4; tn++)
                ldm_x2(bh[tn], baseA + 10240 + boff[tn] + po*4);
            #pragma unroll
            for (int tm = 0; tm < 4; tm++) {
                uint32_t ah[4];
                ldm_x4(ah, baseA + aoff[tm] + po*4);
                #pragma unroll
                for (int tn = 0; tn < 4; tn++)
                    mma16(acc[tm][tn], ah, bh[tn]);
            }
        }
        if (++s == 3) s = 0;
    }

    #pragma unroll
    for (int tm = 0; tm < 4; tm++) {
        #pragma unroll
        for (int tn = 0; tn < 4; tn++) {
            long row = row0 + wm + tm*16 + gid;
            long col = col0 + wn + tn*8 + tig*2;
            #pragma unroll
            for (int half = 0; half < 2; half++) {
                long r = row + half*8;
                float v0 = acc[tm][tn][half*2+0];
                float v1 = acc[tm][tn][half*2+1];
                if (MODE == 0) {
                    *(__half2*)(Ch + r*ldc + col) = __floats2half2_rn(v0, v1);
                } else {
                    v0 += bias[col]; v1 += bias[col+1];
                    v0 = gelu_f(v0); v1 = gelu_f(v1);
                    if (MODE == 2) {
                        float2 rv = *(const float2*)(resid + r*ldc + col);
                        float2 o; o.x = v0 + rv.x; o.y = v1 + rv.y;
                        *(float2*)(Cf + r*ldc + col) = o;
                    } else {
                        *(__half2*)(Ch + r*ldc + col) = __floats2half2_rn(v0, v1);
                    }
                }
            }
        }
    }
}

// ============================================================== S GEMM + exp
__global__ __launch_bounds__(256)
void s_gemm_exp_h(const __half* __restrict__ qkvh, __half* __restrict__ Eo,
                  float* __restrict__ psum)
{
    int z = blockIdx.z, zo = z >> 3, zi = z & 7;
    const __half* A = qkvh + (size_t)zo*Pq*E3      + (size_t)zi*64;  // Q
    const __half* B = qkvh + (size_t)zo*Pq*E3 + Eq + (size_t)zi*64;  // K
    __half* C = Eo + (size_t)z * Pq * Pq;

    extern __shared__ uint32_t sm[];
    uint32_t sb = smem_u32(sm);
    __shared__ float ps[128][2];

    int tid = threadIdx.x, lane = tid & 31, wid = tid >> 5;
    int gid = lane >> 2, tig = lane & 3;
    int wm = (wid >> 2) * 64, wn = (wid & 3) * 32;
    long row0 = (long)blockIdx.y * 128;   // q
    long col0 = (long)blockIdx.x * 128;   // k
    const __half* Ab = A + row0 * E3;
    const __half* Bb = B + col0 * E3;

    uint32_t aoff[4], boff[4];
    #pragma unroll
    for (int tm = 0; tm < 4; tm++)
        aoff[tm] = ((wm + tm*16 + (lane & 15))*20 + (lane >> 4)*4) * 4;
    #pragma unroll
    for (int tn = 0; tn < 4; tn++)
        boff[tn] = ((wn + tn*8 + (lane & 7))*20 + ((lane >> 3) & 1)*4) * 4;

    float acc[4][4][4];
    #pragma unroll
    for (int i = 0; i < 4; i++)
        #pragma unroll
        for (int j = 0; j < 4; j++)
            #pragma unroll
            for (int u = 0; u < 4; u++) acc[i][j][u] = 0.0f;

    {
        #pragma unroll
        for (int j = 0; j < 2; j++) {
            int idx = tid + j*256;
            int row = idx >> 2, q = idx & 3;
            uint32_t d = sb + (row*20 + q*4) * 4;
            CPA(d,         Ab + (long)row*E3 + q*8);
            CPA(d + 10240, Bb + (long)row*E3 + q*8);
        }
        CPCOMMIT();
    }
    #pragma unroll
    for (int t = 0; t < 2; t++) {
        int s = t & 1;
        CPWAIT0();
        __syncthreads();
        if (t == 0) {
            #pragma unroll
            for (int j = 0; j < 2; j++) {
                int idx = tid + j*256;
                int row = idx >> 2, q = idx & 3;
                uint32_t d = sb + 20480 + (row*20 + q*4) * 4;
                CPA(d,         Ab + (long)row*E3 + 32 + q*8);
                CPA(d + 10240, Bb + (long)row*E3 + 32 + q*8);
            }
            CPCOMMIT();
        }
        uint32_t baseA = sb + s * 20480;
        #pragma unroll
        for (int po = 0; po < 16; po += 8) {
            uint32_t bh[4][2];
            #pragma unroll
            for (int tn = 0; tn < 4; tn++)
                ldm_x2(bh[tn], baseA + 10240 + boff[tn] + po*4);
            #pragma unroll
            for (int tm = 0; tm < 4; tm++) {
                uint32_t ah[4];
                ldm_x4(ah, baseA + aoff[tm] + po*4);
                #pragma unroll
                for (int tn = 0; tn < 4; tn++) mma16(acc[tm][tn], ah, bh[tn]);
            }
        }
    }

    const float SC = 0.125f * 1.44269504088896f;
    float cs[4][2];
    #pragma unroll
    for (int tn = 0; tn < 4; tn++) { cs[tn][0] = 0.0f; cs[tn][1] = 0.0f; }
    #pragma unroll
    for (int tm = 0; tm < 4; tm++) {
        #pragma unroll
        for (int half = 0; half < 2; half++) {
            long r = row0 + wm + tm*16 + gid + half*8;
            #pragma unroll
            for (int tn = 0; tn < 4; tn++) {
                float e0 = fexp2f(acc[tm][tn][half*2+0] * SC);
                float e1 = fexp2f(acc[tm][tn][half*2+1] * SC);
                __half2 e2 = __floats2half2_rn(e0, e1);
                long col = col0 + wn + tn*8 + tig*2;
                *(__half2*)(C + r*Pq + col) = e2;
                float2 f = __half22float2(e2);
                cs[tn][0] += f.x; cs[tn][1] += f.y;
            }
        }
    }
    #pragma unroll
    for (int tn = 0; tn < 4; tn++) {
        #pragma unroll
        for (int u = 0; u < 2; u++) {
            float v = cs[tn][u];
            v += __shfl_xor_sync(0xffffffffu, v, 4);
            v += __shfl_xor_sync(0xffffffffu, v, 8);
            v += __shfl_xor_sync(0xffffffffu, v, 16);
            if (gid == 0) ps[wn + tn*8 + tig*2 + u][wid >> 2] = v;
        }
    }
    __syncthreads();
    if (tid < 128) {
        float tot = ps[tid][0] + ps[tid][1];
        psum[((size_t)z*Pq + col0 + tid) * 32 + blockIdx.y] = tot;
    }
}

// ============================================================== combine
__global__ void combine_kernel(const float* __restrict__ psum,
                               float* __restrict__ rinv)
{
    size_t r = (size_t)blockIdx.x * 256 + threadIdx.x;
    const float4* p = (const float4*)(psum + (r << 5));
    float s = 0.0f;
    #pragma unroll
    for (int i = 0; i < 8; i++) {
        float4 v = p[i];
        s += v.x + v.y + v.z + v.w;
    }
    rinv[r] = 1.0f / s;
}

// ============================================================== VT prep
// VT[z][d][k] = rinv[z,k] * V[k, zi*64+d]  (fp16). One block per (64-k chunk, z).
// Load phase: 512 uint4 (2 per thread) — R15 only issued 256, leaving half the
// tile uninitialized (the NaN bug). Stride 72 halves = 144 B (16B-aligned).
__global__ void vt_prep(const __half* __restrict__ qkvh,
                        const float* __restrict__ rinv,
                        __half* __restrict__ VT)
{
    int z = blockIdx.y, zo = z >> 3, zi = z & 7;
    int k0 = blockIdx.x * 64;
    const __half* Vb = qkvh + (size_t)zo*Pq*E3 + 2*Eq + (size_t)zi*64;
    const float* riv = rinv + (size_t)z*Pq;
    __shared__ __half s[64*72];
    int tid = threadIdx.x;
    #pragma unroll
    for (int j = 0; j < 2; j++) {
        int idx = tid + j*256;          // 0..511
        int row = idx >> 3, c = idx & 7;
        uint4 v = *(const uint4*)(Vb + (size_t)(k0 + row)*E3 + c*8);
        *(uint4*)&s[row*72 + c*8] = v;
    }
    __syncthreads();
    int kp = tid & 31;
    int d0 = (tid >> 5) * 8;
    float iv0 = riv[k0 + 2*kp], iv1 = riv[k0 + 2*kp + 1];
    #pragma unroll
    for (int dd = 0; dd < 8; dd++) {
        int d = d0 + dd;
        float v0 = __half2float(s[(2*kp)*72 + d]);
        float v1 = __half2float(s[(2*kp+1)*72 + d]);
        ((uint32_t*)(VT + ((size_t)z*64 + d)*Pq + k0))[kp] =
            h2u(__floats2half2_rn(v0*iv0, v1*iv1));
    }
}

// ============================================================== attention O
// out1[q, zi*64+d] = x + sum_k E[q,k]*VT[d,k] — pure fp16 GEMM,
// both operands cp.async-staged, 3-stage pipeline, ldmatrix fragments.
__global__ __launch_bounds__(256)
void attn_o_h(const __half* __restrict__ Et, const __half* __restrict__ VT,
              float* __restrict__ out1, const float* __restrict__ x)
{
    int z = blockIdx.z, zo = z >> 3, zi = z & 7;
    const __half* Eb = Et + (size_t)z * Pq * Pq;
    const __half* Vt = VT + (size_t)z * 64 * Pq;
    float*        Cb = out1 + (size_t)zo * PE + (size_t)zi*64;
    const float*  Rb = x    + (size_t)zo * PE + (size_t)zi*64;

    extern __shared__ uint32_t sm[];   // stage: stP 128*36 + stV 64*36 = 6912 u32
    uint32_t sb = smem_u32(sm);

    int tid = threadIdx.x, lane = tid & 31, wid = tid >> 5;
    int gid = lane >> 2, tig = lane & 3;
    int wm = (wid >> 2) * 64, wn = (wid & 3) * 16;
    long q0 = (long)blockIdx.y * 128;

    uint32_t poff[4], voff[2];
    #pragma unroll
    for (int tm = 0; tm < 4; tm++)
        poff[tm] = ((wm + tm*16 + (lane & 15))*36 + (lane >> 4)*4) * 4;
    #pragma unroll
    for (int tn = 0; tn < 2; tn++)
        voff[tn] = (4608 + (wn + tn*8 + (lane & 7))*36 + ((lane >> 3) & 1)*4) * 4;

    float acc[4][2][4];
    #pragma unroll
    for (int i = 0; i < 4; i++)
        #pragma unroll
        for (int j = 0; j < 2; j++)
            #pragma unroll
            for (int u = 0; u < 4; u++) acc[i][j][u] = 0.0f;

    // prologue: stages 0, 1
    #pragma unroll
    for (int p = 0; p < 2; p++) {
        int k0 = p * 64;
        int so = p * 6912;
        #pragma unroll
        for (int j = 0; j < 4; j++) {
            int idx = tid + j*256;
            int row = idx >> 3, c = idx & 7;
            CPA(sb + (so + row*36 + c*4)*4, Eb + (size_t)(q0 + row)*Pq + k0 + c*8);
        }
        #pragma unroll
        for (int j = 0; j < 2; j++) {
            int idx = tid + j*256;
            int row = idx >> 3, c = idx & 7;
            CPA(sb + (so + 4608 + row*36 + c*4)*4, Vt + (size_t)row*Pq + k0 + c*8);
        }
        CPCOMMIT();
    }

    int s = 0;
    for (int t = 0; t < 64; t++) {
        CPWAIT1();
        __syncthreads();
        if (t + 2 < 64) {
            int k0 = (t + 2) * 64;
            int sn = s + 2; if (sn >= 3) sn -= 3;
            int so = sn * 6912;
            #pragma unroll
            for (int j = 0; j < 4; j++) {
                int idx = tid + j*256;
                int row = idx >> 3, c = idx & 7;
                CPA(sb + (so + row*36 + c*4)*4, Eb + (size_t)(q0 + row)*Pq + k0 + c*8);
            }
            #pragma unroll
            for (int j = 0; j < 2; j++) {
                int idx = tid + j*256;
                int row = idx >> 3, c = idx & 7;
                CPA(sb + (so + 4608 + row*36 + c*4)*4, Vt + (size_t)row*Pq + k0 + c*8);
            }
        }
        CPCOMMIT();
        uint32_t base = sb + s * 6912 * 4;
        #pragma unroll
        for (int po = 0; po < 32; po += 8) {
            uint32_t b[2][2];
            #pragma unroll
            for (int tn = 0; tn < 2; tn++)
                ldm_x2(b[tn], base + voff[tn] + po*4);
            #pragma unroll
            for (int tm = 0; tm < 4; tm++) {
                uint32_t a[4];
                ldm_x4(a, base + poff[tm] + po*4);
                #pragma unroll
                for (int tn = 0; tn < 2; tn++)
                    mma16(acc[tm][tn], a, b[tn]);
            }
        }
        if (++s == 3) s = 0;
    }

    #pragma unroll
    for (int tm = 0; tm < 4; tm++) {
        #pragma unroll
        for (int tn = 0; tn < 2; tn++) {
            long q = q0 + wm + tm*16 + gid;
            int  d = wn + tn*8 + tig*2;
            #pragma unroll
            for (int half = 0; half < 2; half++) {
                long r = q + half*8;
                float2 rv = *(const float2*)(Rb + r*Eq + d);
                float2 o;
                o.x = acc[tm][tn][half*2+0] + rv.x;
                o.y = acc[tm][tn][half*2+1] + rv.y;
                *(float2*)(Cb + r*Eq + d) = o;
            }
        }
    }
}

// ============================================================== launcher
extern "C" void kernel_launch(void* const* d_in, const int* in_sizes, int n_in,
                              void* d_out, int out_size)
{
    const float* x  = (const float*)d_in[0];
    const float* g1 = (const float*)d_in[1];
    const float* b1 = (const float*)d_in[2];
    const float* W1 = (const float*)d_in[3];
    const float* g2 = (const float*)d_in[4];
    const float* b2 = (const float*)d_in[5];
    const float* Wa = (const float*)d_in[6];
    const float* ba = (const float*)d_in[7];
    const float* Wb = (const float*)d_in[8];
    const float* bb = (const float*)d_in[9];
    float* out = (float*)d_out;

    __half *hh, *W1h, *Wah, *Wbh, *qkvh, *th, *E, *VT;
    float *out1, *riv, *psm;
    cudaGetSymbolAddress((void**)&hh,   g_hh);
    cudaGetSymbolAddress((void**)&W1h,  g_W1h);
    cudaGetSymbolAddress((void**)&Wah,  g_Wah);
    cudaGetSymbolAddress((void**)&Wbh,  g_Wbh);
    cudaGetSymbolAddress((void**)&qkvh, g_qkvh);
    cudaGetSymbolAddress((void**)&th,   g_th);
    cudaGetSymbolAddress((void**)&E,    g_E);
    cudaGetSymbolAddress((void**)&VT,   g_VT);
    cudaGetSymbolAddress((void**)&out1, g_out1);
    cudaGetSymbolAddress((void**)&riv,  g_rinv);
    cudaGetSymbolAddress((void**)&psm,  g_psum);

    const int SM_GEMM = 3 * 5120 * 4;    // 61440 B (3 stages)
    const int SM_S    = 2 * 5120 * 4;
    const int SM_AO   = 3 * 6912 * 4;    // 82944 B (3 stages)
    cudaFuncSetAttribute(gemm_fp16<0>, cudaFuncAttributeMaxDynamicSharedMemorySize, SM_GEMM);
    cudaFuncSetAttribute(gemm_fp16<1>, cudaFuncAttributeMaxDynamicSharedMemorySize, SM_GEMM);
    cudaFuncSetAttribute(gemm_fp16<2>, cudaFuncAttributeMaxDynamicSharedMemorySize, SM_GEMM);
    cudaFuncSetAttribute(s_gemm_exp_h, cudaFuncAttributeMaxDynamicSharedMemorySize, SM_S);
    cudaFuncSetAttribute(attn_o_h,     cudaFuncAttributeMaxDynamicSharedMemorySize, SM_AO);

    const int W_N4 = (E3 * Eq) / 4;

    cvt_h<<<(W_N4 + 255)/256, 256>>>(W1, W1h, W_N4);
    cvt_h<<<(W_N4 + 255)/256, 256>>>(Wa, Wah, W_N4);
    cvt_h<<<(W_N4 + 255)/256, 256>>>(Wb, Wbh, W_N4);

    // LN1
    ln_reduce_kernel<<<dim3(NB_RED, Bq), 256>>>(x);
    ln_final_kernel<<<Bq, 256>>>();
    ln_apply_h<<<(Bq*PE/4 + 255)/256, 256>>>(x, g1, b1, hh);

    // QKV
    gemm_fp16<0><<<dim3(E3/128, (Bq*Pq)/128, 1), 256, SM_GEMM>>>(
        hh, W1h, Eq, Eq, Eq, E3,
        (float*)0, qkvh, (const float*)0, (const float*)0);

    // E + column partials
    s_gemm_exp_h<<<dim3(Pq/128, Pq/128, Bq*Hq), 256, SM_S>>>(qkvh, E, psm);

    combine_kernel<<<(Bq*Hq*Pq)/256, 256>>>(psm, riv);

    // VT = rinv * V^T (once per z)
    vt_prep<<<dim3(Pq/64, Bq*Hq), 256>>>(qkvh, riv, VT);

    // out1 = x + E @ VT^T
    attn_o_h<<<dim3(1, Pq/128, Bq*Hq), 256, SM_AO>>>(E, VT, out1, x);

    // LN2
    ln_reduce_kernel<<<dim3(NB_RED, Bq), 256>>>(out1);
    ln_final_kernel<<<Bq, 256>>>();
    ln_apply_h<<<(Bq*PE/4 + 255)/256, 256>>>(out1, g2, b2, hh);

    // MLP1: t = gelu(h @ Wa^T + ba) -> fp16
    gemm_fp16<1><<<dim3(E3/128, (Bq*Pq)/128, 1), 256, SM_GEMM>>>(
        hh, Wah, Eq, Eq, Eq, E3,
        (float*)0, th, ba, (const float*)0);

    // MLP2: out = gelu(t @ Wb^T + bb) + out1
    gemm_fp16<2><<<dim3(Eq/128, (Bq*Pq)/128, 1), 256, SM_GEMM>>>(
        th, Wbh, E3, E3, E3, Eq,
        out, (__half*)0, bb, out1);
}